// round 9
// baseline (speedup 1.0000x reference)
#include <cuda_runtime.h>
#include <cuda_bf16.h>
#include <math.h>
#include <stdint.h>

// ----------------------------------------------------------------------------
// IGNN / EGNN layer, GB300 (sm_103a built as sm_103 -> mma.sync, no tcgen05).
// Round 9: atomic scatter replaced by bf16 edge-message store + CSR gather
// (R8 showed RED is per-word LTS-throughput bound, ~490us -> removed).
// Node kernels and edge stage-1/HMMA unchanged from R8.
// ----------------------------------------------------------------------------

#define NN 50000
#define NE 800000
#define DH 128
#define DE 16
#define DM 128

__device__ __align__(16) float    g_Ha[(size_t)NN * DM];
__device__ __align__(16) float    g_Hb[(size_t)NN * DM];
__device__ __align__(16) float    g_msg[(size_t)NN * DM];
__device__ __align__(16) uint32_t g_emsg[(size_t)NE * 64];   // bf16x2 words, 64/edge
__device__ int g_cnt[NN];
__device__ int g_rowptr[NN + 1];
__device__ int g_cursor[NN];
__device__ int g_sorted[NE];

__device__ __forceinline__ float fsigmoid(float v) {
    return 1.0f / (1.0f + __expf(-v));
}

__device__ __forceinline__ void fma8x2(float a0c[8], float a1c[8], float a0, float a1,
                                       const float* __restrict__ w) {
    float4 w0 = *(const float4*)(w);
    float4 w1 = *(const float4*)(w + 4);
    a0c[0] += a0 * w0.x; a1c[0] += a1 * w0.x;
    a0c[1] += a0 * w0.y; a1c[1] += a1 * w0.y;
    a0c[2] += a0 * w0.z; a1c[2] += a1 * w0.z;
    a0c[3] += a0 * w0.w; a1c[3] += a1 * w0.w;
    a0c[4] += a0 * w1.x; a1c[4] += a1 * w1.x;
    a0c[5] += a0 * w1.y; a1c[5] += a1 * w1.y;
    a0c[6] += a0 * w1.z; a1c[6] += a1 * w1.z;
    a0c[7] += a0 * w1.w; a1c[7] += a1 * w1.w;
}

__device__ __forceinline__ uint32_t smem_to_u32(const void* smem_ptr) {
    uint32_t addr;
    asm("{ .reg .u64 tmp; cvta.to.shared.u64 tmp, %1; cvt.u32.u64 %0, tmp; }"
        : "=r"(addr) : "l"(smem_ptr));
    return addr;
}

__device__ __forceinline__ void ldmatrix_x4(uint32_t& r0, uint32_t& r1,
                                            uint32_t& r2, uint32_t& r3, uint32_t addr) {
    asm volatile("ldmatrix.sync.aligned.m8n8.x4.shared.b16 {%0,%1,%2,%3}, [%4];"
                 : "=r"(r0), "=r"(r1), "=r"(r2), "=r"(r3) : "r"(addr));
}
__device__ __forceinline__ void ldmatrix_x2(uint32_t& r0, uint32_t& r1, uint32_t addr) {
    asm volatile("ldmatrix.sync.aligned.m8n8.x2.shared.b16 {%0,%1}, [%2];"
                 : "=r"(r0), "=r"(r1) : "r"(addr));
}
__device__ __forceinline__ void mma_bf16(float d[4], const uint32_t a[4],
                                         const uint32_t b[2], const float c[4]) {
    asm volatile(
        "mma.sync.aligned.m16n8k16.row.col.f32.bf16.bf16.f32 "
        "{%0,%1,%2,%3}, {%4,%5,%6,%7}, {%8,%9}, {%10,%11,%12,%13};"
        : "=f"(d[0]), "=f"(d[1]), "=f"(d[2]), "=f"(d[3])
        : "r"(a[0]), "r"(a[1]), "r"(a[2]), "r"(a[3]),
          "r"(b[0]), "r"(b[1]),
          "f"(c[0]), "f"(c[1]), "f"(c[2]), "f"(c[3]));
}

// pack float4 -> two bf16x2 words
__device__ __forceinline__ uint2 pack_bf16x4(float4 v) {
    __nv_bfloat162 lo = __floats2bfloat162_rn(v.x, v.y);
    __nv_bfloat162 hi = __floats2bfloat162_rn(v.z, v.w);
    uint2 r;
    r.x = *(uint32_t*)&lo;
    r.y = *(uint32_t*)&hi;
    return r;
}

// ============================ CSR build =====================================
__global__ void zero_cnt_kernel() {
    int i = blockIdx.x * blockDim.x + threadIdx.x;
    if (i < NN) g_cnt[i] = 0;
}

__global__ void count_kernel(const int* __restrict__ ei) {
    int e = blockIdx.x * blockDim.x + threadIdx.x;
    if (e < NE) atomicAdd(&g_cnt[ei[e]], 1);
}

// single block, 1024 threads; chunk = 49 (1024*49 = 50176 >= NN)
__global__ void __launch_bounds__(1024, 1) scan_kernel() {
    __shared__ int partial[1024];
    const int t = threadIdx.x;
    const int c0 = t * 49;
    int s = 0;
    for (int i = c0; i < c0 + 49 && i < NN; i++) s += g_cnt[i];
    partial[t] = s;
    __syncthreads();
    for (int off = 1; off < 1024; off <<= 1) {
        int v = (t >= off) ? partial[t - off] : 0;
        __syncthreads();
        partial[t] += v;
        __syncthreads();
    }
    int run = (t == 0) ? 0 : partial[t - 1];
    for (int i = c0; i < c0 + 49 && i < NN; i++) {
        g_rowptr[i] = run;
        g_cursor[i] = run;
        run += g_cnt[i];
    }
    if (t == 1023) g_rowptr[NN] = partial[1023];
}

__global__ void fill_kernel(const int* __restrict__ ei) {
    int e = blockIdx.x * blockDim.x + threadIdx.x;
    if (e < NE) {
        int r = ei[e];
        int pos = atomicAdd(&g_cursor[r], 1);
        g_sorted[pos] = e;
    }
}

// ============================ gather ========================================
// 1 warp per node; lane owns cols lane*4 .. lane*4+3.
__global__ void __launch_bounds__(256) gather_kernel() {
    const int warp = threadIdx.x >> 5, lane = threadIdx.x & 31;
    const int node = blockIdx.x * 8 + warp;
    if (node >= NN) return;
    const int beg = g_rowptr[node], end = g_rowptr[node + 1];
    float a0 = 0.f, a1 = 0.f, a2 = 0.f, a3 = 0.f;
    for (int i = beg; i < end; i++) {
        int e = g_sorted[i];
        uint2 w = *(const uint2*)&g_emsg[(size_t)e * 64 + lane * 2];
        __nv_bfloat162 lo = *(__nv_bfloat162*)&w.x;
        __nv_bfloat162 hi = *(__nv_bfloat162*)&w.y;
        a0 += __bfloat162float(lo.x); a1 += __bfloat162float(lo.y);
        a2 += __bfloat162float(hi.x); a3 += __bfloat162float(hi.y);
    }
    *(float4*)&g_msg[(size_t)node * DM + lane * 4] = make_float4(a0, a1, a2, a3);
}

// ---------------------------------------------------------------------------
// kernel 1 (HMMA): Ha = h @ W1a^T, Hb = h @ W1b^T.  (unchanged from R8)
// ---------------------------------------------------------------------------
#define NP_A   0
#define NP_WA  34816
#define NP_WB  69632
#define NP_TOTAL 104448
#define RS 272

__global__ void __launch_bounds__(256, 2)
node_pre_kernel(const float* __restrict__ h, const float* __restrict__ We1) {
    extern __shared__ __align__(16) char smraw[];
    const uint32_t smem_u32 = smem_to_u32(smraw);
    const int tid  = threadIdx.x;
    const int warp = tid >> 5;
    const int lane = tid & 31;

    for (int idx = tid; idx < 128 * 128; idx += 256) {
        int n = idx >> 7, k = idx & 127;
        *(__nv_bfloat16*)(smraw + NP_WA + n * RS + k * 2) =
            __float2bfloat16(We1[n * 273 + k]);
        *(__nv_bfloat16*)(smraw + NP_WB + n * RS + k * 2) =
            __float2bfloat16(We1[n * 273 + 128 + k]);
    }
    __syncthreads();

    const int m0 = warp * 16;
    const int arow = m0 + (lane & 7) + ((lane >> 3) & 1) * 8;
    const uint32_t a_base  = smem_u32 + NP_A + (uint32_t)arow * RS + ((lane >> 4) & 1) * 16;
    const int bl = lane & 15;
    const uint32_t ba_base = smem_u32 + NP_WA + (uint32_t)(bl & 7) * RS + ((bl >> 3) & 1) * 16;
    const uint32_t bb_base = smem_u32 + NP_WB + (uint32_t)(bl & 7) * RS + ((bl >> 3) & 1) * 16;

    const int tig = lane & 3, grp = lane >> 2;
    const int ntiles = (NN + 127) / 128;

    for (int tile = blockIdx.x; tile < ntiles; tile += gridDim.x) {
        const int base = tile * 128;
        __syncthreads();
        for (int idx = tid; idx < 128 * 32; idx += 256) {
            int r = idx >> 5, j4 = (idx & 31) * 4;
            int node = base + r;
            float4 v = (node < NN) ? *(const float4*)&h[(size_t)node * DH + j4]
                                   : make_float4(0.f, 0.f, 0.f, 0.f);
            *(uint2*)(smraw + NP_A + r * RS + j4 * 2) = pack_bf16x4(v);
        }
        __syncthreads();

        const int node0 = base + m0 + grp;
        const int node1 = node0 + 8;

        {
            float acc[16][4];
#pragma unroll
            for (int nt = 0; nt < 16; nt++)
#pragma unroll
                for (int r = 0; r < 4; r++) acc[nt][r] = 0.f;
#pragma unroll
            for (int k = 0; k < 8; k++) {
                uint32_t a[4];
                ldmatrix_x4(a[0], a[1], a[2], a[3], a_base + (uint32_t)k * 32);
#pragma unroll
                for (int nt = 0; nt < 16; nt++) {
                    uint32_t b[2];
                    ldmatrix_x2(b[0], b[1], ba_base + (uint32_t)nt * (8 * RS) + (uint32_t)k * 32);
                    mma_bf16(acc[nt], a, b, acc[nt]);
                }
            }
#pragma unroll
            for (int nt = 0; nt < 16; nt++) {
                const int c0 = nt * 8 + tig * 2;
                if (node0 < NN) *(float2*)&g_Ha[(size_t)node0 * DM + c0] =
                    make_float2(acc[nt][0], acc[nt][1]);
                if (node1 < NN) *(float2*)&g_Ha[(size_t)node1 * DM + c0] =
                    make_float2(acc[nt][2], acc[nt][3]);
            }
        }
        {
            float acc[16][4];
#pragma unroll
            for (int nt = 0; nt < 16; nt++)
#pragma unroll
                for (int r = 0; r < 4; r++) acc[nt][r] = 0.f;
#pragma unroll
            for (int k = 0; k < 8; k++) {
                uint32_t a[4];
                ldmatrix_x4(a[0], a[1], a[2], a[3], a_base + (uint32_t)k * 32);
#pragma unroll
                for (int nt = 0; nt < 16; nt++) {
                    uint32_t b[2];
                    ldmatrix_x2(b[0], b[1], bb_base + (uint32_t)nt * (8 * RS) + (uint32_t)k * 32);
                    mma_bf16(acc[nt], a, b, acc[nt]);
                }
            }
#pragma unroll
            for (int nt = 0; nt < 16; nt++) {
                const int c0 = nt * 8 + tig * 2;
                if (node0 < NN) *(float2*)&g_Hb[(size_t)node0 * DM + c0] =
                    make_float2(acc[nt][0], acc[nt][1]);
                if (node1 < NN) *(float2*)&g_Hb[(size_t)node1 * DM + c0] =
                    make_float2(acc[nt][2], acc[nt][3]);
            }
        }
    }
}

// ---------------------------------------------------------------------------
// kernel 2: edge kernel, HMMA stage 2, bf16 edge-message store (no atomics).
// ---------------------------------------------------------------------------
#define EB_M1    0
#define EB_W2    34816
#define EB_W1ET  69632
#define EB_WR    77824
#define EB_BE1   78336
#define EB_BE2   78848
#define EB_WAS   79360
#define EB_EAS   79872
#define EB_RAD   88576
#define EB_SROW  89088
#define EB_SCOL  89600
#define EB_TOTAL 90112

#define M1_STRIDE 272

__global__ void __launch_bounds__(256, 2)
edge_kernel(const float* __restrict__ x,
            const float* __restrict__ edge_attr,
            const float* __restrict__ We1,
            const float* __restrict__ be1,
            const float* __restrict__ We2,
            const float* __restrict__ be2,
            const float* __restrict__ Wa,
            const float* __restrict__ ba,
            const int* __restrict__ ei) {
    extern __shared__ __align__(16) char smraw[];
    float* W1eT = (float*)(smraw + EB_W1ET);
    float* Wr   = (float*)(smraw + EB_WR);
    float* be1s = (float*)(smraw + EB_BE1);
    float* be2s = (float*)(smraw + EB_BE2);
    float* Was  = (float*)(smraw + EB_WAS);
    float* eas  = (float*)(smraw + EB_EAS);
    float* radS = (float*)(smraw + EB_RAD);
    int*   srow = (int*)(smraw + EB_SROW);
    int*   scol = (int*)(smraw + EB_SCOL);

    const uint32_t smem_u32 = smem_to_u32(smraw);
    const int tid  = threadIdx.x;
    const int warp = tid >> 5;
    const int lane = tid & 31;

    for (int idx = tid; idx < 128 * 128; idx += 256) {
        int n = idx >> 7, k = idx & 127;
        *(__nv_bfloat16*)(smraw + EB_W2 + n * M1_STRIDE + k * 2) =
            __float2bfloat16(We2[n * 128 + k]);
    }
    for (int idx = tid; idx < 16 * 128; idx += 256) {
        int t = idx >> 7, k = idx & 127;
        W1eT[t * 128 + k] = We1[k * 273 + 257 + t];
    }
    for (int k = tid; k < 128; k += 256) {
        Wr[k]   = We1[k * 273 + 256];
        be1s[k] = be1[k];
        be2s[k] = be2[k];
        Was[k]  = Wa[k];
    }
    const float ba0 = ba[0];
    __syncthreads();

    const int m0 = warp * 16;
    const int arow = m0 + (lane & 7) + ((lane >> 3) & 1) * 8;
    const uint32_t a_base = smem_u32 + EB_M1 + (uint32_t)arow * M1_STRIDE
                          + ((lane >> 4) & 1) * 16;
    const uint32_t b4_base = smem_u32 + EB_W2
                           + (uint32_t)((lane & 7) + ((lane >> 4) & 1) * 8) * M1_STRIDE
                           + ((lane >> 3) & 1) * 16;

    const int g = tid >> 4, e0b = tid & 15, k0c = g * 8;
    const int tig = lane & 3, grp = lane >> 2;
    const int jj = tig >> 1;
    const bool isOdd = (tig & 1) != 0;

    for (int tile = blockIdx.x; tile < NE / 128; tile += gridDim.x) {
        const int base = tile * 128;
        __syncthreads();

        if (tid < 128) {
            int r = ei[base + tid];
            int c = ei[NE + base + tid];
            srow[tid] = r;
            scol[tid] = c;
            float dx = x[(size_t)r * 3 + 0] - x[(size_t)c * 3 + 0];
            float dy = x[(size_t)r * 3 + 1] - x[(size_t)c * 3 + 1];
            float dz = x[(size_t)r * 3 + 2] - x[(size_t)c * 3 + 2];
            radS[tid] = sqrtf(dx * dx + dy * dy + dz * dz);
        }
        for (int idx = tid; idx < 128 * 16; idx += 256) {
            int ee = idx >> 4, t = idx & 15;
            eas[ee * 17 + t] = edge_attr[(size_t)(base + ee) * DE + t];
        }
        __syncthreads();

        // ---- stage 1 ----
#pragma unroll
        for (int s = 0; s < 4; s++) {
            const int le0 = s * 32 + e0b;
            const int le1 = le0 + 16;
            const int row0 = srow[le0], col0 = scol[le0];
            const int row1 = srow[le1], col1 = scol[le1];
            const float rad0 = radS[le0], rad1 = radS[le1];

            float acc0[8], acc1[8];
            {
                const float4* pHa0 = (const float4*)(g_Ha + (size_t)row0 * DM + k0c);
                const float4* pHb0 = (const float4*)(g_Hb + (size_t)col0 * DM + k0c);
                const float4* pHa1 = (const float4*)(g_Ha + (size_t)row1 * DM + k0c);
                const float4* pHb1 = (const float4*)(g_Hb + (size_t)col1 * DM + k0c);
                float4 a00 = pHa0[0], a01 = pHa0[1], b00 = pHb0[0], b01 = pHb0[1];
                float4 a10 = pHa1[0], a11 = pHa1[1], b10 = pHb1[0], b11 = pHb1[1];
                acc0[0] = a00.x + b00.x; acc0[1] = a00.y + b00.y;
                acc0[2] = a00.z + b00.z; acc0[3] = a00.w + b00.w;
                acc0[4] = a01.x + b01.x; acc0[5] = a01.y + b01.y;
                acc0[6] = a01.z + b01.z; acc0[7] = a01.w + b01.w;
                acc1[0] = a10.x + b10.x; acc1[1] = a10.y + b10.y;
                acc1[2] = a10.z + b10.z; acc1[3] = a10.w + b10.w;
                acc1[4] = a11.x + b11.x; acc1[5] = a11.y + b11.y;
                acc1[6] = a11.z + b11.z; acc1[7] = a11.w + b11.w;
#pragma unroll
                for (int r = 0; r < 8; r++) {
                    float bb = be1s[k0c + r], wr = Wr[k0c + r];
                    acc0[r] += bb + rad0 * wr;
                    acc1[r] += bb + rad1 * wr;
                }
            }
#pragma unroll
            for (int t = 0; t < 16; t++) {
                float a0 = eas[le0 * 17 + t];
                float a1 = eas[le1 * 17 + t];
                fma8x2(acc0, acc1, a0, a1, W1eT + t * 128 + k0c);
            }
            uint32_t p0[4], p1[4];
#pragma unroll
            for (int r = 0; r < 4; r++) {
                float v00 = acc0[2 * r], v01 = acc0[2 * r + 1];
                float v10 = acc1[2 * r], v11 = acc1[2 * r + 1];
                __nv_bfloat162 q0 = __floats2bfloat162_rn(v00 * fsigmoid(v00), v01 * fsigmoid(v01));
                __nv_bfloat162 q1 = __floats2bfloat162_rn(v10 * fsigmoid(v10), v11 * fsigmoid(v11));
                p0[r] = *(uint32_t*)&q0;
                p1[r] = *(uint32_t*)&q1;
            }
            *(uint4*)(smraw + EB_M1 + le0 * M1_STRIDE + k0c * 2) =
                make_uint4(p0[0], p0[1], p0[2], p0[3]);
            *(uint4*)(smraw + EB_M1 + le1 * M1_STRIDE + k0c * 2) =
                make_uint4(p1[0], p1[1], p1[2], p1[3]);
        }
        __syncthreads();

        // ---- stage 2: HMMA (B via x4 nt-pairs) ----
        float acc[16][4];
#pragma unroll
        for (int nt = 0; nt < 16; nt++)
#pragma unroll
            for (int r = 0; r < 4; r++) acc[nt][r] = 0.f;

#pragma unroll
        for (int k = 0; k < 8; k++) {
            uint32_t a[4];
            ldmatrix_x4(a[0], a[1], a[2], a[3], a_base + (uint32_t)k * 32);
#pragma unroll
            for (int ntp = 0; ntp < 8; ntp++) {
                uint32_t b4[4];
                ldmatrix_x4(b4[0], b4[1], b4[2], b4[3],
                            b4_base + (uint32_t)ntp * (16 * M1_STRIDE) + (uint32_t)k * 32);
                mma_bf16(acc[2 * ntp],     a, b4,     acc[2 * ntp]);
                mma_bf16(acc[2 * ntp + 1], a, b4 + 2, acc[2 * ntp + 1]);
            }
        }

        // ---- epilogue: silu, attention, bf16 store to g_emsg ----
        float pr0 = 0.f, pr1 = 0.f;
#pragma unroll
        for (int nt = 0; nt < 16; nt++) {
            const int c0 = nt * 8 + tig * 2;
            float2 bb = *(float2*)&be2s[c0];
            float2 wa = *(float2*)&Was[c0];
            float v0 = acc[nt][0] + bb.x;
            float v1 = acc[nt][1] + bb.y;
            float v2 = acc[nt][2] + bb.x;
            float v3 = acc[nt][3] + bb.y;
            float s0 = v0 * fsigmoid(v0);
            float s1 = v1 * fsigmoid(v1);
            float s2 = v2 * fsigmoid(v2);
            float s3 = v3 * fsigmoid(v3);
            acc[nt][0] = s0; acc[nt][1] = s1; acc[nt][2] = s2; acc[nt][3] = s3;
            pr0 += s0 * wa.x + s1 * wa.y;
            pr1 += s2 * wa.x + s3 * wa.y;
        }
        pr0 += __shfl_xor_sync(0xFFFFFFFF, pr0, 1);
        pr0 += __shfl_xor_sync(0xFFFFFFFF, pr0, 2);
        pr1 += __shfl_xor_sync(0xFFFFFFFF, pr1, 1);
        pr1 += __shfl_xor_sync(0xFFFFFFFF, pr1, 2);
        const float att0 = fsigmoid(pr0 + ba0);
        const float att1 = fsigmoid(pr1 + ba0);

        // lane-pair assembles 4 contiguous cols of one row, packs bf16x4, STG.64
        const float attm = isOdd ? att1 : att0;
        const int   eg   = base + m0 + grp + (isOdd ? 8 : 0);
        uint32_t* dst = g_emsg + (size_t)eg * 64 + jj * 2;
#pragma unroll
        for (int nt = 0; nt < 16; nt++) {
            float s0 = acc[nt][0], s1 = acc[nt][1];
            float s2 = acc[nt][2], s3 = acc[nt][3];
            float q0 = __shfl_xor_sync(0xFFFFFFFF, s0, 1);
            float q1 = __shfl_xor_sync(0xFFFFFFFF, s1, 1);
            float q2 = __shfl_xor_sync(0xFFFFFFFF, s2, 1);
            float q3 = __shfl_xor_sync(0xFFFFFFFF, s3, 1);
            float v0 = isOdd ? q2 : s0;
            float v1 = isOdd ? q3 : s1;
            float v2 = isOdd ? s2 : q0;
            float v3 = isOdd ? s3 : q1;
            uint2 p = pack_bf16x4(make_float4(v0 * attm, v1 * attm, v2 * attm, v3 * attm));
            *(uint2*)(dst + nt * 4) = p;
        }
    }
}

// ---------------------------------------------------------------------------
// kernel 3 (HMMA): node post.  (unchanged from R8)
// ---------------------------------------------------------------------------
#define PO_A   0
#define PO_W1  67584
#define PO_W2  135168
#define PO_U   169984
#define PO_B1  204800
#define PO_B2  205312
#define PO_TOTAL 205824
#define RS2 528

__global__ void __launch_bounds__(256, 1)
node_post_kernel(const float* __restrict__ h,
                 const float* __restrict__ Wh1,
                 const float* __restrict__ bh1,
                 const float* __restrict__ Wh2,
                 const float* __restrict__ bh2,
                 float* __restrict__ out) {
    extern __shared__ __align__(16) char smraw[];
    float* b1s = (float*)(smraw + PO_B1);
    float* b2s = (float*)(smraw + PO_B2);

    const uint32_t smem_u32 = smem_to_u32(smraw);
    const int tid  = threadIdx.x;
    const int warp = tid >> 5;
    const int lane = tid & 31;

    for (int idx = tid; idx < 128 * 64; idx += 256) {
        int n = idx >> 6, k4 = (idx & 63) * 4;
        float4 v = *(const float4*)&Wh1[(size_t)n * 256 + k4];
        *(uint2*)(smraw + PO_W1 + n * RS2 + k4 * 2) = pack_bf16x4(v);
    }
    for (int idx = tid; idx < 128 * 32; idx += 256) {
        int n = idx >> 5, k4 = (idx & 31) * 4;
        float4 v = *(const float4*)&Wh2[(size_t)n * 128 + k4];
        *(uint2*)(smraw + PO_W2 + n * RS + k4 * 2) = pack_bf16x4(v);
    }
    for (int k = tid; k < 128; k += 256) {
        b1s[k] = bh1[k];
        b2s[k] = bh2[k];
    }
    __syncthreads();

    const int m0 = warp * 16;
    const int arow = m0 + (lane & 7) + ((lane >> 3) & 1) * 8;
    const uint32_t a1_base = smem_u32 + PO_A + (uint32_t)arow * RS2 + ((lane >> 4) & 1) * 16;
    const uint32_t a2_base = smem_u32 + PO_U + (uint32_t)arow * RS  + ((lane >> 4) & 1) * 16;
    const int bl = lane & 15;
    const uint32_t b1_base = smem_u32 + PO_W1 + (uint32_t)(bl & 7) * RS2 + ((bl >> 3) & 1) * 16;
    const uint32_t b2_base = smem_u32 + PO_W2 + (uint32_t)(bl & 7) * RS  + ((bl >> 3) & 1) * 16;

    const int tig = lane & 3, grp = lane >> 2;
    const int ntiles = (NN + 127) / 128;

    for (int tile = blockIdx.x; tile < ntiles; tile += gridDim.x) {
        const int base = tile * 128;
        __syncthreads();
        for (int idx = tid; idx < 128 * 32; idx += 256) {
            int r = idx >> 5, j4 = (idx & 31) * 4;
            int node = base + r;
            float4 vh = (node < NN) ? *(const float4*)&h[(size_t)node * DH + j4]
                                    : make_float4(0.f, 0.f, 0.f, 0.f);
            float4 vm = (node < NN) ? *(const float4*)&g_msg[(size_t)node * DM + j4]
                                    : make_float4(0.f, 0.f, 0.f, 0.f);
            *(uint2*)(smraw + PO_A + r * RS2 + j4 * 2)         = pack_bf16x4(vh);
            *(uint2*)(smraw + PO_A + r * RS2 + 256 + j4 * 2)   = pack_bf16x4(vm);
        }
        __syncthreads();

        float acc[16][4];
#pragma unroll
        for (int nt = 0; nt < 16; nt++)
#pragma unroll
            for (int r = 0; r < 4; r++) acc[nt][r] = 0.f;
#pragma unroll
        for (int k = 0; k < 16; k++) {
            uint32_t a[4];
            ldmatrix_x4(a[0], a[1], a[2], a[3], a1_base + (uint32_t)k * 32);
#pragma unroll
            for (int nt = 0; nt < 16; nt++) {
                uint32_t b[2];
                ldmatrix_x2(b[0], b[1], b1_base + (uint32_t)nt * (8 * RS2) + (uint32_t)k * 32);
                mma_bf16(acc[nt], a, b, acc[nt]);
            }
        }
#pragma unroll
        for (int nt = 0; nt < 16; nt++) {
            const int c0 = nt * 8 + tig * 2;
            float2 bb = *(float2*)&b1s[c0];
            float v0 = acc[nt][0] + bb.x;
            float v1 = acc[nt][1] + bb.y;
            float v2 = acc[nt][2] + bb.x;
            float v3 = acc[nt][3] + bb.y;
            __nv_bfloat162 q0 = __floats2bfloat162_rn(v0 * fsigmoid(v0), v1 * fsigmoid(v1));
            __nv_bfloat162 q1 = __floats2bfloat162_rn(v2 * fsigmoid(v2), v3 * fsigmoid(v3));
            *(uint32_t*)(smraw + PO_U + (m0 + grp) * RS + c0 * 2)     = *(uint32_t*)&q0;
            *(uint32_t*)(smraw + PO_U + (m0 + grp + 8) * RS + c0 * 2) = *(uint32_t*)&q1;
        }
        __syncthreads();

#pragma unroll
        for (int nt = 0; nt < 16; nt++)
#pragma unroll
            for (int r = 0; r < 4; r++) acc[nt][r] = 0.f;
#pragma unroll
        for (int k = 0; k < 8; k++) {
            uint32_t a[4];
            ldmatrix_x4(a[0], a[1], a[2], a[3], a2_base + (uint32_t)k * 32);
#pragma unroll
            for (int nt = 0; nt < 16; nt++) {
                uint32_t b[2];
                ldmatrix_x2(b[0], b[1], b2_base + (uint32_t)nt * (8 * RS) + (uint32_t)k * 32);
                mma_bf16(acc[nt], a, b, acc[nt]);
            }
        }

        const int node0 = base + m0 + grp;
        const int node1 = node0 + 8;
#pragma unroll
        for (int nt = 0; nt < 16; nt++) {
            const int c0 = nt * 8 + tig * 2;
            float2 bb = *(float2*)&b2s[c0];
            if (node0 < NN) {
                float2 hv = *(const float2*)&h[(size_t)node0 * DH + c0];
                *(float2*)&out[(size_t)node0 * DH + c0] =
                    make_float2(hv.x + acc[nt][0] + bb.x, hv.y + acc[nt][1] + bb.y);
            }
            if (node1 < NN) {
                float2 hv = *(const float2*)&h[(size_t)node1 * DH + c0];
                *(float2*)&out[(size_t)node1 * DH + c0] =
                    make_float2(hv.x + acc[nt][2] + bb.x, hv.y + acc[nt][3] + bb.y);
            }
        }
    }
}

// ---------------------------------------------------------------------------
extern "C" void kernel_launch(void* const* d_in, const int* in_sizes, int n_in,
                              void* d_out, int out_size) {
    const float* x   = (const float*)d_in[0];
    const float* h   = (const float*)d_in[1];
    const float* ea  = (const float*)d_in[2];
    const float* We1 = (const float*)d_in[3];
    const float* be1 = (const float*)d_in[4];
    const float* We2 = (const float*)d_in[5];
    const float* be2 = (const float*)d_in[6];
    const float* Wh1 = (const float*)d_in[7];
    const float* bh1 = (const float*)d_in[8];
    const float* Wh2 = (const float*)d_in[9];
    const float* bh2 = (const float*)d_in[10];
    const float* Wa  = (const float*)d_in[11];
    const float* ba  = (const float*)d_in[12];
    const int*   ei  = (const int*)d_in[13];   // int32
    float* out = (float*)d_out;

    cudaFuncSetAttribute(node_pre_kernel,
                         cudaFuncAttributeMaxDynamicSharedMemorySize, NP_TOTAL);
    cudaFuncSetAttribute(edge_kernel,
                         cudaFuncAttributeMaxDynamicSharedMemorySize, EB_TOTAL);
    cudaFuncSetAttribute(node_post_kernel,
                         cudaFuncAttributeMaxDynamicSharedMemorySize, PO_TOTAL);

    // CSR build (row-major aggregation)
    zero_cnt_kernel<<<(NN + 255) / 256, 256>>>();
    count_kernel<<<(NE + 255) / 256, 256>>>(ei);
    scan_kernel<<<1, 1024>>>();
    fill_kernel<<<(NE + 255) / 256, 256>>>(ei);

    node_pre_kernel<<<296, 256, NP_TOTAL>>>(h, We1);
    edge_kernel<<<296, 256, EB_TOTAL>>>(x, ea, We1, be1, We2, be2, Wa, ba, ei);
    gather_kernel<<<(NN + 7) / 8, 256>>>();
    node_post_kernel<<<148, 256, PO_TOTAL>>>(h, Wh1, bh1, Wh2, bh2, out);
}

// round 10
// speedup vs baseline: 1.2985x; 1.2985x over previous
#include <cuda_runtime.h>
#include <cuda_bf16.h>
#include <math.h>
#include <stdint.h>

// ----------------------------------------------------------------------------
// IGNN / EGNN layer, GB300 (sm_103a built as sm_103 -> mma.sync, no tcgen05).
// Round 10: R9 post-mortem showed atomics are ~free (overlapped) and the edge
// kernel is phase-barrier stall-bound. This round: warp-autonomous edge tiles
// (16 edges/warp, zero block syncs in the loop), R8 atomic scatter restored,
// CSR/gather machinery deleted. Node kernels unchanged (R8 HMMA).
// ----------------------------------------------------------------------------

#define NN 50000
#define NE 800000
#define DH 128
#define DE 16
#define DM 128

__device__ __align__(16) float g_Ha[(size_t)NN * DM];
__device__ __align__(16) float g_Hb[(size_t)NN * DM];
__device__ __align__(16) float g_msg[(size_t)NN * DM];

__device__ __forceinline__ float fsigmoid(float v) {
    return 1.0f / (1.0f + __expf(-v));
}

__device__ __forceinline__ uint32_t smem_to_u32(const void* smem_ptr) {
    uint32_t addr;
    asm("{ .reg .u64 tmp; cvta.to.shared.u64 tmp, %1; cvt.u32.u64 %0, tmp; }"
        : "=r"(addr) : "l"(smem_ptr));
    return addr;
}

__device__ __forceinline__ void ldmatrix_x4(uint32_t& r0, uint32_t& r1,
                                            uint32_t& r2, uint32_t& r3, uint32_t addr) {
    asm volatile("ldmatrix.sync.aligned.m8n8.x4.shared.b16 {%0,%1,%2,%3}, [%4];"
                 : "=r"(r0), "=r"(r1), "=r"(r2), "=r"(r3) : "r"(addr));
}
__device__ __forceinline__ void ldmatrix_x2(uint32_t& r0, uint32_t& r1, uint32_t addr) {
    asm volatile("ldmatrix.sync.aligned.m8n8.x2.shared.b16 {%0,%1}, [%2];"
                 : "=r"(r0), "=r"(r1) : "r"(addr));
}
__device__ __forceinline__ void mma_bf16(float d[4], const uint32_t a[4],
                                         const uint32_t b[2], const float c[4]) {
    asm volatile(
        "mma.sync.aligned.m16n8k16.row.col.f32.bf16.bf16.f32 "
        "{%0,%1,%2,%3}, {%4,%5,%6,%7}, {%8,%9}, {%10,%11,%12,%13};"
        : "=f"(d[0]), "=f"(d[1]), "=f"(d[2]), "=f"(d[3])
        : "r"(a[0]), "r"(a[1]), "r"(a[2]), "r"(a[3]),
          "r"(b[0]), "r"(b[1]),
          "f"(c[0]), "f"(c[1]), "f"(c[2]), "f"(c[3]));
}
__device__ __forceinline__ void red_v4(float* addr, float v0, float v1, float v2, float v3) {
    asm volatile("red.global.add.v4.f32 [%0], {%1, %2, %3, %4};"
                 :: "l"(addr), "f"(v0), "f"(v1), "f"(v2), "f"(v3) : "memory");
}

// pack float4 -> two bf16x2 words
__device__ __forceinline__ uint2 pack_bf16x4(float4 v) {
    __nv_bfloat162 lo = __floats2bfloat162_rn(v.x, v.y);
    __nv_bfloat162 hi = __floats2bfloat162_rn(v.z, v.w);
    uint2 r;
    r.x = *(uint32_t*)&lo;
    r.y = *(uint32_t*)&hi;
    return r;
}

// ---------------------------------------------------------------------------
__global__ void zero_msg_kernel() {
    size_t i = (size_t)blockIdx.x * blockDim.x + threadIdx.x;
    size_t n4 = (size_t)NN * DM / 4;
    if (i < n4) ((float4*)g_msg)[i] = make_float4(0.f, 0.f, 0.f, 0.f);
}

// ---------------------------------------------------------------------------
// kernel 1 (HMMA): Ha = h @ W1a^T, Hb = h @ W1b^T.  (unchanged from R8)
// ---------------------------------------------------------------------------
#define NP_A   0
#define NP_WA  34816
#define NP_WB  69632
#define NP_TOTAL 104448
#define RS 272

__global__ void __launch_bounds__(256, 2)
node_pre_kernel(const float* __restrict__ h, const float* __restrict__ We1) {
    extern __shared__ __align__(16) char smraw[];
    const uint32_t smem_u32 = smem_to_u32(smraw);
    const int tid  = threadIdx.x;
    const int warp = tid >> 5;
    const int lane = tid & 31;

    for (int idx = tid; idx < 128 * 128; idx += 256) {
        int n = idx >> 7, k = idx & 127;
        *(__nv_bfloat16*)(smraw + NP_WA + n * RS + k * 2) =
            __float2bfloat16(We1[n * 273 + k]);
        *(__nv_bfloat16*)(smraw + NP_WB + n * RS + k * 2) =
            __float2bfloat16(We1[n * 273 + 128 + k]);
    }
    __syncthreads();

    const int m0 = warp * 16;
    const int arow = m0 + (lane & 7) + ((lane >> 3) & 1) * 8;
    const uint32_t a_base  = smem_u32 + NP_A + (uint32_t)arow * RS + ((lane >> 4) & 1) * 16;
    const int bl = lane & 15;
    const uint32_t ba_base = smem_u32 + NP_WA + (uint32_t)(bl & 7) * RS + ((bl >> 3) & 1) * 16;
    const uint32_t bb_base = smem_u32 + NP_WB + (uint32_t)(bl & 7) * RS + ((bl >> 3) & 1) * 16;

    const int tig = lane & 3, grp = lane >> 2;
    const int ntiles = (NN + 127) / 128;

    for (int tile = blockIdx.x; tile < ntiles; tile += gridDim.x) {
        const int base = tile * 128;
        __syncthreads();
        for (int idx = tid; idx < 128 * 32; idx += 256) {
            int r = idx >> 5, j4 = (idx & 31) * 4;
            int node = base + r;
            float4 v = (node < NN) ? *(const float4*)&h[(size_t)node * DH + j4]
                                   : make_float4(0.f, 0.f, 0.f, 0.f);
            *(uint2*)(smraw + NP_A + r * RS + j4 * 2) = pack_bf16x4(v);
        }
        __syncthreads();

        const int node0 = base + m0 + grp;
        const int node1 = node0 + 8;

        {
            float acc[16][4];
#pragma unroll
            for (int nt = 0; nt < 16; nt++)
#pragma unroll
                for (int r = 0; r < 4; r++) acc[nt][r] = 0.f;
#pragma unroll
            for (int k = 0; k < 8; k++) {
                uint32_t a[4];
                ldmatrix_x4(a[0], a[1], a[2], a[3], a_base + (uint32_t)k * 32);
#pragma unroll
                for (int nt = 0; nt < 16; nt++) {
                    uint32_t b[2];
                    ldmatrix_x2(b[0], b[1], ba_base + (uint32_t)nt * (8 * RS) + (uint32_t)k * 32);
                    mma_bf16(acc[nt], a, b, acc[nt]);
                }
            }
#pragma unroll
            for (int nt = 0; nt < 16; nt++) {
                const int c0 = nt * 8 + tig * 2;
                if (node0 < NN) *(float2*)&g_Ha[(size_t)node0 * DM + c0] =
                    make_float2(acc[nt][0], acc[nt][1]);
                if (node1 < NN) *(float2*)&g_Ha[(size_t)node1 * DM + c0] =
                    make_float2(acc[nt][2], acc[nt][3]);
            }
        }
        {
            float acc[16][4];
#pragma unroll
            for (int nt = 0; nt < 16; nt++)
#pragma unroll
                for (int r = 0; r < 4; r++) acc[nt][r] = 0.f;
#pragma unroll
            for (int k = 0; k < 8; k++) {
                uint32_t a[4];
                ldmatrix_x4(a[0], a[1], a[2], a[3], a_base + (uint32_t)k * 32);
#pragma unroll
                for (int nt = 0; nt < 16; nt++) {
                    uint32_t b[2];
                    ldmatrix_x2(b[0], b[1], bb_base + (uint32_t)nt * (8 * RS) + (uint32_t)k * 32);
                    mma_bf16(acc[nt], a, b, acc[nt]);
                }
            }
#pragma unroll
            for (int nt = 0; nt < 16; nt++) {
                const int c0 = nt * 8 + tig * 2;
                if (node0 < NN) *(float2*)&g_Hb[(size_t)node0 * DM + c0] =
                    make_float2(acc[nt][0], acc[nt][1]);
                if (node1 < NN) *(float2*)&g_Hb[(size_t)node1 * DM + c0] =
                    make_float2(acc[nt][2], acc[nt][3]);
            }
        }
    }
}

// ---------------------------------------------------------------------------
// kernel 2: edge kernel — warp-autonomous 16-edge tiles, no block syncs.
//
// SMEM bytes:
//   [0]      A    : 8 warps x (16 rows x 136 bf16, stride 272B) = 34816
//   [34816]  W2   : 128 x 136 bf16 (We2 as [n][k])              = 34816
//   [69632]  W1eT : 16 x 128 f32                                 = 8192
//   [77824]  Wr / [78336] be1s / [78848] be2s / [79360] Was : 128 f32 each
//   total 79872 B -> 2 CTAs/SM
// ---------------------------------------------------------------------------
#define EB_A     0
#define EB_W2    34816
#define EB_W1ET  69632
#define EB_WR    77824
#define EB_BE1   78336
#define EB_BE2   78848
#define EB_WAS   79360
#define EB_TOTAL 79872

#define M1_STRIDE 272
#define WARP_A_BYTES (16 * M1_STRIDE)   // 4352

__global__ void __launch_bounds__(256, 2)
edge_kernel(const float* __restrict__ x,
            const float* __restrict__ edge_attr,
            const float* __restrict__ We1,
            const float* __restrict__ be1,
            const float* __restrict__ We2,
            const float* __restrict__ be2,
            const float* __restrict__ Wa,
            const float* __restrict__ ba,
            const int* __restrict__ ei) {
    extern __shared__ __align__(16) char smraw[];
    float* W1eT = (float*)(smraw + EB_W1ET);
    float* Wr   = (float*)(smraw + EB_WR);
    float* be1s = (float*)(smraw + EB_BE1);
    float* be2s = (float*)(smraw + EB_BE2);
    float* Was  = (float*)(smraw + EB_WAS);

    const uint32_t smem_u32 = smem_to_u32(smraw);
    const int tid  = threadIdx.x;
    const int warp = tid >> 5;
    const int lane = tid & 31;

    // ---- preamble (only block sync in the kernel) ----
    for (int idx = tid; idx < 128 * 128; idx += 256) {
        int n = idx >> 7, k = idx & 127;
        *(__nv_bfloat16*)(smraw + EB_W2 + n * M1_STRIDE + k * 2) =
            __float2bfloat16(We2[n * 128 + k]);
    }
    for (int idx = tid; idx < 16 * 128; idx += 256) {
        int t = idx >> 7, k = idx & 127;
        W1eT[t * 128 + k] = We1[k * 273 + 257 + t];     // edge_attr cols 257..272
    }
    for (int k = tid; k < 128; k += 256) {
        Wr[k]   = We1[k * 273 + 256];                   // radial col 256
        be1s[k] = be1[k];
        be2s[k] = be2[k];
        Was[k]  = Wa[k];
    }
    const float ba0 = ba[0];
    __syncthreads();

    // per-warp A region, ldmatrix lane addressing (rows 0..15 within region)
    const uint32_t a_region = smem_u32 + EB_A + (uint32_t)warp * WARP_A_BYTES;
    const int arow = (lane & 7) + ((lane >> 3) & 1) * 8;
    const uint32_t a_base = a_region + (uint32_t)arow * M1_STRIDE + ((lane >> 4) & 1) * 16;
    const uint32_t b4_base = smem_u32 + EB_W2
                           + (uint32_t)((lane & 7) + ((lane >> 4) & 1) * 8) * M1_STRIDE
                           + ((lane >> 3) & 1) * 16;

    const int es   = lane >> 1;          // edge slot (0..15) for stage 1
    const int hf   = lane & 1;           // column half (0 -> 0..63, 1 -> 64..127)
    const int col0 = hf * 64;
    const int tig = lane & 3, grp = lane >> 2;
    const int jj = tig >> 1;
    const bool isOdd = (tig & 1) != 0;

    const int NWT = NE / 16;             // 50000 warp-tiles
    const int wstride = gridDim.x * 8;

    for (int wt = blockIdx.x * 8 + warp; wt < NWT; wt += wstride) {
        const int base = wt * 16;

        // ---- per-edge loads (lanes 0..15) ----
        int rld = 0, cld = 0;
        float radld = 0.f;
        if (lane < 16) {
            rld = ei[base + lane];
            cld = ei[NE + base + lane];
            float dx = x[(size_t)rld * 3 + 0] - x[(size_t)cld * 3 + 0];
            float dy = x[(size_t)rld * 3 + 1] - x[(size_t)cld * 3 + 1];
            float dz = x[(size_t)rld * 3 + 2] - x[(size_t)cld * 3 + 2];
            radld = sqrtf(dx * dx + dy * dy + dz * dz);
        }
        const int   row  = __shfl_sync(0xFFFFFFFF, rld, es);
        const int   colN = __shfl_sync(0xFFFFFFFF, cld, es);
        const float radv = __shfl_sync(0xFFFFFFFF, radld, es);

        // ---- stage 1: 64 outputs/thread for edge `es`, cols col0..col0+63 ----
        float acc[64];
        {
            const float4* pHa = (const float4*)(g_Ha + (size_t)row  * DM + col0);
            const float4* pHb = (const float4*)(g_Hb + (size_t)colN * DM + col0);
            const float4* pb1 = (const float4*)(be1s + col0);
            const float4* pwr = (const float4*)(Wr + col0);
#pragma unroll
            for (int q = 0; q < 16; q++) {
                float4 ha = pHa[q], hb = pHb[q], bb = pb1[q], wr = pwr[q];
                acc[4 * q + 0] = ha.x + hb.x + bb.x + radv * wr.x;
                acc[4 * q + 1] = ha.y + hb.y + bb.y + radv * wr.y;
                acc[4 * q + 2] = ha.z + hb.z + bb.z + radv * wr.z;
                acc[4 * q + 3] = ha.w + hb.w + bb.w + radv * wr.w;
            }
        }
        {
            const float4* pe = (const float4*)(edge_attr + (size_t)(base + es) * DE);
            float4 e0 = pe[0], e1 = pe[1], e2 = pe[2], e3 = pe[3];
            float ea[16] = {e0.x, e0.y, e0.z, e0.w, e1.x, e1.y, e1.z, e1.w,
                            e2.x, e2.y, e2.z, e2.w, e3.x, e3.y, e3.z, e3.w};
#pragma unroll
            for (int t = 0; t < 16; t++) {
                const float4* w = (const float4*)(W1eT + t * 128 + col0);
                float a = ea[t];
#pragma unroll
                for (int q = 0; q < 16; q++) {
                    float4 wv = w[q];
                    acc[4 * q + 0] += a * wv.x;
                    acc[4 * q + 1] += a * wv.y;
                    acc[4 * q + 2] += a * wv.z;
                    acc[4 * q + 3] += a * wv.w;
                }
            }
        }
        // silu -> bf16 pack -> warp-private A region (row es, cols col0..+63)
        {
            char* adst = (char*)smraw + EB_A + warp * WARP_A_BYTES
                       + es * M1_STRIDE + col0 * 2;
#pragma unroll
            for (int q = 0; q < 8; q++) {
                float v0 = acc[8 * q + 0], v1 = acc[8 * q + 1];
                float v2 = acc[8 * q + 2], v3 = acc[8 * q + 3];
                float v4 = acc[8 * q + 4], v5 = acc[8 * q + 5];
                float v6 = acc[8 * q + 6], v7 = acc[8 * q + 7];
                uint2 lo = pack_bf16x4(make_float4(v0 * fsigmoid(v0), v1 * fsigmoid(v1),
                                                   v2 * fsigmoid(v2), v3 * fsigmoid(v3)));
                uint2 hi = pack_bf16x4(make_float4(v4 * fsigmoid(v4), v5 * fsigmoid(v5),
                                                   v6 * fsigmoid(v6), v7 * fsigmoid(v7)));
                *(uint4*)(adst + q * 16) = make_uint4(lo.x, lo.y, hi.x, hi.y);
            }
        }
        __syncwarp();

        // ---- stage 2: HMMA  D[16x128] = m1 @ We2^T  (warp-local A) ----
        float dacc[16][4];
#pragma unroll
        for (int nt = 0; nt < 16; nt++)
#pragma unroll
            for (int r = 0; r < 4; r++) dacc[nt][r] = 0.f;

#pragma unroll
        for (int k = 0; k < 8; k++) {
            uint32_t a[4];
            ldmatrix_x4(a[0], a[1], a[2], a[3], a_base + (uint32_t)k * 32);
#pragma unroll
            for (int ntp = 0; ntp < 8; ntp++) {
                uint32_t b4[4];
                ldmatrix_x4(b4[0], b4[1], b4[2], b4[3],
                            b4_base + (uint32_t)ntp * (16 * M1_STRIDE) + (uint32_t)k * 32);
                mma_bf16(dacc[2 * ntp],     a, b4,     dacc[2 * ntp]);
                mma_bf16(dacc[2 * ntp + 1], a, b4 + 2, dacc[2 * ntp + 1]);
            }
        }
        __syncwarp();   // A region reused next iteration

        // ---- epilogue (warp-local): silu, attention, RED v4 scatter ----
        float pr0 = 0.f, pr1 = 0.f;
#pragma unroll
        for (int nt = 0; nt < 16; nt++) {
            const int c0 = nt * 8 + tig * 2;
            float2 bb = *(float2*)&be2s[c0];
            float2 wa = *(float2*)&Was[c0];
            float v0 = dacc[nt][0] + bb.x;
            float v1 = dacc[nt][1] + bb.y;
            float v2 = dacc[nt][2] + bb.x;
            float v3 = dacc[nt][3] + bb.y;
            float s0 = v0 * fsigmoid(v0);
            float s1 = v1 * fsigmoid(v1);
            float s2 = v2 * fsigmoid(v2);
            float s3 = v3 * fsigmoid(v3);
            dacc[nt][0] = s0; dacc[nt][1] = s1; dacc[nt][2] = s2; dacc[nt][3] = s3;
            pr0 += s0 * wa.x + s1 * wa.y;
            pr1 += s2 * wa.x + s3 * wa.y;
        }
        pr0 += __shfl_xor_sync(0xFFFFFFFF, pr0, 1);
        pr0 += __shfl_xor_sync(0xFFFFFFFF, pr0, 2);
        pr1 += __shfl_xor_sync(0xFFFFFFFF, pr1, 1);
        pr1 += __shfl_xor_sync(0xFFFFFFFF, pr1, 2);
        const float att0 = fsigmoid(pr0 + ba0);
        const float att1 = fsigmoid(pr1 + ba0);

        const int node0 = __shfl_sync(0xFFFFFFFF, rld, grp);      // row of edge grp
        const int node1 = __shfl_sync(0xFFFFFFFF, rld, grp + 8);  // row of edge grp+8
        const float attm = isOdd ? att1 : att0;
        float* dst = g_msg + (size_t)(isOdd ? node1 : node0) * DM + jj * 4;
#pragma unroll
        for (int nt = 0; nt < 16; nt++) {
            float s0 = dacc[nt][0], s1 = dacc[nt][1];
            float s2 = dacc[nt][2], s3 = dacc[nt][3];
            float q0 = __shfl_xor_sync(0xFFFFFFFF, s0, 1);
            float q1 = __shfl_xor_sync(0xFFFFFFFF, s1, 1);
            float q2 = __shfl_xor_sync(0xFFFFFFFF, s2, 1);
            float q3 = __shfl_xor_sync(0xFFFFFFFF, s3, 1);
            float v0 = isOdd ? q2 : s0;
            float v1 = isOdd ? q3 : s1;
            float v2 = isOdd ? s2 : q0;
            float v3 = isOdd ? s3 : q1;
            red_v4(dst + nt * 8, v0 * attm, v1 * attm, v2 * attm, v3 * attm);
        }
    }
}

// ---------------------------------------------------------------------------
// kernel 3 (HMMA): node post.  (unchanged from R8)
// ---------------------------------------------------------------------------
#define PO_A   0
#define PO_W1  67584
#define PO_W2  135168
#define PO_U   169984
#define PO_B1  204800
#define PO_B2  205312
#define PO_TOTAL 205824
#define RS2 528

__global__ void __launch_bounds__(256, 1)
node_post_kernel(const float* __restrict__ h,
                 const float* __restrict__ Wh1,
                 const float* __restrict__ bh1,
                 const float* __restrict__ Wh2,
                 const float* __restrict__ bh2,
                 float* __restrict__ out) {
    extern __shared__ __align__(16) char smraw[];
    float* b1s = (float*)(smraw + PO_B1);
    float* b2s = (float*)(smraw + PO_B2);

    const uint32_t smem_u32 = smem_to_u32(smraw);
    const int tid  = threadIdx.x;
    const int warp = tid >> 5;
    const int lane = tid & 31;

    for (int idx = tid; idx < 128 * 64; idx += 256) {
        int n = idx >> 6, k4 = (idx & 63) * 4;
        float4 v = *(const float4*)&Wh1[(size_t)n * 256 + k4];
        *(uint2*)(smraw + PO_W1 + n * RS2 + k4 * 2) = pack_bf16x4(v);
    }
    for (int idx = tid; idx < 128 * 32; idx += 256) {
        int n = idx >> 5, k4 = (idx & 31) * 4;
        float4 v = *(const float4*)&Wh2[(size_t)n * 128 + k4];
        *(uint2*)(smraw + PO_W2 + n * RS + k4 * 2) = pack_bf16x4(v);
    }
    for (int k = tid; k < 128; k += 256) {
        b1s[k] = bh1[k];
        b2s[k] = bh2[k];
    }
    __syncthreads();

    const int m0 = warp * 16;
    const int arow = m0 + (lane & 7) + ((lane >> 3) & 1) * 8;
    const uint32_t a1_base = smem_u32 + PO_A + (uint32_t)arow * RS2 + ((lane >> 4) & 1) * 16;
    const uint32_t a2_base = smem_u32 + PO_U + (uint32_t)arow * RS  + ((lane >> 4) & 1) * 16;
    const int bl = lane & 15;
    const uint32_t b1_base = smem_u32 + PO_W1 + (uint32_t)(bl & 7) * RS2 + ((bl >> 3) & 1) * 16;
    const uint32_t b2_base = smem_u32 + PO_W2 + (uint32_t)(bl & 7) * RS  + ((bl >> 3) & 1) * 16;

    const int tig = lane & 3, grp = lane >> 2;
    const int ntiles = (NN + 127) / 128;

    for (int tile = blockIdx.x; tile < ntiles; tile += gridDim.x) {
        const int base = tile * 128;
        __syncthreads();
        for (int idx = tid; idx < 128 * 32; idx += 256) {
            int r = idx >> 5, j4 = (idx & 31) * 4;
            int node = base + r;
            float4 vh = (node < NN) ? *(const float4*)&h[(size_t)node * DH + j4]
                                    : make_float4(0.f, 0.f, 0.f, 0.f);
            float4 vm = (node < NN) ? *(const float4*)&g_msg[(size_t)node * DM + j4]
                                    : make_float4(0.f, 0.f, 0.f, 0.f);
            *(uint2*)(smraw + PO_A + r * RS2 + j4 * 2)         = pack_bf16x4(vh);
            *(uint2*)(smraw + PO_A + r * RS2 + 256 + j4 * 2)   = pack_bf16x4(vm);
        }
        __syncthreads();

        float acc[16][4];
#pragma unroll
        for (int nt = 0; nt < 16; nt++)
#pragma unroll
            for (int r = 0; r < 4; r++) acc[nt][r] = 0.f;
#pragma unroll
        for (int k = 0; k < 16; k++) {
            uint32_t a[4];
            ldmatrix_x4(a[0], a[1], a[2], a[3], a1_base + (uint32_t)k * 32);
#pragma unroll
            for (int nt = 0; nt < 16; nt++) {
                uint32_t b[2];
                ldmatrix_x2(b[0], b[1], b1_base + (uint32_t)nt * (8 * RS2) + (uint32_t)k * 32);
                mma_bf16(acc[nt], a, b, acc[nt]);
            }
        }
#pragma unroll
        for (int nt = 0; nt < 16; nt++) {
            const int c0 = nt * 8 + tig * 2;
            float2 bb = *(float2*)&b1s[c0];
            float v0 = acc[nt][0] + bb.x;
            float v1 = acc[nt][1] + bb.y;
            float v2 = acc[nt][2] + bb.x;
            float v3 = acc[nt][3] + bb.y;
            __nv_bfloat162 q0 = __floats2bfloat162_rn(v0 * fsigmoid(v0), v1 * fsigmoid(v1));
            __nv_bfloat162 q1 = __floats2bfloat162_rn(v2 * fsigmoid(v2), v3 * fsigmoid(v3));
            *(uint32_t*)(smraw + PO_U + (m0 + grp) * RS + c0 * 2)     = *(uint32_t*)&q0;
            *(uint32_t*)(smraw + PO_U + (m0 + grp + 8) * RS + c0 * 2) = *(uint32_t*)&q1;
        }
        __syncthreads();

#pragma unroll
        for (int nt = 0; nt < 16; nt++)
#pragma unroll
            for (int r = 0; r < 4; r++) acc[nt][r] = 0.f;
#pragma unroll
        for (int k = 0; k < 8; k++) {
            uint32_t a[4];
            ldmatrix_x4(a[0], a[1], a[2], a[3], a2_base + (uint32_t)k * 32);
#pragma unroll
            for (int nt = 0; nt < 16; nt++) {
                uint32_t b[2];
                ldmatrix_x2(b[0], b[1], b2_base + (uint32_t)nt * (8 * RS) + (uint32_t)k * 32);
                mma_bf16(acc[nt], a, b, acc[nt]);
            }
        }

        const int node0 = base + m0 + grp;
        const int node1 = node0 + 8;
#pragma unroll
        for (int nt = 0; nt < 16; nt++) {
            const int c0 = nt * 8 + tig * 2;
            float2 bb = *(float2*)&b2s[c0];
            if (node0 < NN) {
                float2 hv = *(const float2*)&h[(size_t)node0 * DH + c0];
                *(float2*)&out[(size_t)node0 * DH + c0] =
                    make_float2(hv.x + acc[nt][0] + bb.x, hv.y + acc[nt][1] + bb.y);
            }
            if (node1 < NN) {
                float2 hv = *(const float2*)&h[(size_t)node1 * DH + c0];
                *(float2*)&out[(size_t)node1 * DH + c0] =
                    make_float2(hv.x + acc[nt][2] + bb.x, hv.y + acc[nt][3] + bb.y);
            }
        }
    }
}

// ---------------------------------------------------------------------------
extern "C" void kernel_launch(void* const* d_in, const int* in_sizes, int n_in,
                              void* d_out, int out_size) {
    const float* x   = (const float*)d_in[0];
    const float* h   = (const float*)d_in[1];
    const float* ea  = (const float*)d_in[2];
    const float* We1 = (const float*)d_in[3];
    const float* be1 = (const float*)d_in[4];
    const float* We2 = (const float*)d_in[5];
    const float* be2 = (const float*)d_in[6];
    const float* Wh1 = (const float*)d_in[7];
    const float* bh1 = (const float*)d_in[8];
    const float* Wh2 = (const float*)d_in[9];
    const float* bh2 = (const float*)d_in[10];
    const float* Wa  = (const float*)d_in[11];
    const float* ba  = (const float*)d_in[12];
    const int*   ei  = (const int*)d_in[13];   // int32
    float* out = (float*)d_out;

    cudaFuncSetAttribute(node_pre_kernel,
                         cudaFuncAttributeMaxDynamicSharedMemorySize, NP_TOTAL);
    cudaFuncSetAttribute(edge_kernel,
                         cudaFuncAttributeMaxDynamicSharedMemorySize, EB_TOTAL);
    cudaFuncSetAttribute(node_post_kernel,
                         cudaFuncAttributeMaxDynamicSharedMemorySize, PO_TOTAL);

    zero_msg_kernel<<<(NN * DM / 4 + 255) / 256, 256>>>();
    node_pre_kernel<<<296, 256, NP_TOTAL>>>(h, We1);
    edge_kernel<<<296, 256, EB_TOTAL>>>(x, ea, We1, be1, We2, be2, Wa, ba, ei);
    node_post_kernel<<<148, 256, PO_TOTAL>>>(h, Wh1, bh1, Wh2, bh2, out);
}

// round 11
// speedup vs baseline: 2.2054x; 1.6985x over previous
#include <cuda_runtime.h>
#include <cuda_bf16.h>
#include <math.h>
#include <stdint.h>

// ----------------------------------------------------------------------------
// IGNN / EGNN layer, GB300 (sm_103a built as sm_103 -> mma.sync, no tcgen05).
// Round 11: edge kernel stage-1 rebuilt — coalesced row-major Ha/Hb gather
// (8x fewer L1tex wavefronts), edge_attr GEMM on HMMA with accumulator init
// from gathered C, m1 kept entirely in registers (D-frag == A-frag columns).
// Node kernels and epilogue/scatter unchanged from R10.
// ----------------------------------------------------------------------------

#define NN 50000
#define NE 800000
#define DH 128
#define DE 16
#define DM 128

__device__ __align__(16) float g_Ha[(size_t)NN * DM];
__device__ __align__(16) float g_Hb[(size_t)NN * DM];
__device__ __align__(16) float g_msg[(size_t)NN * DM];

__device__ __forceinline__ float fsigmoid(float v) {
    return 1.0f / (1.0f + __expf(-v));
}

__device__ __forceinline__ uint32_t smem_to_u32(const void* smem_ptr) {
    uint32_t addr;
    asm("{ .reg .u64 tmp; cvta.to.shared.u64 tmp, %1; cvt.u32.u64 %0, tmp; }"
        : "=r"(addr) : "l"(smem_ptr));
    return addr;
}

__device__ __forceinline__ void ldmatrix_x4(uint32_t& r0, uint32_t& r1,
                                            uint32_t& r2, uint32_t& r3, uint32_t addr) {
    asm volatile("ldmatrix.sync.aligned.m8n8.x4.shared.b16 {%0,%1,%2,%3}, [%4];"
                 : "=r"(r0), "=r"(r1), "=r"(r2), "=r"(r3) : "r"(addr));
}
__device__ __forceinline__ void ldmatrix_x2(uint32_t& r0, uint32_t& r1, uint32_t addr) {
    asm volatile("ldmatrix.sync.aligned.m8n8.x2.shared.b16 {%0,%1}, [%2];"
                 : "=r"(r0), "=r"(r1) : "r"(addr));
}
__device__ __forceinline__ void mma_bf16(float d[4], const uint32_t a[4],
                                         const uint32_t b[2], const float c[4]) {
    asm volatile(
        "mma.sync.aligned.m16n8k16.row.col.f32.bf16.bf16.f32 "
        "{%0,%1,%2,%3}, {%4,%5,%6,%7}, {%8,%9}, {%10,%11,%12,%13};"
        : "=f"(d[0]), "=f"(d[1]), "=f"(d[2]), "=f"(d[3])
        : "r"(a[0]), "r"(a[1]), "r"(a[2]), "r"(a[3]),
          "r"(b[0]), "r"(b[1]),
          "f"(c[0]), "f"(c[1]), "f"(c[2]), "f"(c[3]));
}
__device__ __forceinline__ void red_v4(float* addr, float v0, float v1, float v2, float v3) {
    asm volatile("red.global.add.v4.f32 [%0], {%1, %2, %3, %4};"
                 :: "l"(addr), "f"(v0), "f"(v1), "f"(v2), "f"(v3) : "memory");
}

__device__ __forceinline__ uint2 pack_bf16x4(float4 v) {
    __nv_bfloat162 lo = __floats2bfloat162_rn(v.x, v.y);
    __nv_bfloat162 hi = __floats2bfloat162_rn(v.z, v.w);
    uint2 r;
    r.x = *(uint32_t*)&lo;
    r.y = *(uint32_t*)&hi;
    return r;
}
__device__ __forceinline__ uint32_t pack_bf16x2(float a, float b) {
    __nv_bfloat162 p = __floats2bfloat162_rn(a, b);
    return *(uint32_t*)&p;
}
__device__ __forceinline__ float2 unpack_bf16x2(uint32_t w) {
    __nv_bfloat162 p = *(__nv_bfloat162*)&w;
    return make_float2(__bfloat162float(p.x), __bfloat162float(p.y));
}

// ---------------------------------------------------------------------------
__global__ void zero_msg_kernel() {
    size_t i = (size_t)blockIdx.x * blockDim.x + threadIdx.x;
    size_t n4 = (size_t)NN * DM / 4;
    if (i < n4) ((float4*)g_msg)[i] = make_float4(0.f, 0.f, 0.f, 0.f);
}

// ---------------------------------------------------------------------------
// kernel 1 (HMMA): Ha = h @ W1a^T, Hb = h @ W1b^T.  (unchanged from R10)
// ---------------------------------------------------------------------------
#define NP_A   0
#define NP_WA  34816
#define NP_WB  69632
#define NP_TOTAL 104448
#define RS 272

__global__ void __launch_bounds__(256, 2)
node_pre_kernel(const float* __restrict__ h, const float* __restrict__ We1) {
    extern __shared__ __align__(16) char smraw[];
    const uint32_t smem_u32 = smem_to_u32(smraw);
    const int tid  = threadIdx.x;
    const int warp = tid >> 5;
    const int lane = tid & 31;

    for (int idx = tid; idx < 128 * 128; idx += 256) {
        int n = idx >> 7, k = idx & 127;
        *(__nv_bfloat16*)(smraw + NP_WA + n * RS + k * 2) =
            __float2bfloat16(We1[n * 273 + k]);
        *(__nv_bfloat16*)(smraw + NP_WB + n * RS + k * 2) =
            __float2bfloat16(We1[n * 273 + 128 + k]);
    }
    __syncthreads();

    const int m0 = warp * 16;
    const int arow = m0 + (lane & 7) + ((lane >> 3) & 1) * 8;
    const uint32_t a_base  = smem_u32 + NP_A + (uint32_t)arow * RS + ((lane >> 4) & 1) * 16;
    const int bl = lane & 15;
    const uint32_t ba_base = smem_u32 + NP_WA + (uint32_t)(bl & 7) * RS + ((bl >> 3) & 1) * 16;
    const uint32_t bb_base = smem_u32 + NP_WB + (uint32_t)(bl & 7) * RS + ((bl >> 3) & 1) * 16;

    const int tig = lane & 3, grp = lane >> 2;
    const int ntiles = (NN + 127) / 128;

    for (int tile = blockIdx.x; tile < ntiles; tile += gridDim.x) {
        const int base = tile * 128;
        __syncthreads();
        for (int idx = tid; idx < 128 * 32; idx += 256) {
            int r = idx >> 5, j4 = (idx & 31) * 4;
            int node = base + r;
            float4 v = (node < NN) ? *(const float4*)&h[(size_t)node * DH + j4]
                                   : make_float4(0.f, 0.f, 0.f, 0.f);
            *(uint2*)(smraw + NP_A + r * RS + j4 * 2) = pack_bf16x4(v);
        }
        __syncthreads();

        const int node0 = base + m0 + grp;
        const int node1 = node0 + 8;

        {
            float acc[16][4];
#pragma unroll
            for (int nt = 0; nt < 16; nt++)
#pragma unroll
                for (int r = 0; r < 4; r++) acc[nt][r] = 0.f;
#pragma unroll
            for (int k = 0; k < 8; k++) {
                uint32_t a[4];
                ldmatrix_x4(a[0], a[1], a[2], a[3], a_base + (uint32_t)k * 32);
#pragma unroll
                for (int nt = 0; nt < 16; nt++) {
                    uint32_t b[2];
                    ldmatrix_x2(b[0], b[1], ba_base + (uint32_t)nt * (8 * RS) + (uint32_t)k * 32);
                    mma_bf16(acc[nt], a, b, acc[nt]);
                }
            }
#pragma unroll
            for (int nt = 0; nt < 16; nt++) {
                const int c0 = nt * 8 + tig * 2;
                if (node0 < NN) *(float2*)&g_Ha[(size_t)node0 * DM + c0] =
                    make_float2(acc[nt][0], acc[nt][1]);
                if (node1 < NN) *(float2*)&g_Ha[(size_t)node1 * DM + c0] =
                    make_float2(acc[nt][2], acc[nt][3]);
            }
        }
        {
            float acc[16][4];
#pragma unroll
            for (int nt = 0; nt < 16; nt++)
#pragma unroll
                for (int r = 0; r < 4; r++) acc[nt][r] = 0.f;
#pragma unroll
            for (int k = 0; k < 8; k++) {
                uint32_t a[4];
                ldmatrix_x4(a[0], a[1], a[2], a[3], a_base + (uint32_t)k * 32);
#pragma unroll
                for (int nt = 0; nt < 16; nt++) {
                    uint32_t b[2];
                    ldmatrix_x2(b[0], b[1], bb_base + (uint32_t)nt * (8 * RS) + (uint32_t)k * 32);
                    mma_bf16(acc[nt], a, b, acc[nt]);
                }
            }
#pragma unroll
            for (int nt = 0; nt < 16; nt++) {
                const int c0 = nt * 8 + tig * 2;
                if (node0 < NN) *(float2*)&g_Hb[(size_t)node0 * DM + c0] =
                    make_float2(acc[nt][0], acc[nt][1]);
                if (node1 < NN) *(float2*)&g_Hb[(size_t)node1 * DM + c0] =
                    make_float2(acc[nt][2], acc[nt][3]);
            }
        }
    }
}

// ---------------------------------------------------------------------------
// kernel 2: edge kernel — warp-autonomous, coalesced gather, full-HMMA.
//
// SMEM bytes:
//   [0]      C    : 8 warps x (16 rows x 136 bf16, stride 272B) = 34816
//   [34816]  EA   : 8 warps x (16 rows x 16 bf16, stride 32B)   = 4096
//   [38912]  W2   : 128 x 136 bf16 (We2 as [n][k], stride 272)  = 34816
//   [73728]  W1E  : 128 x 16 bf16 ([n][t], stride 32)           = 4096
//   [77824]  Wr / [78336] be1s / [78848] be2s / [79360] Was : 128 f32 each
//   total 79872 B -> 2 CTAs/SM
// ---------------------------------------------------------------------------
#define EB_C     0
#define EB_EA    34816
#define EB_W2    38912
#define EB_W1E   73728
#define EB_WR    77824
#define EB_BE1   78336
#define EB_BE2   78848
#define EB_WAS   79360
#define EB_TOTAL 79872

#define CSTRIDE 272
#define WARP_C_BYTES (16 * CSTRIDE)   // 4352
#define WARP_EA_BYTES 512

__global__ void __launch_bounds__(256, 2)
edge_kernel(const float* __restrict__ x,
            const float* __restrict__ edge_attr,
            const float* __restrict__ We1,
            const float* __restrict__ be1,
            const float* __restrict__ We2,
            const float* __restrict__ be2,
            const float* __restrict__ Wa,
            const float* __restrict__ ba,
            const int* __restrict__ ei) {
    extern __shared__ __align__(16) char smraw[];
    float* Wr   = (float*)(smraw + EB_WR);
    float* be1s = (float*)(smraw + EB_BE1);
    float* be2s = (float*)(smraw + EB_BE2);
    float* Was  = (float*)(smraw + EB_WAS);

    const uint32_t smem_u32 = smem_to_u32(smraw);
    const int tid  = threadIdx.x;
    const int warp = tid >> 5;
    const int lane = tid & 31;

    // ---- preamble (only block sync in the kernel) ----
    for (int idx = tid; idx < 128 * 128; idx += 256) {
        int n = idx >> 7, k = idx & 127;
        *(__nv_bfloat16*)(smraw + EB_W2 + n * CSTRIDE + k * 2) =
            __float2bfloat16(We2[n * 128 + k]);
    }
    for (int idx = tid; idx < 128 * 16; idx += 256) {
        int n = idx >> 4, t = idx & 15;
        *(__nv_bfloat16*)(smraw + EB_W1E + n * 32 + t * 2) =
            __float2bfloat16(We1[n * 273 + 257 + t]);   // edge_attr cols 257..272
    }
    for (int k = tid; k < 128; k += 256) {
        Wr[k]   = We1[k * 273 + 256];                   // radial col 256
        be1s[k] = be1[k];
        be2s[k] = be2[k];
        Was[k]  = Wa[k];
    }
    const float ba0 = ba[0];
    __syncthreads();

    // per-warp regions
    const uint32_t c_region  = smem_u32 + EB_C  + (uint32_t)warp * WARP_C_BYTES;
    const uint32_t ea_region = smem_u32 + EB_EA + (uint32_t)warp * WARP_EA_BYTES;

    const int tig = lane & 3, grp = lane >> 2;
    // C fragment-read bases (row grp / grp+8, col-pair tig*2)
    const uint32_t c_fr0 = c_region + (uint32_t)grp * CSTRIDE + (uint32_t)tig * 4;
    const uint32_t c_fr1 = c_fr0 + 8 * CSTRIDE;
    // ea a-fragment ldmatrix base (16x16 bf16, stride 32B)
    const uint32_t ea_lm = ea_region + (uint32_t)(lane & 15) * 32 + ((lane >> 4) & 1) * 16;
    // W1E b-fragment base
    const int bl = lane & 15;
    const uint32_t w1e_base = smem_u32 + EB_W1E + (uint32_t)(bl & 7) * 32 + ((bl >> 3) & 1) * 16;
    // We2 b-fragment x4 nt-pair base (stride 272)
    const uint32_t b4_base = smem_u32 + EB_W2
                           + (uint32_t)((lane & 7) + ((lane >> 4) & 1) * 8) * CSTRIDE
                           + ((lane >> 3) & 1) * 16;

    const int jj = tig >> 1;
    const bool isOdd = (tig & 1) != 0;

    const int NWT = NE / 16;             // 50000 warp-tiles
    const int wstride = gridDim.x * 8;

    // per-lane constant vectors for C build
    const float4 wr4  = *(const float4*)(Wr + lane * 4);
    const float4 be14 = *(const float4*)(be1s + lane * 4);

    for (int wt = blockIdx.x * 8 + warp; wt < NWT; wt += wstride) {
        const int base = wt * 16;

        // ---- per-edge indices (lanes 0..15) ----
        int rld = 0, cld = 0;
        float radld = 0.f;
        if (lane < 16) {
            rld = ei[base + lane];
            cld = ei[NE + base + lane];
            float dx = x[(size_t)rld * 3 + 0] - x[(size_t)cld * 3 + 0];
            float dy = x[(size_t)rld * 3 + 1] - x[(size_t)cld * 3 + 1];
            float dz = x[(size_t)rld * 3 + 2] - x[(size_t)cld * 3 + 2];
            radld = sqrtf(dx * dx + dy * dy + dz * dz);
        }

        // ---- coalesced gather: C[e] = Ha[row_e] + Hb[col_e] + rad*wr + be1 ----
#pragma unroll
        for (int e = 0; e < 16; e++) {
            const int   row  = __shfl_sync(0xFFFFFFFF, rld, e);
            const int   colN = __shfl_sync(0xFFFFFFFF, cld, e);
            const float rv   = __shfl_sync(0xFFFFFFFF, radld, e);
            float4 ha = *(const float4*)&g_Ha[(size_t)row  * DM + lane * 4];
            float4 hb = *(const float4*)&g_Hb[(size_t)colN * DM + lane * 4];
            float4 c;
            c.x = ha.x + hb.x + be14.x + rv * wr4.x;
            c.y = ha.y + hb.y + be14.y + rv * wr4.y;
            c.z = ha.z + hb.z + be14.z + rv * wr4.z;
            c.w = ha.w + hb.w + be14.w + rv * wr4.w;
            *(uint2*)(smraw + (c_region - smem_u32) + e * CSTRIDE + lane * 8) = pack_bf16x4(c);
        }

        // ---- ea staging (bf16, [16 x 16], stride 32B) ----
        {
            int e = lane >> 1, hf2 = lane & 1;
            const float4* pe = (const float4*)(edge_attr + (size_t)(base + e) * DE + hf2 * 8);
            float4 u0 = pe[0], u1 = pe[1];
            uint2 w0 = pack_bf16x4(u0), w1 = pack_bf16x4(u1);
            *(uint4*)(smraw + (ea_region - smem_u32) + e * 32 + hf2 * 16) =
                make_uint4(w0.x, w0.y, w1.x, w1.y);
        }
        __syncwarp();

        // ---- stage 1 HMMA: dacc = C + ea @ W1e^T  (K=16) ----
        float dacc[16][4];
#pragma unroll
        for (int nt = 0; nt < 16; nt++) {
            uint32_t lo = *(const uint32_t*)(smraw + (c_fr0 - smem_u32) + nt * 16);
            uint32_t hi = *(const uint32_t*)(smraw + (c_fr1 - smem_u32) + nt * 16);
            float2 f0 = unpack_bf16x2(lo);
            float2 f1 = unpack_bf16x2(hi);
            dacc[nt][0] = f0.x; dacc[nt][1] = f0.y;
            dacc[nt][2] = f1.x; dacc[nt][3] = f1.y;
        }
        {
            uint32_t aea[4];
            ldmatrix_x4(aea[0], aea[1], aea[2], aea[3], ea_lm);
#pragma unroll
            for (int nt = 0; nt < 16; nt++) {
                uint32_t b[2];
                ldmatrix_x2(b[0], b[1], w1e_base + (uint32_t)nt * 256);
                mma_bf16(dacc[nt], aea, b, dacc[nt]);
            }
        }
        __syncwarp();   // C/EA regions reused next iteration

        // ---- silu -> register a-fragments (m1 never touches smem) ----
        uint32_t au[8][4];
#pragma unroll
        for (int kk = 0; kk < 8; kk++) {
            float* d0 = dacc[2 * kk];
            float* d1 = dacc[2 * kk + 1];
            float s00 = d0[0] * fsigmoid(d0[0]);
            float s01 = d0[1] * fsigmoid(d0[1]);
            float s02 = d0[2] * fsigmoid(d0[2]);
            float s03 = d0[3] * fsigmoid(d0[3]);
            float s10 = d1[0] * fsigmoid(d1[0]);
            float s11 = d1[1] * fsigmoid(d1[1]);
            float s12 = d1[2] * fsigmoid(d1[2]);
            float s13 = d1[3] * fsigmoid(d1[3]);
            au[kk][0] = pack_bf16x2(s00, s01);   // row grp,   k = kk*16+tig*2
            au[kk][1] = pack_bf16x2(s02, s03);   // row grp+8, k = kk*16+tig*2
            au[kk][2] = pack_bf16x2(s10, s11);   // row grp,   k = kk*16+8+tig*2
            au[kk][3] = pack_bf16x2(s12, s13);   // row grp+8, k = kk*16+8+tig*2
        }

        // ---- stage 2 HMMA: D = m1 @ We2^T ----
        float dd[16][4];
#pragma unroll
        for (int nt = 0; nt < 16; nt++)
#pragma unroll
            for (int r = 0; r < 4; r++) dd[nt][r] = 0.f;

#pragma unroll
        for (int kk = 0; kk < 8; kk++) {
#pragma unroll
            for (int ntp = 0; ntp < 8; ntp++) {
                uint32_t b4[4];
                ldmatrix_x4(b4[0], b4[1], b4[2], b4[3],
                            b4_base + (uint32_t)ntp * (16 * CSTRIDE) + (uint32_t)kk * 32);
                mma_bf16(dd[2 * ntp],     au[kk], b4,     dd[2 * ntp]);
                mma_bf16(dd[2 * ntp + 1], au[kk], b4 + 2, dd[2 * ntp + 1]);
            }
        }

        // ---- epilogue: silu, attention, RED v4 scatter ----
        float pr0 = 0.f, pr1 = 0.f;
#pragma unroll
        for (int nt = 0; nt < 16; nt++) {
            const int c0 = nt * 8 + tig * 2;
            float2 bb = *(float2*)&be2s[c0];
            float2 wa = *(float2*)&Was[c0];
            float v0 = dd[nt][0] + bb.x;
            float v1 = dd[nt][1] + bb.y;
            float v2 = dd[nt][2] + bb.x;
            float v3 = dd[nt][3] + bb.y;
            float s0 = v0 * fsigmoid(v0);
            float s1 = v1 * fsigmoid(v1);
            float s2 = v2 * fsigmoid(v2);
            float s3 = v3 * fsigmoid(v3);
            dd[nt][0] = s0; dd[nt][1] = s1; dd[nt][2] = s2; dd[nt][3] = s3;
            pr0 += s0 * wa.x + s1 * wa.y;
            pr1 += s2 * wa.x + s3 * wa.y;
        }
        pr0 += __shfl_xor_sync(0xFFFFFFFF, pr0, 1);
        pr0 += __shfl_xor_sync(0xFFFFFFFF, pr0, 2);
        pr1 += __shfl_xor_sync(0xFFFFFFFF, pr1, 1);
        pr1 += __shfl_xor_sync(0xFFFFFFFF, pr1, 2);
        const float att0 = fsigmoid(pr0 + ba0);
        const float att1 = fsigmoid(pr1 + ba0);

        const int node0 = __shfl_sync(0xFFFFFFFF, rld, grp);
        const int node1 = __shfl_sync(0xFFFFFFFF, rld, grp + 8);
        const float attm = isOdd ? att1 : att0;
        float* dst = g_msg + (size_t)(isOdd ? node1 : node0) * DM + jj * 4;
#pragma unroll
        for (int nt = 0; nt < 16; nt++) {
            float s0 = dd[nt][0], s1 = dd[nt][1];
            float s2 = dd[nt][2], s3 = dd[nt][3];
            float q0 = __shfl_xor_sync(0xFFFFFFFF, s0, 1);
            float q1 = __shfl_xor_sync(0xFFFFFFFF, s1, 1);
            float q2 = __shfl_xor_sync(0xFFFFFFFF, s2, 1);
            float q3 = __shfl_xor_sync(0xFFFFFFFF, s3, 1);
            float v0 = isOdd ? q2 : s0;
            float v1 = isOdd ? q3 : s1;
            float v2 = isOdd ? s2 : q0;
            float v3 = isOdd ? s3 : q1;
            red_v4(dst + nt * 8, v0 * attm, v1 * attm, v2 * attm, v3 * attm);
        }
    }
}

// ---------------------------------------------------------------------------
// kernel 3 (HMMA): node post.  (unchanged from R10)
// ---------------------------------------------------------------------------
#define PO_A   0
#define PO_W1  67584
#define PO_W2  135168
#define PO_U   169984
#define PO_B1  204800
#define PO_B2  205312
#define PO_TOTAL 205824
#define RS2 528

__global__ void __launch_bounds__(256, 1)
node_post_kernel(const float* __restrict__ h,
                 const float* __restrict__ Wh1,
                 const float* __restrict__ bh1,
                 const float* __restrict__ Wh2,
                 const float* __restrict__ bh2,
                 float* __restrict__ out) {
    extern __shared__ __align__(16) char smraw[];
    float* b1s = (float*)(smraw + PO_B1);
    float* b2s = (float*)(smraw + PO_B2);

    const uint32_t smem_u32 = smem_to_u32(smraw);
    const int tid  = threadIdx.x;
    const int warp = tid >> 5;
    const int lane = tid & 31;

    for (int idx = tid; idx < 128 * 64; idx += 256) {
        int n = idx >> 6, k4 = (idx & 63) * 4;
        float4 v = *(const float4*)&Wh1[(size_t)n * 256 + k4];
        *(uint2*)(smraw + PO_W1 + n * RS2 + k4 * 2) = pack_bf16x4(v);
    }
    for (int idx = tid; idx < 128 * 32; idx += 256) {
        int n = idx >> 5, k4 = (idx & 31) * 4;
        float4 v = *(const float4*)&Wh2[(size_t)n * 128 + k4];
        *(uint2*)(smraw + PO_W2 + n * RS + k4 * 2) = pack_bf16x4(v);
    }
    for (int k = tid; k < 128; k += 256) {
        b1s[k] = bh1[k];
        b2s[k] = bh2[k];
    }
    __syncthreads();

    const int m0 = warp * 16;
    const int arow = m0 + (lane & 7) + ((lane >> 3) & 1) * 8;
    const uint32_t a1_base = smem_u32 + PO_A + (uint32_t)arow * RS2 + ((lane >> 4) & 1) * 16;
    const uint32_t a2_base = smem_u32 + PO_U + (uint32_t)arow * RS  + ((lane >> 4) & 1) * 16;
    const int bl = lane & 15;
    const uint32_t b1_base = smem_u32 + PO_W1 + (uint32_t)(bl & 7) * RS2 + ((bl >> 3) & 1) * 16;
    const uint32_t b2_base = smem_u32 + PO_W2 + (uint32_t)(bl & 7) * RS  + ((bl >> 3) & 1) * 16;

    const int tig = lane & 3, grp = lane >> 2;
    const int ntiles = (NN + 127) / 128;

    for (int tile = blockIdx.x; tile < ntiles; tile += gridDim.x) {
        const int base = tile * 128;
        __syncthreads();
        for (int idx = tid; idx < 128 * 32; idx += 256) {
            int r = idx >> 5, j4 = (idx & 31) * 4;
            int node = base + r;
            float4 vh = (node < NN) ? *(const float4*)&h[(size_t)node * DH + j4]
                                    : make_float4(0.f, 0.f, 0.f, 0.f);
            float4 vm = (node < NN) ? *(const float4*)&g_msg[(size_t)node * DM + j4]
                                    : make_float4(0.f, 0.f, 0.f, 0.f);
            *(uint2*)(smraw + PO_A + r * RS2 + j4 * 2)         = pack_bf16x4(vh);
            *(uint2*)(smraw + PO_A + r * RS2 + 256 + j4 * 2)   = pack_bf16x4(vm);
        }
        __syncthreads();

        float acc[16][4];
#pragma unroll
        for (int nt = 0; nt < 16; nt++)
#pragma unroll
            for (int r = 0; r < 4; r++) acc[nt][r] = 0.f;
#pragma unroll
        for (int k = 0; k < 16; k++) {
            uint32_t a[4];
            ldmatrix_x4(a[0], a[1], a[2], a[3], a1_base + (uint32_t)k * 32);
#pragma unroll
            for (int nt = 0; nt < 16; nt++) {
                uint32_t b[2];
                ldmatrix_x2(b[0], b[1], b1_base + (uint32_t)nt * (8 * RS2) + (uint32_t)k * 32);
                mma_bf16(acc[nt], a, b, acc[nt]);
            }
        }
#pragma unroll
        for (int nt = 0; nt < 16; nt++) {
            const int c0 = nt * 8 + tig * 2;
            float2 bb = *(float2*)&b1s[c0];
            float v0 = acc[nt][0] + bb.x;
            float v1 = acc[nt][1] + bb.y;
            float v2 = acc[nt][2] + bb.x;
            float v3 = acc[nt][3] + bb.y;
            uint32_t q0 = pack_bf16x2(v0 * fsigmoid(v0), v1 * fsigmoid(v1));
            uint32_t q1 = pack_bf16x2(v2 * fsigmoid(v2), v3 * fsigmoid(v3));
            *(uint32_t*)(smraw + PO_U + (m0 + grp) * RS + c0 * 2)     = q0;
            *(uint32_t*)(smraw + PO_U + (m0 + grp + 8) * RS + c0 * 2) = q1;
        }
        __syncthreads();

#pragma unroll
        for (int nt = 0; nt < 16; nt++)
#pragma unroll
            for (int r = 0; r < 4; r++) acc[nt][r] = 0.f;
#pragma unroll
        for (int k = 0; k < 8; k++) {
            uint32_t a[4];
            ldmatrix_x4(a[0], a[1], a[2], a[3], a2_base + (uint32_t)k * 32);
#pragma unroll
            for (int nt = 0; nt < 16; nt++) {
                uint32_t b[2];
                ldmatrix_x2(b[0], b[1], b2_base + (uint32_t)nt * (8 * RS) + (uint32_t)k * 32);
                mma_bf16(acc[nt], a, b, acc[nt]);
            }
        }

        const int node0 = base + m0 + grp;
        const int node1 = node0 + 8;
#pragma unroll
        for (int nt = 0; nt < 16; nt++) {
            const int c0 = nt * 8 + tig * 2;
            float2 bb = *(float2*)&b2s[c0];
            if (node0 < NN) {
                float2 hv = *(const float2*)&h[(size_t)node0 * DH + c0];
                *(float2*)&out[(size_t)node0 * DH + c0] =
                    make_float2(hv.x + acc[nt][0] + bb.x, hv.y + acc[nt][1] + bb.y);
            }
            if (node1 < NN) {
                float2 hv = *(const float2*)&h[(size_t)node1 * DH + c0];
                *(float2*)&out[(size_t)node1 * DH + c0] =
                    make_float2(hv.x + acc[nt][2] + bb.x, hv.y + acc[nt][3] + bb.y);
            }
        }
    }
}

// ---------------------------------------------------------------------------
extern "C" void kernel_launch(void* const* d_in, const int* in_sizes, int n_in,
                              void* d_out, int out_size) {
    const float* x   = (const float*)d_in[0];
    const float* h   = (const float*)d_in[1];
    const float* ea  = (const float*)d_in[2];
    const float* We1 = (const float*)d_in[3];
    const float* be1 = (const float*)d_in[4];
    const float* We2 = (const float*)d_in[5];
    const float* be2 = (const float*)d_in[6];
    const float* Wh1 = (const float*)d_in[7];
    const float* bh1 = (const float*)d_in[8];
    const float* Wh2 = (const float*)d_in[9];
    const float* bh2 = (const float*)d_in[10];
    const float* Wa  = (const float*)d_in[11];
    const float* ba  = (const float*)d_in[12];
    const int*   ei  = (const int*)d_in[13];   // int32
    float* out = (float*)d_out;

    cudaFuncSetAttribute(node_pre_kernel,
                         cudaFuncAttributeMaxDynamicSharedMemorySize, NP_TOTAL);
    cudaFuncSetAttribute(edge_kernel,
                         cudaFuncAttributeMaxDynamicSharedMemorySize, EB_TOTAL);
    cudaFuncSetAttribute(node_post_kernel,
                         cudaFuncAttributeMaxDynamicSharedMemorySize, PO_TOTAL);

    zero_msg_kernel<<<(NN * DM / 4 + 255) / 256, 256>>>();
    node_pre_kernel<<<296, 256, NP_TOTAL>>>(h, We1);
    edge_kernel<<<296, 256, EB_TOTAL>>>(x, ea, We1, be1, We2, be2, Wa, ba, ei);
    node_post_kernel<<<148, 256, PO_TOTAL>>>(h, Wh1, bh1, Wh2, bh2, out);
}

// round 12
// speedup vs baseline: 2.2282x; 1.0103x over previous
#include <cuda_runtime.h>
#include <cuda_bf16.h>
#include <math.h>
#include <stdint.h>

// ----------------------------------------------------------------------------
// IGNN / EGNN layer, GB300 (sm_103a built as sm_103 -> mma.sync, no tcgen05).
// Round 12: node-side compound — zero_msg folded into node_pre, node_pre
// A-fragment reuse across Ha/Hb GEMMs + x4 B-pairs, node_post x4 B-pairs.
// Edge kernel unchanged from R11 (proven 365us).
// ----------------------------------------------------------------------------

#define NN 50000
#define NE 800000
#define DH 128
#define DE 16
#define DM 128

__device__ __align__(16) float g_Ha[(size_t)NN * DM];
__device__ __align__(16) float g_Hb[(size_t)NN * DM];
__device__ __align__(16) float g_msg[(size_t)NN * DM];

__device__ __forceinline__ float fsigmoid(float v) {
    return 1.0f / (1.0f + __expf(-v));
}

__device__ __forceinline__ uint32_t smem_to_u32(const void* smem_ptr) {
    uint32_t addr;
    asm("{ .reg .u64 tmp; cvta.to.shared.u64 tmp, %1; cvt.u32.u64 %0, tmp; }"
        : "=r"(addr) : "l"(smem_ptr));
    return addr;
}

__device__ __forceinline__ void ldmatrix_x4(uint32_t& r0, uint32_t& r1,
                                            uint32_t& r2, uint32_t& r3, uint32_t addr) {
    asm volatile("ldmatrix.sync.aligned.m8n8.x4.shared.b16 {%0,%1,%2,%3}, [%4];"
                 : "=r"(r0), "=r"(r1), "=r"(r2), "=r"(r3) : "r"(addr));
}
__device__ __forceinline__ void ldmatrix_x2(uint32_t& r0, uint32_t& r1, uint32_t addr) {
    asm volatile("ldmatrix.sync.aligned.m8n8.x2.shared.b16 {%0,%1}, [%2];"
                 : "=r"(r0), "=r"(r1) : "r"(addr));
}
__device__ __forceinline__ void mma_bf16(float d[4], const uint32_t a[4],
                                         const uint32_t b[2], const float c[4]) {
    asm volatile(
        "mma.sync.aligned.m16n8k16.row.col.f32.bf16.bf16.f32 "
        "{%0,%1,%2,%3}, {%4,%5,%6,%7}, {%8,%9}, {%10,%11,%12,%13};"
        : "=f"(d[0]), "=f"(d[1]), "=f"(d[2]), "=f"(d[3])
        : "r"(a[0]), "r"(a[1]), "r"(a[2]), "r"(a[3]),
          "r"(b[0]), "r"(b[1]),
          "f"(c[0]), "f"(c[1]), "f"(c[2]), "f"(c[3]));
}
__device__ __forceinline__ void red_v4(float* addr, float v0, float v1, float v2, float v3) {
    asm volatile("red.global.add.v4.f32 [%0], {%1, %2, %3, %4};"
                 :: "l"(addr), "f"(v0), "f"(v1), "f"(v2), "f"(v3) : "memory");
}

__device__ __forceinline__ uint2 pack_bf16x4(float4 v) {
    __nv_bfloat162 lo = __floats2bfloat162_rn(v.x, v.y);
    __nv_bfloat162 hi = __floats2bfloat162_rn(v.z, v.w);
    uint2 r;
    r.x = *(uint32_t*)&lo;
    r.y = *(uint32_t*)&hi;
    return r;
}
__device__ __forceinline__ uint32_t pack_bf16x2(float a, float b) {
    __nv_bfloat162 p = __floats2bfloat162_rn(a, b);
    return *(uint32_t*)&p;
}
__device__ __forceinline__ float2 unpack_bf16x2(uint32_t w) {
    __nv_bfloat162 p = *(__nv_bfloat162*)&w;
    return make_float2(__bfloat162float(p.x), __bfloat162float(p.y));
}

// ---------------------------------------------------------------------------
// kernel 1 (HMMA): Ha = h @ W1a^T, Hb = h @ W1b^T + g_msg zeroing.
// A-fragments cached across both GEMMs; B via x4 nt-pairs.
// ---------------------------------------------------------------------------
#define NP_A   0
#define NP_WA  34816
#define NP_WB  69632
#define NP_TOTAL 104448
#define RS 272

__global__ void __launch_bounds__(256, 2)
node_pre_kernel(const float* __restrict__ h, const float* __restrict__ We1) {
    extern __shared__ __align__(16) char smraw[];
    const uint32_t smem_u32 = smem_to_u32(smraw);
    const int tid  = threadIdx.x;
    const int warp = tid >> 5;
    const int lane = tid & 31;

    for (int idx = tid; idx < 128 * 128; idx += 256) {
        int n = idx >> 7, k = idx & 127;
        *(__nv_bfloat16*)(smraw + NP_WA + n * RS + k * 2) =
            __float2bfloat16(We1[n * 273 + k]);
        *(__nv_bfloat16*)(smraw + NP_WB + n * RS + k * 2) =
            __float2bfloat16(We1[n * 273 + 128 + k]);
    }
    __syncthreads();

    const int m0 = warp * 16;
    const int arow = m0 + (lane & 7) + ((lane >> 3) & 1) * 8;
    const uint32_t a_base  = smem_u32 + NP_A + (uint32_t)arow * RS + ((lane >> 4) & 1) * 16;
    // x4 nt-pair B bases
    const uint32_t ba4_base = smem_u32 + NP_WA
                            + (uint32_t)((lane & 7) + ((lane >> 4) & 1) * 8) * RS
                            + ((lane >> 3) & 1) * 16;
    const uint32_t bb4_base = ba4_base + (NP_WB - NP_WA);

    const int tig = lane & 3, grp = lane >> 2;
    const int ntiles = (NN + 127) / 128;

    for (int tile = blockIdx.x; tile < ntiles; tile += gridDim.x) {
        const int base = tile * 128;
        __syncthreads();
        for (int idx = tid; idx < 128 * 32; idx += 256) {
            int r = idx >> 5, j4 = (idx & 31) * 4;
            int node = base + r;
            float4 v = make_float4(0.f, 0.f, 0.f, 0.f);
            if (node < NN) {
                v = *(const float4*)&h[(size_t)node * DH + j4];
                *(float4*)&g_msg[(size_t)node * DM + j4] = make_float4(0.f, 0.f, 0.f, 0.f);
            }
            *(uint2*)(smraw + NP_A + r * RS + j4 * 2) = pack_bf16x4(v);
        }
        __syncthreads();

        const int node0 = base + m0 + grp;
        const int node1 = node0 + 8;

        // A fragments cached for both GEMMs (8 k-steps x 4 regs = 32)
        uint32_t afr[8][4];
#pragma unroll
        for (int k = 0; k < 8; k++)
            ldmatrix_x4(afr[k][0], afr[k][1], afr[k][2], afr[k][3],
                        a_base + (uint32_t)k * 32);

        float acc[16][4];

        // GEMM A -> Ha
#pragma unroll
        for (int nt = 0; nt < 16; nt++)
#pragma unroll
            for (int r = 0; r < 4; r++) acc[nt][r] = 0.f;
#pragma unroll
        for (int k = 0; k < 8; k++) {
#pragma unroll
            for (int ntp = 0; ntp < 8; ntp++) {
                uint32_t b4[4];
                ldmatrix_x4(b4[0], b4[1], b4[2], b4[3],
                            ba4_base + (uint32_t)ntp * (16 * RS) + (uint32_t)k * 32);
                mma_bf16(acc[2 * ntp],     afr[k], b4,     acc[2 * ntp]);
                mma_bf16(acc[2 * ntp + 1], afr[k], b4 + 2, acc[2 * ntp + 1]);
            }
        }
#pragma unroll
        for (int nt = 0; nt < 16; nt++) {
            const int c0 = nt * 8 + tig * 2;
            if (node0 < NN) *(float2*)&g_Ha[(size_t)node0 * DM + c0] =
                make_float2(acc[nt][0], acc[nt][1]);
            if (node1 < NN) *(float2*)&g_Ha[(size_t)node1 * DM + c0] =
                make_float2(acc[nt][2], acc[nt][3]);
        }

        // GEMM B -> Hb (reuse afr)
#pragma unroll
        for (int nt = 0; nt < 16; nt++)
#pragma unroll
            for (int r = 0; r < 4; r++) acc[nt][r] = 0.f;
#pragma unroll
        for (int k = 0; k < 8; k++) {
#pragma unroll
            for (int ntp = 0; ntp < 8; ntp++) {
                uint32_t b4[4];
                ldmatrix_x4(b4[0], b4[1], b4[2], b4[3],
                            bb4_base + (uint32_t)ntp * (16 * RS) + (uint32_t)k * 32);
                mma_bf16(acc[2 * ntp],     afr[k], b4,     acc[2 * ntp]);
                mma_bf16(acc[2 * ntp + 1], afr[k], b4 + 2, acc[2 * ntp + 1]);
            }
        }
#pragma unroll
        for (int nt = 0; nt < 16; nt++) {
            const int c0 = nt * 8 + tig * 2;
            if (node0 < NN) *(float2*)&g_Hb[(size_t)node0 * DM + c0] =
                make_float2(acc[nt][0], acc[nt][1]);
            if (node1 < NN) *(float2*)&g_Hb[(size_t)node1 * DM + c0] =
                make_float2(acc[nt][2], acc[nt][3]);
        }
    }
}

// ---------------------------------------------------------------------------
// kernel 2: edge kernel — warp-autonomous, coalesced gather, full-HMMA.
// (unchanged from R11)
// ---------------------------------------------------------------------------
#define EB_C     0
#define EB_EA    34816
#define EB_W2    38912
#define EB_W1E   73728
#define EB_WR    77824
#define EB_BE1   78336
#define EB_BE2   78848
#define EB_WAS   79360
#define EB_TOTAL 79872

#define CSTRIDE 272
#define WARP_C_BYTES (16 * CSTRIDE)
#define WARP_EA_BYTES 512

__global__ void __launch_bounds__(256, 2)
edge_kernel(const float* __restrict__ x,
            const float* __restrict__ edge_attr,
            const float* __restrict__ We1,
            const float* __restrict__ be1,
            const float* __restrict__ We2,
            const float* __restrict__ be2,
            const float* __restrict__ Wa,
            const float* __restrict__ ba,
            const int* __restrict__ ei) {
    extern __shared__ __align__(16) char smraw[];
    float* Wr   = (float*)(smraw + EB_WR);
    float* be1s = (float*)(smraw + EB_BE1);
    float* be2s = (float*)(smraw + EB_BE2);
    float* Was  = (float*)(smraw + EB_WAS);

    const uint32_t smem_u32 = smem_to_u32(smraw);
    const int tid  = threadIdx.x;
    const int warp = tid >> 5;
    const int lane = tid & 31;

    for (int idx = tid; idx < 128 * 128; idx += 256) {
        int n = idx >> 7, k = idx & 127;
        *(__nv_bfloat16*)(smraw + EB_W2 + n * CSTRIDE + k * 2) =
            __float2bfloat16(We2[n * 128 + k]);
    }
    for (int idx = tid; idx < 128 * 16; idx += 256) {
        int n = idx >> 4, t = idx & 15;
        *(__nv_bfloat16*)(smraw + EB_W1E + n * 32 + t * 2) =
            __float2bfloat16(We1[n * 273 + 257 + t]);
    }
    for (int k = tid; k < 128; k += 256) {
        Wr[k]   = We1[k * 273 + 256];
        be1s[k] = be1[k];
        be2s[k] = be2[k];
        Was[k]  = Wa[k];
    }
    const float ba0 = ba[0];
    __syncthreads();

    const uint32_t c_region  = smem_u32 + EB_C  + (uint32_t)warp * WARP_C_BYTES;
    const uint32_t ea_region = smem_u32 + EB_EA + (uint32_t)warp * WARP_EA_BYTES;

    const int tig = lane & 3, grp = lane >> 2;
    const uint32_t c_fr0 = c_region + (uint32_t)grp * CSTRIDE + (uint32_t)tig * 4;
    const uint32_t c_fr1 = c_fr0 + 8 * CSTRIDE;
    const uint32_t ea_lm = ea_region + (uint32_t)(lane & 15) * 32 + ((lane >> 4) & 1) * 16;
    const int bl = lane & 15;
    const uint32_t w1e_base = smem_u32 + EB_W1E + (uint32_t)(bl & 7) * 32 + ((bl >> 3) & 1) * 16;
    const uint32_t b4_base = smem_u32 + EB_W2
                           + (uint32_t)((lane & 7) + ((lane >> 4) & 1) * 8) * CSTRIDE
                           + ((lane >> 3) & 1) * 16;

    const int jj = tig >> 1;
    const bool isOdd = (tig & 1) != 0;

    const int NWT = NE / 16;
    const int wstride = gridDim.x * 8;

    const float4 wr4  = *(const float4*)(Wr + lane * 4);
    const float4 be14 = *(const float4*)(be1s + lane * 4);

    for (int wt = blockIdx.x * 8 + warp; wt < NWT; wt += wstride) {
        const int base = wt * 16;

        int rld = 0, cld = 0;
        float radld = 0.f;
        if (lane < 16) {
            rld = ei[base + lane];
            cld = ei[NE + base + lane];
            float dx = x[(size_t)rld * 3 + 0] - x[(size_t)cld * 3 + 0];
            float dy = x[(size_t)rld * 3 + 1] - x[(size_t)cld * 3 + 1];
            float dz = x[(size_t)rld * 3 + 2] - x[(size_t)cld * 3 + 2];
            radld = sqrtf(dx * dx + dy * dy + dz * dz);
        }

#pragma unroll
        for (int e = 0; e < 16; e++) {
            const int   row  = __shfl_sync(0xFFFFFFFF, rld, e);
            const int   colN = __shfl_sync(0xFFFFFFFF, cld, e);
            const float rv   = __shfl_sync(0xFFFFFFFF, radld, e);
            float4 ha = *(const float4*)&g_Ha[(size_t)row  * DM + lane * 4];
            float4 hb = *(const float4*)&g_Hb[(size_t)colN * DM + lane * 4];
            float4 c;
            c.x = ha.x + hb.x + be14.x + rv * wr4.x;
            c.y = ha.y + hb.y + be14.y + rv * wr4.y;
            c.z = ha.z + hb.z + be14.z + rv * wr4.z;
            c.w = ha.w + hb.w + be14.w + rv * wr4.w;
            *(uint2*)(smraw + (c_region - smem_u32) + e * CSTRIDE + lane * 8) = pack_bf16x4(c);
        }

        {
            int e = lane >> 1, hf2 = lane & 1;
            const float4* pe = (const float4*)(edge_attr + (size_t)(base + e) * DE + hf2 * 8);
            float4 u0 = pe[0], u1 = pe[1];
            uint2 w0 = pack_bf16x4(u0), w1 = pack_bf16x4(u1);
            *(uint4*)(smraw + (ea_region - smem_u32) + e * 32 + hf2 * 16) =
                make_uint4(w0.x, w0.y, w1.x, w1.y);
        }
        __syncwarp();

        float dacc[16][4];
#pragma unroll
        for (int nt = 0; nt < 16; nt++) {
            uint32_t lo = *(const uint32_t*)(smraw + (c_fr0 - smem_u32) + nt * 16);
            uint32_t hi = *(const uint32_t*)(smraw + (c_fr1 - smem_u32) + nt * 16);
            float2 f0 = unpack_bf16x2(lo);
            float2 f1 = unpack_bf16x2(hi);
            dacc[nt][0] = f0.x; dacc[nt][1] = f0.y;
            dacc[nt][2] = f1.x; dacc[nt][3] = f1.y;
        }
        {
            uint32_t aea[4];
            ldmatrix_x4(aea[0], aea[1], aea[2], aea[3], ea_lm);
#pragma unroll
            for (int nt = 0; nt < 16; nt++) {
                uint32_t b[2];
                ldmatrix_x2(b[0], b[1], w1e_base + (uint32_t)nt * 256);
                mma_bf16(dacc[nt], aea, b, dacc[nt]);
            }
        }
        __syncwarp();

        uint32_t au[8][4];
#pragma unroll
        for (int kk = 0; kk < 8; kk++) {
            float* d0 = dacc[2 * kk];
            float* d1 = dacc[2 * kk + 1];
            float s00 = d0[0] * fsigmoid(d0[0]);
            float s01 = d0[1] * fsigmoid(d0[1]);
            float s02 = d0[2] * fsigmoid(d0[2]);
            float s03 = d0[3] * fsigmoid(d0[3]);
            float s10 = d1[0] * fsigmoid(d1[0]);
            float s11 = d1[1] * fsigmoid(d1[1]);
            float s12 = d1[2] * fsigmoid(d1[2]);
            float s13 = d1[3] * fsigmoid(d1[3]);
            au[kk][0] = pack_bf16x2(s00, s01);
            au[kk][1] = pack_bf16x2(s02, s03);
            au[kk][2] = pack_bf16x2(s10, s11);
            au[kk][3] = pack_bf16x2(s12, s13);
        }

        float dd[16][4];
#pragma unroll
        for (int nt = 0; nt < 16; nt++)
#pragma unroll
            for (int r = 0; r < 4; r++) dd[nt][r] = 0.f;

#pragma unroll
        for (int kk = 0; kk < 8; kk++) {
#pragma unroll
            for (int ntp = 0; ntp < 8; ntp++) {
                uint32_t b4[4];
                ldmatrix_x4(b4[0], b4[1], b4[2], b4[3],
                            b4_base + (uint32_t)ntp * (16 * CSTRIDE) + (uint32_t)kk * 32);
                mma_bf16(dd[2 * ntp],     au[kk], b4,     dd[2 * ntp]);
                mma_bf16(dd[2 * ntp + 1], au[kk], b4 + 2, dd[2 * ntp + 1]);
            }
        }

        float pr0 = 0.f, pr1 = 0.f;
#pragma unroll
        for (int nt = 0; nt < 16; nt++) {
            const int c0 = nt * 8 + tig * 2;
            float2 bb = *(float2*)&be2s[c0];
            float2 wa = *(float2*)&Was[c0];
            float v0 = dd[nt][0] + bb.x;
            float v1 = dd[nt][1] + bb.y;
            float v2 = dd[nt][2] + bb.x;
            float v3 = dd[nt][3] + bb.y;
            float s0 = v0 * fsigmoid(v0);
            float s1 = v1 * fsigmoid(v1);
            float s2 = v2 * fsigmoid(v2);
            float s3 = v3 * fsigmoid(v3);
            dd[nt][0] = s0; dd[nt][1] = s1; dd[nt][2] = s2; dd[nt][3] = s3;
            pr0 += s0 * wa.x + s1 * wa.y;
            pr1 += s2 * wa.x + s3 * wa.y;
        }
        pr0 += __shfl_xor_sync(0xFFFFFFFF, pr0, 1);
        pr0 += __shfl_xor_sync(0xFFFFFFFF, pr0, 2);
        pr1 += __shfl_xor_sync(0xFFFFFFFF, pr1, 1);
        pr1 += __shfl_xor_sync(0xFFFFFFFF, pr1, 2);
        const float att0 = fsigmoid(pr0 + ba0);
        const float att1 = fsigmoid(pr1 + ba0);

        const int node0 = __shfl_sync(0xFFFFFFFF, rld, grp);
        const int node1 = __shfl_sync(0xFFFFFFFF, rld, grp + 8);
        const float attm = isOdd ? att1 : att0;
        float* dst = g_msg + (size_t)(isOdd ? node1 : node0) * DM + jj * 4;
#pragma unroll
        for (int nt = 0; nt < 16; nt++) {
            float s0 = dd[nt][0], s1 = dd[nt][1];
            float s2 = dd[nt][2], s3 = dd[nt][3];
            float q0 = __shfl_xor_sync(0xFFFFFFFF, s0, 1);
            float q1 = __shfl_xor_sync(0xFFFFFFFF, s1, 1);
            float q2 = __shfl_xor_sync(0xFFFFFFFF, s2, 1);
            float q3 = __shfl_xor_sync(0xFFFFFFFF, s3, 1);
            float v0 = isOdd ? q2 : s0;
            float v1 = isOdd ? q3 : s1;
            float v2 = isOdd ? s2 : q0;
            float v3 = isOdd ? s3 : q1;
            red_v4(dst + nt * 8, v0 * attm, v1 * attm, v2 * attm, v3 * attm);
        }
    }
}

// ---------------------------------------------------------------------------
// kernel 3 (HMMA): node post.  x4 nt-pair B fragments in both GEMMs.
// ---------------------------------------------------------------------------
#define PO_A   0
#define PO_W1  67584
#define PO_W2  135168
#define PO_U   169984
#define PO_B1  204800
#define PO_B2  205312
#define PO_TOTAL 205824
#define RS2 528

__global__ void __launch_bounds__(256, 1)
node_post_kernel(const float* __restrict__ h,
                 const float* __restrict__ Wh1,
                 const float* __restrict__ bh1,
                 const float* __restrict__ Wh2,
                 const float* __restrict__ bh2,
                 float* __restrict__ out) {
    extern __shared__ __align__(16) char smraw[];
    float* b1s = (float*)(smraw + PO_B1);
    float* b2s = (float*)(smraw + PO_B2);

    const uint32_t smem_u32 = smem_to_u32(smraw);
    const int tid  = threadIdx.x;
    const int warp = tid >> 5;
    const int lane = tid & 31;

    for (int idx = tid; idx < 128 * 64; idx += 256) {
        int n = idx >> 6, k4 = (idx & 63) * 4;
        float4 v = *(const float4*)&Wh1[(size_t)n * 256 + k4];
        *(uint2*)(smraw + PO_W1 + n * RS2 + k4 * 2) = pack_bf16x4(v);
    }
    for (int idx = tid; idx < 128 * 32; idx += 256) {
        int n = idx >> 5, k4 = (idx & 31) * 4;
        float4 v = *(const float4*)&Wh2[(size_t)n * 128 + k4];
        *(uint2*)(smraw + PO_W2 + n * RS + k4 * 2) = pack_bf16x4(v);
    }
    for (int k = tid; k < 128; k += 256) {
        b1s[k] = bh1[k];
        b2s[k] = bh2[k];
    }
    __syncthreads();

    const int m0 = warp * 16;
    const int arow = m0 + (lane & 7) + ((lane >> 3) & 1) * 8;
    const uint32_t a1_base = smem_u32 + PO_A + (uint32_t)arow * RS2 + ((lane >> 4) & 1) * 16;
    const uint32_t a2_base = smem_u32 + PO_U + (uint32_t)arow * RS  + ((lane >> 4) & 1) * 16;
    // x4 nt-pair B bases
    const uint32_t b14_base = smem_u32 + PO_W1
                            + (uint32_t)((lane & 7) + ((lane >> 4) & 1) * 8) * RS2
                            + ((lane >> 3) & 1) * 16;
    const uint32_t b24_base = smem_u32 + PO_W2
                            + (uint32_t)((lane & 7) + ((lane >> 4) & 1) * 8) * RS
                            + ((lane >> 3) & 1) * 16;

    const int tig = lane & 3, grp = lane >> 2;
    const int ntiles = (NN + 127) / 128;

    for (int tile = blockIdx.x; tile < ntiles; tile += gridDim.x) {
        const int base = tile * 128;
        __syncthreads();
        for (int idx = tid; idx < 128 * 32; idx += 256) {
            int r = idx >> 5, j4 = (idx & 31) * 4;
            int node = base + r;
            float4 vh = (node < NN) ? *(const float4*)&h[(size_t)node * DH + j4]
                                    : make_float4(0.f, 0.f, 0.f, 0.f);
            float4 vm = (node < NN) ? *(const float4*)&g_msg[(size_t)node * DM + j4]
                                    : make_float4(0.f, 0.f, 0.f, 0.f);
            *(uint2*)(smraw + PO_A + r * RS2 + j4 * 2)         = pack_bf16x4(vh);
            *(uint2*)(smraw + PO_A + r * RS2 + 256 + j4 * 2)   = pack_bf16x4(vm);
        }
        __syncthreads();

        float acc[16][4];
#pragma unroll
        for (int nt = 0; nt < 16; nt++)
#pragma unroll
            for (int r = 0; r < 4; r++) acc[nt][r] = 0.f;
#pragma unroll
        for (int k = 0; k < 16; k++) {
            uint32_t a[4];
            ldmatrix_x4(a[0], a[1], a[2], a[3], a1_base + (uint32_t)k * 32);
#pragma unroll
            for (int ntp = 0; ntp < 8; ntp++) {
                uint32_t b4[4];
                ldmatrix_x4(b4[0], b4[1], b4[2], b4[3],
                            b14_base + (uint32_t)ntp * (16 * RS2) + (uint32_t)k * 32);
                mma_bf16(acc[2 * ntp],     a, b4,     acc[2 * ntp]);
                mma_bf16(acc[2 * ntp + 1], a, b4 + 2, acc[2 * ntp + 1]);
            }
        }
#pragma unroll
        for (int nt = 0; nt < 16; nt++) {
            const int c0 = nt * 8 + tig * 2;
            float2 bb = *(float2*)&b1s[c0];
            float v0 = acc[nt][0] + bb.x;
            float v1 = acc[nt][1] + bb.y;
            float v2 = acc[nt][2] + bb.x;
            float v3 = acc[nt][3] + bb.y;
            uint32_t q0 = pack_bf16x2(v0 * fsigmoid(v0), v1 * fsigmoid(v1));
            uint32_t q1 = pack_bf16x2(v2 * fsigmoid(v2), v3 * fsigmoid(v3));
            *(uint32_t*)(smraw + PO_U + (m0 + grp) * RS + c0 * 2)     = q0;
            *(uint32_t*)(smraw + PO_U + (m0 + grp + 8) * RS + c0 * 2) = q1;
        }
        __syncthreads();

#pragma unroll
        for (int nt = 0; nt < 16; nt++)
#pragma unroll
            for (int r = 0; r < 4; r++) acc[nt][r] = 0.f;
#pragma unroll
        for (int k = 0; k < 8; k++) {
            uint32_t a[4];
            ldmatrix_x4(a[0], a[1], a[2], a[3], a2_base + (uint32_t)k * 32);
#pragma unroll
            for (int ntp = 0; ntp < 8; ntp++) {
                uint32_t b4[4];
                ldmatrix_x4(b4[0], b4[1], b4[2], b4[3],
                            b24_base + (uint32_t)ntp * (16 * RS) + (uint32_t)k * 32);
                mma_bf16(acc[2 * ntp],     a, b4,     acc[2 * ntp]);
                mma_bf16(acc[2 * ntp + 1], a, b4 + 2, acc[2 * ntp + 1]);
            }
        }

        const int node0 = base + m0 + grp;
        const int node1 = node0 + 8;
#pragma unroll
        for (int nt = 0; nt < 16; nt++) {
            const int c0 = nt * 8 + tig * 2;
            float2 bb = *(float2*)&b2s[c0];
            if (node0 < NN) {
                float2 hv = *(const float2*)&h[(size_t)node0 * DH + c0];
                *(float2*)&out[(size_t)node0 * DH + c0] =
                    make_float2(hv.x + acc[nt][0] + bb.x, hv.y + acc[nt][1] + bb.y);
            }
            if (node1 < NN) {
                float2 hv = *(const float2*)&h[(size_t)node1 * DH + c0];
                *(float2*)&out[(size_t)node1 * DH + c0] =
                    make_float2(hv.x + acc[nt][2] + bb.x, hv.y + acc[nt][3] + bb.y);
            }
        }
    }
}

// ---------------------------------------------------------------------------
extern "C" void kernel_launch(void* const* d_in, const int* in_sizes, int n_in,
                              void* d_out, int out_size) {
    const float* x   = (const float*)d_in[0];
    const float* h   = (const float*)d_in[1];
    const float* ea  = (const float*)d_in[2];
    const float* We1 = (const float*)d_in[3];
    const float* be1 = (const float*)d_in[4];
    const float* We2 = (const float*)d_in[5];
    const float* be2 = (const float*)d_in[6];
    const float* Wh1 = (const float*)d_in[7];
    const float* bh1 = (const float*)d_in[8];
    const float* Wh2 = (const float*)d_in[9];
    const float* bh2 = (const float*)d_in[10];
    const float* Wa  = (const float*)d_in[11];
    const float* ba  = (const float*)d_in[12];
    const int*   ei  = (const int*)d_in[13];   // int32
    float* out = (float*)d_out;

    cudaFuncSetAttribute(node_pre_kernel,
                         cudaFuncAttributeMaxDynamicSharedMemorySize, NP_TOTAL);
    cudaFuncSetAttribute(edge_kernel,
                         cudaFuncAttributeMaxDynamicSharedMemorySize, EB_TOTAL);
    cudaFuncSetAttribute(node_post_kernel,
                         cudaFuncAttributeMaxDynamicSharedMemorySize, PO_TOTAL);

    node_pre_kernel<<<296, 256, NP_TOTAL>>>(h, We1);   // also zeroes g_msg
    edge_kernel<<<296, 256, EB_TOTAL>>>(x, ea, We1, be1, We2, be2, Wa, ba, ei);
    node_post_kernel<<<148, 256, PO_TOTAL>>>(h, Wh1, bh1, Wh2, bh2, out);
}

// round 13
// speedup vs baseline: 3.4336x; 1.5410x over previous
#include <cuda_runtime.h>
#include <cuda_bf16.h>
#include <math.h>
#include <stdint.h>

// ----------------------------------------------------------------------------
// IGNN / EGNN layer, GB300 (sm_103a built as sm_103 -> mma.sync, no tcgen05).
// Round 13: sigmoid via tanh.approx.f32 (1 MUFU instead of 2 -> halves the
// largest issue-side term in the edge kernel), W1E b-fragments via x4 pairs.
// Structure otherwise identical to R12.
// ----------------------------------------------------------------------------

#define NN 50000
#define NE 800000
#define DH 128
#define DE 16
#define DM 128

__device__ __align__(16) float g_Ha[(size_t)NN * DM];
__device__ __align__(16) float g_Hb[(size_t)NN * DM];
__device__ __align__(16) float g_msg[(size_t)NN * DM];

// sigmoid(x) = 0.5*tanh(x/2) + 0.5   (tanh.approx.f32: single MUFU-class op)
__device__ __forceinline__ float fsigmoid(float v) {
    float t;
    asm("tanh.approx.f32 %0, %1;" : "=f"(t) : "f"(v * 0.5f));
    return fmaf(0.5f, t, 0.5f);
}

__device__ __forceinline__ uint32_t smem_to_u32(const void* smem_ptr) {
    uint32_t addr;
    asm("{ .reg .u64 tmp; cvta.to.shared.u64 tmp, %1; cvt.u32.u64 %0, tmp; }"
        : "=r"(addr) : "l"(smem_ptr));
    return addr;
}

__device__ __forceinline__ void ldmatrix_x4(uint32_t& r0, uint32_t& r1,
                                            uint32_t& r2, uint32_t& r3, uint32_t addr) {
    asm volatile("ldmatrix.sync.aligned.m8n8.x4.shared.b16 {%0,%1,%2,%3}, [%4];"
                 : "=r"(r0), "=r"(r1), "=r"(r2), "=r"(r3) : "r"(addr));
}
__device__ __forceinline__ void ldmatrix_x2(uint32_t& r0, uint32_t& r1, uint32_t addr) {
    asm volatile("ldmatrix.sync.aligned.m8n8.x2.shared.b16 {%0,%1}, [%2];"
                 : "=r"(r0), "=r"(r1) : "r"(addr));
}
__device__ __forceinline__ void mma_bf16(float d[4], const uint32_t a[4],
                                         const uint32_t b[2], const float c[4]) {
    asm volatile(
        "mma.sync.aligned.m16n8k16.row.col.f32.bf16.bf16.f32 "
        "{%0,%1,%2,%3}, {%4,%5,%6,%7}, {%8,%9}, {%10,%11,%12,%13};"
        : "=f"(d[0]), "=f"(d[1]), "=f"(d[2]), "=f"(d[3])
        : "r"(a[0]), "r"(a[1]), "r"(a[2]), "r"(a[3]),
          "r"(b[0]), "r"(b[1]),
          "f"(c[0]), "f"(c[1]), "f"(c[2]), "f"(c[3]));
}
__device__ __forceinline__ void red_v4(float* addr, float v0, float v1, float v2, float v3) {
    asm volatile("red.global.add.v4.f32 [%0], {%1, %2, %3, %4};"
                 :: "l"(addr), "f"(v0), "f"(v1), "f"(v2), "f"(v3) : "memory");
}

__device__ __forceinline__ uint2 pack_bf16x4(float4 v) {
    __nv_bfloat162 lo = __floats2bfloat162_rn(v.x, v.y);
    __nv_bfloat162 hi = __floats2bfloat162_rn(v.z, v.w);
    uint2 r;
    r.x = *(uint32_t*)&lo;
    r.y = *(uint32_t*)&hi;
    return r;
}
__device__ __forceinline__ uint32_t pack_bf16x2(float a, float b) {
    __nv_bfloat162 p = __floats2bfloat162_rn(a, b);
    return *(uint32_t*)&p;
}
__device__ __forceinline__ float2 unpack_bf16x2(uint32_t w) {
    __nv_bfloat162 p = *(__nv_bfloat162*)&w;
    return make_float2(__bfloat162float(p.x), __bfloat162float(p.y));
}

// ---------------------------------------------------------------------------
// kernel 1 (HMMA): Ha = h @ W1a^T, Hb = h @ W1b^T + g_msg zeroing.
// (unchanged from R12)
// ---------------------------------------------------------------------------
#define NP_A   0
#define NP_WA  34816
#define NP_WB  69632
#define NP_TOTAL 104448
#define RS 272

__global__ void __launch_bounds__(256, 2)
node_pre_kernel(const float* __restrict__ h, const float* __restrict__ We1) {
    extern __shared__ __align__(16) char smraw[];
    const uint32_t smem_u32 = smem_to_u32(smraw);
    const int tid  = threadIdx.x;
    const int warp = tid >> 5;
    const int lane = tid & 31;

    for (int idx = tid; idx < 128 * 128; idx += 256) {
        int n = idx >> 7, k = idx & 127;
        *(__nv_bfloat16*)(smraw + NP_WA + n * RS + k * 2) =
            __float2bfloat16(We1[n * 273 + k]);
        *(__nv_bfloat16*)(smraw + NP_WB + n * RS + k * 2) =
            __float2bfloat16(We1[n * 273 + 128 + k]);
    }
    __syncthreads();

    const int m0 = warp * 16;
    const int arow = m0 + (lane & 7) + ((lane >> 3) & 1) * 8;
    const uint32_t a_base  = smem_u32 + NP_A + (uint32_t)arow * RS + ((lane >> 4) & 1) * 16;
    const uint32_t ba4_base = smem_u32 + NP_WA
                            + (uint32_t)((lane & 7) + ((lane >> 4) & 1) * 8) * RS
                            + ((lane >> 3) & 1) * 16;
    const uint32_t bb4_base = ba4_base + (NP_WB - NP_WA);

    const int tig = lane & 3, grp = lane >> 2;
    const int ntiles = (NN + 127) / 128;

    for (int tile = blockIdx.x; tile < ntiles; tile += gridDim.x) {
        const int base = tile * 128;
        __syncthreads();
        for (int idx = tid; idx < 128 * 32; idx += 256) {
            int r = idx >> 5, j4 = (idx & 31) * 4;
            int node = base + r;
            float4 v = make_float4(0.f, 0.f, 0.f, 0.f);
            if (node < NN) {
                v = *(const float4*)&h[(size_t)node * DH + j4];
                *(float4*)&g_msg[(size_t)node * DM + j4] = make_float4(0.f, 0.f, 0.f, 0.f);
            }
            *(uint2*)(smraw + NP_A + r * RS + j4 * 2) = pack_bf16x4(v);
        }
        __syncthreads();

        const int node0 = base + m0 + grp;
        const int node1 = node0 + 8;

        uint32_t afr[8][4];
#pragma unroll
        for (int k = 0; k < 8; k++)
            ldmatrix_x4(afr[k][0], afr[k][1], afr[k][2], afr[k][3],
                        a_base + (uint32_t)k * 32);

        float acc[16][4];

#pragma unroll
        for (int nt = 0; nt < 16; nt++)
#pragma unroll
            for (int r = 0; r < 4; r++) acc[nt][r] = 0.f;
#pragma unroll
        for (int k = 0; k < 8; k++) {
#pragma unroll
            for (int ntp = 0; ntp < 8; ntp++) {
                uint32_t b4[4];
                ldmatrix_x4(b4[0], b4[1], b4[2], b4[3],
                            ba4_base + (uint32_t)ntp * (16 * RS) + (uint32_t)k * 32);
                mma_bf16(acc[2 * ntp],     afr[k], b4,     acc[2 * ntp]);
                mma_bf16(acc[2 * ntp + 1], afr[k], b4 + 2, acc[2 * ntp + 1]);
            }
        }
#pragma unroll
        for (int nt = 0; nt < 16; nt++) {
            const int c0 = nt * 8 + tig * 2;
            if (node0 < NN) *(float2*)&g_Ha[(size_t)node0 * DM + c0] =
                make_float2(acc[nt][0], acc[nt][1]);
            if (node1 < NN) *(float2*)&g_Ha[(size_t)node1 * DM + c0] =
                make_float2(acc[nt][2], acc[nt][3]);
        }

#pragma unroll
        for (int nt = 0; nt < 16; nt++)
#pragma unroll
            for (int r = 0; r < 4; r++) acc[nt][r] = 0.f;
#pragma unroll
        for (int k = 0; k < 8; k++) {
#pragma unroll
            for (int ntp = 0; ntp < 8; ntp++) {
                uint32_t b4[4];
                ldmatrix_x4(b4[0], b4[1], b4[2], b4[3],
                            bb4_base + (uint32_t)ntp * (16 * RS) + (uint32_t)k * 32);
                mma_bf16(acc[2 * ntp],     afr[k], b4,     acc[2 * ntp]);
                mma_bf16(acc[2 * ntp + 1], afr[k], b4 + 2, acc[2 * ntp + 1]);
            }
        }
#pragma unroll
        for (int nt = 0; nt < 16; nt++) {
            const int c0 = nt * 8 + tig * 2;
            if (node0 < NN) *(float2*)&g_Hb[(size_t)node0 * DM + c0] =
                make_float2(acc[nt][0], acc[nt][1]);
            if (node1 < NN) *(float2*)&g_Hb[(size_t)node1 * DM + c0] =
                make_float2(acc[nt][2], acc[nt][3]);
        }
    }
}

// ---------------------------------------------------------------------------
// kernel 2: edge kernel — warp-autonomous, coalesced gather, full-HMMA.
// W1E b-fragments now via x4 nt-pairs. Sigmoid via tanh.
// ---------------------------------------------------------------------------
#define EB_C     0
#define EB_EA    34816
#define EB_W2    38912
#define EB_W1E   73728
#define EB_WR    77824
#define EB_BE1   78336
#define EB_BE2   78848
#define EB_WAS   79360
#define EB_TOTAL 79872

#define CSTRIDE 272
#define WARP_C_BYTES (16 * CSTRIDE)
#define WARP_EA_BYTES 512

__global__ void __launch_bounds__(256, 2)
edge_kernel(const float* __restrict__ x,
            const float* __restrict__ edge_attr,
            const float* __restrict__ We1,
            const float* __restrict__ be1,
            const float* __restrict__ We2,
            const float* __restrict__ be2,
            const float* __restrict__ Wa,
            const float* __restrict__ ba,
            const int* __restrict__ ei) {
    extern __shared__ __align__(16) char smraw[];
    float* Wr   = (float*)(smraw + EB_WR);
    float* be1s = (float*)(smraw + EB_BE1);
    float* be2s = (float*)(smraw + EB_BE2);
    float* Was  = (float*)(smraw + EB_WAS);

    const uint32_t smem_u32 = smem_to_u32(smraw);
    const int tid  = threadIdx.x;
    const int warp = tid >> 5;
    const int lane = tid & 31;

    for (int idx = tid; idx < 128 * 128; idx += 256) {
        int n = idx >> 7, k = idx & 127;
        *(__nv_bfloat16*)(smraw + EB_W2 + n * CSTRIDE + k * 2) =
            __float2bfloat16(We2[n * 128 + k]);
    }
    for (int idx = tid; idx < 128 * 16; idx += 256) {
        int n = idx >> 4, t = idx & 15;
        *(__nv_bfloat16*)(smraw + EB_W1E + n * 32 + t * 2) =
            __float2bfloat16(We1[n * 273 + 257 + t]);
    }
    for (int k = tid; k < 128; k += 256) {
        Wr[k]   = We1[k * 273 + 256];
        be1s[k] = be1[k];
        be2s[k] = be2[k];
        Was[k]  = Wa[k];
    }
    const float ba0 = ba[0];
    __syncthreads();

    const uint32_t c_region  = smem_u32 + EB_C  + (uint32_t)warp * WARP_C_BYTES;
    const uint32_t ea_region = smem_u32 + EB_EA + (uint32_t)warp * WARP_EA_BYTES;

    const int tig = lane & 3, grp = lane >> 2;
    const uint32_t c_fr0 = c_region + (uint32_t)grp * CSTRIDE + (uint32_t)tig * 4;
    const uint32_t c_fr1 = c_fr0 + 8 * CSTRIDE;
    const uint32_t ea_lm = ea_region + (uint32_t)(lane & 15) * 32 + ((lane >> 4) & 1) * 16;
    // W1E x4 nt-pair base (stride 32B, k-offset {0,16})
    const uint32_t w1e4_base = smem_u32 + EB_W1E
                             + (uint32_t)((lane & 7) + ((lane >> 4) & 1) * 8) * 32
                             + ((lane >> 3) & 1) * 16;
    const uint32_t b4_base = smem_u32 + EB_W2
                           + (uint32_t)((lane & 7) + ((lane >> 4) & 1) * 8) * CSTRIDE
                           + ((lane >> 3) & 1) * 16;

    const int jj = tig >> 1;
    const bool isOdd = (tig & 1) != 0;

    const int NWT = NE / 16;
    const int wstride = gridDim.x * 8;

    const float4 wr4  = *(const float4*)(Wr + lane * 4);
    const float4 be14 = *(const float4*)(be1s + lane * 4);

    for (int wt = blockIdx.x * 8 + warp; wt < NWT; wt += wstride) {
        const int base = wt * 16;

        int rld = 0, cld = 0;
        float radld = 0.f;
        if (lane < 16) {
            rld = ei[base + lane];
            cld = ei[NE + base + lane];
            float dx = x[(size_t)rld * 3 + 0] - x[(size_t)cld * 3 + 0];
            float dy = x[(size_t)rld * 3 + 1] - x[(size_t)cld * 3 + 1];
            float dz = x[(size_t)rld * 3 + 2] - x[(size_t)cld * 3 + 2];
            radld = sqrtf(dx * dx + dy * dy + dz * dz);
        }

#pragma unroll
        for (int e = 0; e < 16; e++) {
            const int   row  = __shfl_sync(0xFFFFFFFF, rld, e);
            const int   colN = __shfl_sync(0xFFFFFFFF, cld, e);
            const float rv   = __shfl_sync(0xFFFFFFFF, radld, e);
            float4 ha = *(const float4*)&g_Ha[(size_t)row  * DM + lane * 4];
            float4 hb = *(const float4*)&g_Hb[(size_t)colN * DM + lane * 4];
            float4 c;
            c.x = ha.x + hb.x + be14.x + rv * wr4.x;
            c.y = ha.y + hb.y + be14.y + rv * wr4.y;
            c.z = ha.z + hb.z + be14.z + rv * wr4.z;
            c.w = ha.w + hb.w + be14.w + rv * wr4.w;
            *(uint2*)(smraw + (c_region - smem_u32) + e * CSTRIDE + lane * 8) = pack_bf16x4(c);
        }

        {
            int e = lane >> 1, hf2 = lane & 1;
            const float4* pe = (const float4*)(edge_attr + (size_t)(base + e) * DE + hf2 * 8);
            float4 u0 = pe[0], u1 = pe[1];
            uint2 w0 = pack_bf16x4(u0), w1 = pack_bf16x4(u1);
            *(uint4*)(smraw + (ea_region - smem_u32) + e * 32 + hf2 * 16) =
                make_uint4(w0.x, w0.y, w1.x, w1.y);
        }
        __syncwarp();

        float dacc[16][4];
#pragma unroll
        for (int nt = 0; nt < 16; nt++) {
            uint32_t lo = *(const uint32_t*)(smraw + (c_fr0 - smem_u32) + nt * 16);
            uint32_t hi = *(const uint32_t*)(smraw + (c_fr1 - smem_u32) + nt * 16);
            float2 f0 = unpack_bf16x2(lo);
            float2 f1 = unpack_bf16x2(hi);
            dacc[nt][0] = f0.x; dacc[nt][1] = f0.y;
            dacc[nt][2] = f1.x; dacc[nt][3] = f1.y;
        }
        {
            uint32_t aea[4];
            ldmatrix_x4(aea[0], aea[1], aea[2], aea[3], ea_lm);
#pragma unroll
            for (int ntp = 0; ntp < 8; ntp++) {
                uint32_t b4[4];
                ldmatrix_x4(b4[0], b4[1], b4[2], b4[3],
                            w1e4_base + (uint32_t)ntp * 512);
                mma_bf16(dacc[2 * ntp],     aea, b4,     dacc[2 * ntp]);
                mma_bf16(dacc[2 * ntp + 1], aea, b4 + 2, dacc[2 * ntp + 1]);
            }
        }
        __syncwarp();

        uint32_t au[8][4];
#pragma unroll
        for (int kk = 0; kk < 8; kk++) {
            float* d0 = dacc[2 * kk];
            float* d1 = dacc[2 * kk + 1];
            float s00 = d0[0] * fsigmoid(d0[0]);
            float s01 = d0[1] * fsigmoid(d0[1]);
            float s02 = d0[2] * fsigmoid(d0[2]);
            float s03 = d0[3] * fsigmoid(d0[3]);
            float s10 = d1[0] * fsigmoid(d1[0]);
            float s11 = d1[1] * fsigmoid(d1[1]);
            float s12 = d1[2] * fsigmoid(d1[2]);
            float s13 = d1[3] * fsigmoid(d1[3]);
            au[kk][0] = pack_bf16x2(s00, s01);
            au[kk][1] = pack_bf16x2(s02, s03);
            au[kk][2] = pack_bf16x2(s10, s11);
            au[kk][3] = pack_bf16x2(s12, s13);
        }

        float dd[16][4];
#pragma unroll
        for (int nt = 0; nt < 16; nt++)
#pragma unroll
            for (int r = 0; r < 4; r++) dd[nt][r] = 0.f;

#pragma unroll
        for (int kk = 0; kk < 8; kk++) {
#pragma unroll
            for (int ntp = 0; ntp < 8; ntp++) {
                uint32_t b4[4];
                ldmatrix_x4(b4[0], b4[1], b4[2], b4[3],
                            b4_base + (uint32_t)ntp * (16 * CSTRIDE) + (uint32_t)kk * 32);
                mma_bf16(dd[2 * ntp],     au[kk], b4,     dd[2 * ntp]);
                mma_bf16(dd[2 * ntp + 1], au[kk], b4 + 2, dd[2 * ntp + 1]);
            }
        }

        float pr0 = 0.f, pr1 = 0.f;
#pragma unroll
        for (int nt = 0; nt < 16; nt++) {
            const int c0 = nt * 8 + tig * 2;
            float2 bb = *(float2*)&be2s[c0];
            float2 wa = *(float2*)&Was[c0];
            float v0 = dd[nt][0] + bb.x;
            float v1 = dd[nt][1] + bb.y;
            float v2 = dd[nt][2] + bb.x;
            float v3 = dd[nt][3] + bb.y;
            float s0 = v0 * fsigmoid(v0);
            float s1 = v1 * fsigmoid(v1);
            float s2 = v2 * fsigmoid(v2);
            float s3 = v3 * fsigmoid(v3);
            dd[nt][0] = s0; dd[nt][1] = s1; dd[nt][2] = s2; dd[nt][3] = s3;
            pr0 += s0 * wa.x + s1 * wa.y;
            pr1 += s2 * wa.x + s3 * wa.y;
        }
        pr0 += __shfl_xor_sync(0xFFFFFFFF, pr0, 1);
        pr0 += __shfl_xor_sync(0xFFFFFFFF, pr0, 2);
        pr1 += __shfl_xor_sync(0xFFFFFFFF, pr1, 1);
        pr1 += __shfl_xor_sync(0xFFFFFFFF, pr1, 2);
        const float att0 = fsigmoid(pr0 + ba0);
        const float att1 = fsigmoid(pr1 + ba0);

        const int node0 = __shfl_sync(0xFFFFFFFF, rld, grp);
        const int node1 = __shfl_sync(0xFFFFFFFF, rld, grp + 8);
        const float attm = isOdd ? att1 : att0;
        float* dst = g_msg + (size_t)(isOdd ? node1 : node0) * DM + jj * 4;
#pragma unroll
        for (int nt = 0; nt < 16; nt++) {
            float s0 = dd[nt][0], s1 = dd[nt][1];
            float s2 = dd[nt][2], s3 = dd[nt][3];
            float q0 = __shfl_xor_sync(0xFFFFFFFF, s0, 1);
            float q1 = __shfl_xor_sync(0xFFFFFFFF, s1, 1);
            float q2 = __shfl_xor_sync(0xFFFFFFFF, s2, 1);
            float q3 = __shfl_xor_sync(0xFFFFFFFF, s3, 1);
            float v0 = isOdd ? q2 : s0;
            float v1 = isOdd ? q3 : s1;
            float v2 = isOdd ? s2 : q0;
            float v3 = isOdd ? s3 : q1;
            red_v4(dst + nt * 8, v0 * attm, v1 * attm, v2 * attm, v3 * attm);
        }
    }
}

// ---------------------------------------------------------------------------
// kernel 3 (HMMA): node post.  (structure unchanged from R12; tanh sigmoid)
// ---------------------------------------------------------------------------
#define PO_A   0
#define PO_W1  67584
#define PO_W2  135168
#define PO_U   169984
#define PO_B1  204800
#define PO_B2  205312
#define PO_TOTAL 205824
#define RS2 528

__global__ void __launch_bounds__(256, 1)
node_post_kernel(const float* __restrict__ h,
                 const float* __restrict__ Wh1,
                 const float* __restrict__ bh1,
                 const float* __restrict__ Wh2,
                 const float* __restrict__ bh2,
                 float* __restrict__ out) {
    extern __shared__ __align__(16) char smraw[];
    float* b1s = (float*)(smraw + PO_B1);
    float* b2s = (float*)(smraw + PO_B2);

    const uint32_t smem_u32 = smem_to_u32(smraw);
    const int tid  = threadIdx.x;
    const int warp = tid >> 5;
    const int lane = tid & 31;

    for (int idx = tid; idx < 128 * 64; idx += 256) {
        int n = idx >> 6, k4 = (idx & 63) * 4;
        float4 v = *(const float4*)&Wh1[(size_t)n * 256 + k4];
        *(uint2*)(smraw + PO_W1 + n * RS2 + k4 * 2) = pack_bf16x4(v);
    }
    for (int idx = tid; idx < 128 * 32; idx += 256) {
        int n = idx >> 5, k4 = (idx & 31) * 4;
        float4 v = *(const float4*)&Wh2[(size_t)n * 128 + k4];
        *(uint2*)(smraw + PO_W2 + n * RS + k4 * 2) = pack_bf16x4(v);
    }
    for (int k = tid; k < 128; k += 256) {
        b1s[k] = bh1[k];
        b2s[k] = bh2[k];
    }
    __syncthreads();

    const int m0 = warp * 16;
    const int arow = m0 + (lane & 7) + ((lane >> 3) & 1) * 8;
    const uint32_t a1_base = smem_u32 + PO_A + (uint32_t)arow * RS2 + ((lane >> 4) & 1) * 16;
    const uint32_t a2_base = smem_u32 + PO_U + (uint32_t)arow * RS  + ((lane >> 4) & 1) * 16;
    const uint32_t b14_base = smem_u32 + PO_W1
                            + (uint32_t)((lane & 7) + ((lane >> 4) & 1) * 8) * RS2
                            + ((lane >> 3) & 1) * 16;
    const uint32_t b24_base = smem_u32 + PO_W2
                            + (uint32_t)((lane & 7) + ((lane >> 4) & 1) * 8) * RS
                            + ((lane >> 3) & 1) * 16;

    const int tig = lane & 3, grp = lane >> 2;
    const int ntiles = (NN + 127) / 128;

    for (int tile = blockIdx.x; tile < ntiles; tile += gridDim.x) {
        const int base = tile * 128;
        __syncthreads();
        for (int idx = tid; idx < 128 * 32; idx += 256) {
            int r = idx >> 5, j4 = (idx & 31) * 4;
            int node = base + r;
            float4 vh = (node < NN) ? *(const float4*)&h[(size_t)node * DH + j4]
                                    : make_float4(0.f, 0.f, 0.f, 0.f);
            float4 vm = (node < NN) ? *(const float4*)&g_msg[(size_t)node * DM + j4]
                                    : make_float4(0.f, 0.f, 0.f, 0.f);
            *(uint2*)(smraw + PO_A + r * RS2 + j4 * 2)         = pack_bf16x4(vh);
            *(uint2*)(smraw + PO_A + r * RS2 + 256 + j4 * 2)   = pack_bf16x4(vm);
        }
        __syncthreads();

        float acc[16][4];
#pragma unroll
        for (int nt = 0; nt < 16; nt++)
#pragma unroll
            for (int r = 0; r < 4; r++) acc[nt][r] = 0.f;
#pragma unroll
        for (int k = 0; k < 16; k++) {
            uint32_t a[4];
            ldmatrix_x4(a[0], a[1], a[2], a[3], a1_base + (uint32_t)k * 32);
#pragma unroll
            for (int ntp = 0; ntp < 8; ntp++) {
                uint32_t b4[4];
                ldmatrix_x4(b4[0], b4[1], b4[2], b4[3],
                            b14_base + (uint32_t)ntp * (16 * RS2) + (uint32_t)k * 32);
                mma_bf16(acc[2 * ntp],     a, b4,     acc[2 * ntp]);
                mma_bf16(acc[2 * ntp + 1], a, b4 + 2, acc[2 * ntp + 1]);
            }
        }
#pragma unroll
        for (int nt = 0; nt < 16; nt++) {
            const int c0 = nt * 8 + tig * 2;
            float2 bb = *(float2*)&b1s[c0];
            float v0 = acc[nt][0] + bb.x;
            float v1 = acc[nt][1] + bb.y;
            float v2 = acc[nt][2] + bb.x;
            float v3 = acc[nt][3] + bb.y;
            uint32_t q0 = pack_bf16x2(v0 * fsigmoid(v0), v1 * fsigmoid(v1));
            uint32_t q1 = pack_bf16x2(v2 * fsigmoid(v2), v3 * fsigmoid(v3));
            *(uint32_t*)(smraw + PO_U + (m0 + grp) * RS + c0 * 2)     = q0;
            *(uint32_t*)(smraw + PO_U + (m0 + grp + 8) * RS + c0 * 2) = q1;
        }
        __syncthreads();

#pragma unroll
        for (int nt = 0; nt < 16; nt++)
#pragma unroll
            for (int r = 0; r < 4; r++) acc[nt][r] = 0.f;
#pragma unroll
        for (int k = 0; k < 8; k++) {
            uint32_t a[4];
            ldmatrix_x4(a[0], a[1], a[2], a[3], a2_base + (uint32_t)k * 32);
#pragma unroll
            for (int ntp = 0; ntp < 8; ntp++) {
                uint32_t b4[4];
                ldmatrix_x4(b4[0], b4[1], b4[2], b4[3],
                            b24_base + (uint32_t)ntp * (16 * RS) + (uint32_t)k * 32);
                mma_bf16(acc[2 * ntp],     a, b4,     acc[2 * ntp]);
                mma_bf16(acc[2 * ntp + 1], a, b4 + 2, acc[2 * ntp + 1]);
            }
        }

        const int node0 = base + m0 + grp;
        const int node1 = node0 + 8;
#pragma unroll
        for (int nt = 0; nt < 16; nt++) {
            const int c0 = nt * 8 + tig * 2;
            float2 bb = *(float2*)&b2s[c0];
            if (node0 < NN) {
                float2 hv = *(const float2*)&h[(size_t)node0 * DH + c0];
                *(float2*)&out[(size_t)node0 * DH + c0] =
                    make_float2(hv.x + acc[nt][0] + bb.x, hv.y + acc[nt][1] + bb.y);
            }
            if (node1 < NN) {
                float2 hv = *(const float2*)&h[(size_t)node1 * DH + c0];
                *(float2*)&out[(size_t)node1 * DH + c0] =
                    make_float2(hv.x + acc[nt][2] + bb.x, hv.y + acc[nt][3] + bb.y);
            }
        }
    }
}

// ---------------------------------------------------------------------------
extern "C" void kernel_launch(void* const* d_in, const int* in_sizes, int n_in,
                              void* d_out, int out_size) {
    const float* x   = (const float*)d_in[0];
    const float* h   = (const float*)d_in[1];
    const float* ea  = (const float*)d_in[2];
    const float* We1 = (const float*)d_in[3];
    const float* be1 = (const float*)d_in[4];
    const float* We2 = (const float*)d_in[5];
    const float* be2 = (const float*)d_in[6];
    const float* Wh1 = (const float*)d_in[7];
    const float* bh1 = (const float*)d_in[8];
    const float* Wh2 = (const float*)d_in[9];
    const float* bh2 = (const float*)d_in[10];
    const float* Wa  = (const float*)d_in[11];
    const float* ba  = (const float*)d_in[12];
    const int*   ei  = (const int*)d_in[13];   // int32
    float* out = (float*)d_out;

    cudaFuncSetAttribute(node_pre_kernel,
                         cudaFuncAttributeMaxDynamicSharedMemorySize, NP_TOTAL);
    cudaFuncSetAttribute(edge_kernel,
                         cudaFuncAttributeMaxDynamicSharedMemorySize, EB_TOTAL);
    cudaFuncSetAttribute(node_post_kernel,
                         cudaFuncAttributeMaxDynamicSharedMemorySize, PO_TOTAL);

    node_pre_kernel<<<296, 256, NP_TOTAL>>>(h, We1);   // also zeroes g_msg
    edge_kernel<<<296, 256, EB_TOTAL>>>(x, ea, We1, be1, We2, be2, Wa, ba, ei);
    node_post_kernel<<<148, 256, PO_TOTAL>>>(h, Wh1, bh1, Wh2, bh2, out);
}

// round 14
// speedup vs baseline: 3.4773x; 1.0127x over previous
#include <cuda_runtime.h>
#include <cuda_bf16.h>
#include <math.h>
#include <stdint.h>

// ----------------------------------------------------------------------------
// IGNN / EGNN layer, GB300 (sm_103a built as sm_103 -> mma.sync, no tcgen05).
// Round 14: node_post widened to 512 threads (16 warps, warp-pairs split the
// nt range) to double issue parallelism on its latency-bound chain.
// node_pre and edge kernel unchanged from R13.
// ----------------------------------------------------------------------------

#define NN 50000
#define NE 800000
#define DH 128
#define DE 16
#define DM 128

__device__ __align__(16) float g_Ha[(size_t)NN * DM];
__device__ __align__(16) float g_Hb[(size_t)NN * DM];
__device__ __align__(16) float g_msg[(size_t)NN * DM];

// sigmoid(x) = 0.5*tanh(x/2) + 0.5   (tanh.approx.f32: single MUFU-class op)
__device__ __forceinline__ float fsigmoid(float v) {
    float t;
    asm("tanh.approx.f32 %0, %1;" : "=f"(t) : "f"(v * 0.5f));
    return fmaf(0.5f, t, 0.5f);
}

__device__ __forceinline__ uint32_t smem_to_u32(const void* smem_ptr) {
    uint32_t addr;
    asm("{ .reg .u64 tmp; cvta.to.shared.u64 tmp, %1; cvt.u32.u64 %0, tmp; }"
        : "=r"(addr) : "l"(smem_ptr));
    return addr;
}

__device__ __forceinline__ void ldmatrix_x4(uint32_t& r0, uint32_t& r1,
                                            uint32_t& r2, uint32_t& r3, uint32_t addr) {
    asm volatile("ldmatrix.sync.aligned.m8n8.x4.shared.b16 {%0,%1,%2,%3}, [%4];"
                 : "=r"(r0), "=r"(r1), "=r"(r2), "=r"(r3) : "r"(addr));
}
__device__ __forceinline__ void ldmatrix_x2(uint32_t& r0, uint32_t& r1, uint32_t addr) {
    asm volatile("ldmatrix.sync.aligned.m8n8.x2.shared.b16 {%0,%1}, [%2];"
                 : "=r"(r0), "=r"(r1) : "r"(addr));
}
__device__ __forceinline__ void mma_bf16(float d[4], const uint32_t a[4],
                                         const uint32_t b[2], const float c[4]) {
    asm volatile(
        "mma.sync.aligned.m16n8k16.row.col.f32.bf16.bf16.f32 "
        "{%0,%1,%2,%3}, {%4,%5,%6,%7}, {%8,%9}, {%10,%11,%12,%13};"
        : "=f"(d[0]), "=f"(d[1]), "=f"(d[2]), "=f"(d[3])
        : "r"(a[0]), "r"(a[1]), "r"(a[2]), "r"(a[3]),
          "r"(b[0]), "r"(b[1]),
          "f"(c[0]), "f"(c[1]), "f"(c[2]), "f"(c[3]));
}
__device__ __forceinline__ void red_v4(float* addr, float v0, float v1, float v2, float v3) {
    asm volatile("red.global.add.v4.f32 [%0], {%1, %2, %3, %4};"
                 :: "l"(addr), "f"(v0), "f"(v1), "f"(v2), "f"(v3) : "memory");
}

__device__ __forceinline__ uint2 pack_bf16x4(float4 v) {
    __nv_bfloat162 lo = __floats2bfloat162_rn(v.x, v.y);
    __nv_bfloat162 hi = __floats2bfloat162_rn(v.z, v.w);
    uint2 r;
    r.x = *(uint32_t*)&lo;
    r.y = *(uint32_t*)&hi;
    return r;
}
__device__ __forceinline__ uint32_t pack_bf16x2(float a, float b) {
    __nv_bfloat162 p = __floats2bfloat162_rn(a, b);
    return *(uint32_t*)&p;
}
__device__ __forceinline__ float2 unpack_bf16x2(uint32_t w) {
    __nv_bfloat162 p = *(__nv_bfloat162*)&w;
    return make_float2(__bfloat162float(p.x), __bfloat162float(p.y));
}

// ---------------------------------------------------------------------------
// kernel 1 (HMMA): Ha = h @ W1a^T, Hb = h @ W1b^T + g_msg zeroing.
// (unchanged from R13)
// ---------------------------------------------------------------------------
#define NP_A   0
#define NP_WA  34816
#define NP_WB  69632
#define NP_TOTAL 104448
#define RS 272

__global__ void __launch_bounds__(256, 2)
node_pre_kernel(const float* __restrict__ h, const float* __restrict__ We1) {
    extern __shared__ __align__(16) char smraw[];
    const uint32_t smem_u32 = smem_to_u32(smraw);
    const int tid  = threadIdx.x;
    const int warp = tid >> 5;
    const int lane = tid & 31;

    for (int idx = tid; idx < 128 * 128; idx += 256) {
        int n = idx >> 7, k = idx & 127;
        *(__nv_bfloat16*)(smraw + NP_WA + n * RS + k * 2) =
            __float2bfloat16(We1[n * 273 + k]);
        *(__nv_bfloat16*)(smraw + NP_WB + n * RS + k * 2) =
            __float2bfloat16(We1[n * 273 + 128 + k]);
    }
    __syncthreads();

    const int m0 = warp * 16;
    const int arow = m0 + (lane & 7) + ((lane >> 3) & 1) * 8;
    const uint32_t a_base  = smem_u32 + NP_A + (uint32_t)arow * RS + ((lane >> 4) & 1) * 16;
    const uint32_t ba4_base = smem_u32 + NP_WA
                            + (uint32_t)((lane & 7) + ((lane >> 4) & 1) * 8) * RS
                            + ((lane >> 3) & 1) * 16;
    const uint32_t bb4_base = ba4_base + (NP_WB - NP_WA);

    const int tig = lane & 3, grp = lane >> 2;
    const int ntiles = (NN + 127) / 128;

    for (int tile = blockIdx.x; tile < ntiles; tile += gridDim.x) {
        const int base = tile * 128;
        __syncthreads();
        for (int idx = tid; idx < 128 * 32; idx += 256) {
            int r = idx >> 5, j4 = (idx & 31) * 4;
            int node = base + r;
            float4 v = make_float4(0.f, 0.f, 0.f, 0.f);
            if (node < NN) {
                v = *(const float4*)&h[(size_t)node * DH + j4];
                *(float4*)&g_msg[(size_t)node * DM + j4] = make_float4(0.f, 0.f, 0.f, 0.f);
            }
            *(uint2*)(smraw + NP_A + r * RS + j4 * 2) = pack_bf16x4(v);
        }
        __syncthreads();

        const int node0 = base + m0 + grp;
        const int node1 = node0 + 8;

        uint32_t afr[8][4];
#pragma unroll
        for (int k = 0; k < 8; k++)
            ldmatrix_x4(afr[k][0], afr[k][1], afr[k][2], afr[k][3],
                        a_base + (uint32_t)k * 32);

        float acc[16][4];

#pragma unroll
        for (int nt = 0; nt < 16; nt++)
#pragma unroll
            for (int r = 0; r < 4; r++) acc[nt][r] = 0.f;
#pragma unroll
        for (int k = 0; k < 8; k++) {
#pragma unroll
            for (int ntp = 0; ntp < 8; ntp++) {
                uint32_t b4[4];
                ldmatrix_x4(b4[0], b4[1], b4[2], b4[3],
                            ba4_base + (uint32_t)ntp * (16 * RS) + (uint32_t)k * 32);
                mma_bf16(acc[2 * ntp],     afr[k], b4,     acc[2 * ntp]);
                mma_bf16(acc[2 * ntp + 1], afr[k], b4 + 2, acc[2 * ntp + 1]);
            }
        }
#pragma unroll
        for (int nt = 0; nt < 16; nt++) {
            const int c0 = nt * 8 + tig * 2;
            if (node0 < NN) *(float2*)&g_Ha[(size_t)node0 * DM + c0] =
                make_float2(acc[nt][0], acc[nt][1]);
            if (node1 < NN) *(float2*)&g_Ha[(size_t)node1 * DM + c0] =
                make_float2(acc[nt][2], acc[nt][3]);
        }

#pragma unroll
        for (int nt = 0; nt < 16; nt++)
#pragma unroll
            for (int r = 0; r < 4; r++) acc[nt][r] = 0.f;
#pragma unroll
        for (int k = 0; k < 8; k++) {
#pragma unroll
            for (int ntp = 0; ntp < 8; ntp++) {
                uint32_t b4[4];
                ldmatrix_x4(b4[0], b4[1], b4[2], b4[3],
                            bb4_base + (uint32_t)ntp * (16 * RS) + (uint32_t)k * 32);
                mma_bf16(acc[2 * ntp],     afr[k], b4,     acc[2 * ntp]);
                mma_bf16(acc[2 * ntp + 1], afr[k], b4 + 2, acc[2 * ntp + 1]);
            }
        }
#pragma unroll
        for (int nt = 0; nt < 16; nt++) {
            const int c0 = nt * 8 + tig * 2;
            if (node0 < NN) *(float2*)&g_Hb[(size_t)node0 * DM + c0] =
                make_float2(acc[nt][0], acc[nt][1]);
            if (node1 < NN) *(float2*)&g_Hb[(size_t)node1 * DM + c0] =
                make_float2(acc[nt][2], acc[nt][3]);
        }
    }
}

// ---------------------------------------------------------------------------
// kernel 2: edge kernel — warp-autonomous, coalesced gather, full-HMMA.
// (unchanged from R13)
// ---------------------------------------------------------------------------
#define EB_C     0
#define EB_EA    34816
#define EB_W2    38912
#define EB_W1E   73728
#define EB_WR    77824
#define EB_BE1   78336
#define EB_BE2   78848
#define EB_WAS   79360
#define EB_TOTAL 79872

#define CSTRIDE 272
#define WARP_C_BYTES (16 * CSTRIDE)
#define WARP_EA_BYTES 512

__global__ void __launch_bounds__(256, 2)
edge_kernel(const float* __restrict__ x,
            const float* __restrict__ edge_attr,
            const float* __restrict__ We1,
            const float* __restrict__ be1,
            const float* __restrict__ We2,
            const float* __restrict__ be2,
            const float* __restrict__ Wa,
            const float* __restrict__ ba,
            const int* __restrict__ ei) {
    extern __shared__ __align__(16) char smraw[];
    float* Wr   = (float*)(smraw + EB_WR);
    float* be1s = (float*)(smraw + EB_BE1);
    float* be2s = (float*)(smraw + EB_BE2);
    float* Was  = (float*)(smraw + EB_WAS);

    const uint32_t smem_u32 = smem_to_u32(smraw);
    const int tid  = threadIdx.x;
    const int warp = tid >> 5;
    const int lane = tid & 31;

    for (int idx = tid; idx < 128 * 128; idx += 256) {
        int n = idx >> 7, k = idx & 127;
        *(__nv_bfloat16*)(smraw + EB_W2 + n * CSTRIDE + k * 2) =
            __float2bfloat16(We2[n * 128 + k]);
    }
    for (int idx = tid; idx < 128 * 16; idx += 256) {
        int n = idx >> 4, t = idx & 15;
        *(__nv_bfloat16*)(smraw + EB_W1E + n * 32 + t * 2) =
            __float2bfloat16(We1[n * 273 + 257 + t]);
    }
    for (int k = tid; k < 128; k += 256) {
        Wr[k]   = We1[k * 273 + 256];
        be1s[k] = be1[k];
        be2s[k] = be2[k];
        Was[k]  = Wa[k];
    }
    const float ba0 = ba[0];
    __syncthreads();

    const uint32_t c_region  = smem_u32 + EB_C  + (uint32_t)warp * WARP_C_BYTES;
    const uint32_t ea_region = smem_u32 + EB_EA + (uint32_t)warp * WARP_EA_BYTES;

    const int tig = lane & 3, grp = lane >> 2;
    const uint32_t c_fr0 = c_region + (uint32_t)grp * CSTRIDE + (uint32_t)tig * 4;
    const uint32_t c_fr1 = c_fr0 + 8 * CSTRIDE;
    const uint32_t ea_lm = ea_region + (uint32_t)(lane & 15) * 32 + ((lane >> 4) & 1) * 16;
    const uint32_t w1e4_base = smem_u32 + EB_W1E
                             + (uint32_t)((lane & 7) + ((lane >> 4) & 1) * 8) * 32
                             + ((lane >> 3) & 1) * 16;
    const uint32_t b4_base = smem_u32 + EB_W2
                           + (uint32_t)((lane & 7) + ((lane >> 4) & 1) * 8) * CSTRIDE
                           + ((lane >> 3) & 1) * 16;

    const int jj = tig >> 1;
    const bool isOdd = (tig & 1) != 0;

    const int NWT = NE / 16;
    const int wstride = gridDim.x * 8;

    const float4 wr4  = *(const float4*)(Wr + lane * 4);
    const float4 be14 = *(const float4*)(be1s + lane * 4);

    for (int wt = blockIdx.x * 8 + warp; wt < NWT; wt += wstride) {
        const int base = wt * 16;

        int rld = 0, cld = 0;
        float radld = 0.f;
        if (lane < 16) {
            rld = ei[base + lane];
            cld = ei[NE + base + lane];
            float dx = x[(size_t)rld * 3 + 0] - x[(size_t)cld * 3 + 0];
            float dy = x[(size_t)rld * 3 + 1] - x[(size_t)cld * 3 + 1];
            float dz = x[(size_t)rld * 3 + 2] - x[(size_t)cld * 3 + 2];
            radld = sqrtf(dx * dx + dy * dy + dz * dz);
        }

#pragma unroll
        for (int e = 0; e < 16; e++) {
            const int   row  = __shfl_sync(0xFFFFFFFF, rld, e);
            const int   colN = __shfl_sync(0xFFFFFFFF, cld, e);
            const float rv   = __shfl_sync(0xFFFFFFFF, radld, e);
            float4 ha = *(const float4*)&g_Ha[(size_t)row  * DM + lane * 4];
            float4 hb = *(const float4*)&g_Hb[(size_t)colN * DM + lane * 4];
            float4 c;
            c.x = ha.x + hb.x + be14.x + rv * wr4.x;
            c.y = ha.y + hb.y + be14.y + rv * wr4.y;
            c.z = ha.z + hb.z + be14.z + rv * wr4.z;
            c.w = ha.w + hb.w + be14.w + rv * wr4.w;
            *(uint2*)(smraw + (c_region - smem_u32) + e * CSTRIDE + lane * 8) = pack_bf16x4(c);
        }

        {
            int e = lane >> 1, hf2 = lane & 1;
            const float4* pe = (const float4*)(edge_attr + (size_t)(base + e) * DE + hf2 * 8);
            float4 u0 = pe[0], u1 = pe[1];
            uint2 w0 = pack_bf16x4(u0), w1 = pack_bf16x4(u1);
            *(uint4*)(smraw + (ea_region - smem_u32) + e * 32 + hf2 * 16) =
                make_uint4(w0.x, w0.y, w1.x, w1.y);
        }
        __syncwarp();

        float dacc[16][4];
#pragma unroll
        for (int nt = 0; nt < 16; nt++) {
            uint32_t lo = *(const uint32_t*)(smraw + (c_fr0 - smem_u32) + nt * 16);
            uint32_t hi = *(const uint32_t*)(smraw + (c_fr1 - smem_u32) + nt * 16);
            float2 f0 = unpack_bf16x2(lo);
            float2 f1 = unpack_bf16x2(hi);
            dacc[nt][0] = f0.x; dacc[nt][1] = f0.y;
            dacc[nt][2] = f1.x; dacc[nt][3] = f1.y;
        }
        {
            uint32_t aea[4];
            ldmatrix_x4(aea[0], aea[1], aea[2], aea[3], ea_lm);
#pragma unroll
            for (int ntp = 0; ntp < 8; ntp++) {
                uint32_t b4[4];
                ldmatrix_x4(b4[0], b4[1], b4[2], b4[3],
                            w1e4_base + (uint32_t)ntp * 512);
                mma_bf16(dacc[2 * ntp],     aea, b4,     dacc[2 * ntp]);
                mma_bf16(dacc[2 * ntp + 1], aea, b4 + 2, dacc[2 * ntp + 1]);
            }
        }
        __syncwarp();

        uint32_t au[8][4];
#pragma unroll
        for (int kk = 0; kk < 8; kk++) {
            float* d0 = dacc[2 * kk];
            float* d1 = dacc[2 * kk + 1];
            float s00 = d0[0] * fsigmoid(d0[0]);
            float s01 = d0[1] * fsigmoid(d0[1]);
            float s02 = d0[2] * fsigmoid(d0[2]);
            float s03 = d0[3] * fsigmoid(d0[3]);
            float s10 = d1[0] * fsigmoid(d1[0]);
            float s11 = d1[1] * fsigmoid(d1[1]);
            float s12 = d1[2] * fsigmoid(d1[2]);
            float s13 = d1[3] * fsigmoid(d1[3]);
            au[kk][0] = pack_bf16x2(s00, s01);
            au[kk][1] = pack_bf16x2(s02, s03);
            au[kk][2] = pack_bf16x2(s10, s11);
            au[kk][3] = pack_bf16x2(s12, s13);
        }

        float dd[16][4];
#pragma unroll
        for (int nt = 0; nt < 16; nt++)
#pragma unroll
            for (int r = 0; r < 4; r++) dd[nt][r] = 0.f;

#pragma unroll
        for (int kk = 0; kk < 8; kk++) {
#pragma unroll
            for (int ntp = 0; ntp < 8; ntp++) {
                uint32_t b4[4];
                ldmatrix_x4(b4[0], b4[1], b4[2], b4[3],
                            b4_base + (uint32_t)ntp * (16 * CSTRIDE) + (uint32_t)kk * 32);
                mma_bf16(dd[2 * ntp],     au[kk], b4,     dd[2 * ntp]);
                mma_bf16(dd[2 * ntp + 1], au[kk], b4 + 2, dd[2 * ntp + 1]);
            }
        }

        float pr0 = 0.f, pr1 = 0.f;
#pragma unroll
        for (int nt = 0; nt < 16; nt++) {
            const int c0 = nt * 8 + tig * 2;
            float2 bb = *(float2*)&be2s[c0];
            float2 wa = *(float2*)&Was[c0];
            float v0 = dd[nt][0] + bb.x;
            float v1 = dd[nt][1] + bb.y;
            float v2 = dd[nt][2] + bb.x;
            float v3 = dd[nt][3] + bb.y;
            float s0 = v0 * fsigmoid(v0);
            float s1 = v1 * fsigmoid(v1);
            float s2 = v2 * fsigmoid(v2);
            float s3 = v3 * fsigmoid(v3);
            dd[nt][0] = s0; dd[nt][1] = s1; dd[nt][2] = s2; dd[nt][3] = s3;
            pr0 += s0 * wa.x + s1 * wa.y;
            pr1 += s2 * wa.x + s3 * wa.y;
        }
        pr0 += __shfl_xor_sync(0xFFFFFFFF, pr0, 1);
        pr0 += __shfl_xor_sync(0xFFFFFFFF, pr0, 2);
        pr1 += __shfl_xor_sync(0xFFFFFFFF, pr1, 1);
        pr1 += __shfl_xor_sync(0xFFFFFFFF, pr1, 2);
        const float att0 = fsigmoid(pr0 + ba0);
        const float att1 = fsigmoid(pr1 + ba0);

        const int node0 = __shfl_sync(0xFFFFFFFF, rld, grp);
        const int node1 = __shfl_sync(0xFFFFFFFF, rld, grp + 8);
        const float attm = isOdd ? att1 : att0;
        float* dst = g_msg + (size_t)(isOdd ? node1 : node0) * DM + jj * 4;
#pragma unroll
        for (int nt = 0; nt < 16; nt++) {
            float s0 = dd[nt][0], s1 = dd[nt][1];
            float s2 = dd[nt][2], s3 = dd[nt][3];
            float q0 = __shfl_xor_sync(0xFFFFFFFF, s0, 1);
            float q1 = __shfl_xor_sync(0xFFFFFFFF, s1, 1);
            float q2 = __shfl_xor_sync(0xFFFFFFFF, s2, 1);
            float q3 = __shfl_xor_sync(0xFFFFFFFF, s3, 1);
            float v0 = isOdd ? q2 : s0;
            float v1 = isOdd ? q3 : s1;
            float v2 = isOdd ? s2 : q0;
            float v3 = isOdd ? s3 : q1;
            red_v4(dst + nt * 8, v0 * attm, v1 * attm, v2 * attm, v3 * attm);
        }
    }
}

// ---------------------------------------------------------------------------
// kernel 3 (HMMA): node post — 512 threads, 16 warps; warp-pair splits the
// nt range (warp w: row group w&7, nt half w>>3).
// ---------------------------------------------------------------------------
#define PO_A   0
#define PO_W1  67584
#define PO_W2  135168
#define PO_U   169984
#define PO_B1  204800
#define PO_B2  205312
#define PO_TOTAL 205824
#define RS2 528

__global__ void __launch_bounds__(512, 1)
node_post_kernel(const float* __restrict__ h,
                 const float* __restrict__ Wh1,
                 const float* __restrict__ bh1,
                 const float* __restrict__ Wh2,
                 const float* __restrict__ bh2,
                 float* __restrict__ out) {
    extern __shared__ __align__(16) char smraw[];
    float* b1s = (float*)(smraw + PO_B1);
    float* b2s = (float*)(smraw + PO_B2);

    const uint32_t smem_u32 = smem_to_u32(smraw);
    const int tid  = threadIdx.x;
    const int warp = tid >> 5;
    const int lane = tid & 31;
    const int rg   = warp & 7;     // row group (16 rows)
    const int nh   = warp >> 3;    // nt half (0: nt 0..7, 1: nt 8..15)

    for (int idx = tid; idx < 128 * 64; idx += 512) {
        int n = idx >> 6, k4 = (idx & 63) * 4;
        float4 v = *(const float4*)&Wh1[(size_t)n * 256 + k4];
        *(uint2*)(smraw + PO_W1 + n * RS2 + k4 * 2) = pack_bf16x4(v);
    }
    for (int idx = tid; idx < 128 * 32; idx += 512) {
        int n = idx >> 5, k4 = (idx & 31) * 4;
        float4 v = *(const float4*)&Wh2[(size_t)n * 128 + k4];
        *(uint2*)(smraw + PO_W2 + n * RS + k4 * 2) = pack_bf16x4(v);
    }
    for (int k = tid; k < 128; k += 512) {
        b1s[k] = bh1[k];
        b2s[k] = bh2[k];
    }
    __syncthreads();

    const int m0 = rg * 16;
    const int arow = m0 + (lane & 7) + ((lane >> 3) & 1) * 8;
    const uint32_t a1_base = smem_u32 + PO_A + (uint32_t)arow * RS2 + ((lane >> 4) & 1) * 16;
    const uint32_t a2_base = smem_u32 + PO_U + (uint32_t)arow * RS  + ((lane >> 4) & 1) * 16;
    const uint32_t b14_base = smem_u32 + PO_W1
                            + (uint32_t)((lane & 7) + ((lane >> 4) & 1) * 8) * RS2
                            + ((lane >> 3) & 1) * 16;
    const uint32_t b24_base = smem_u32 + PO_W2
                            + (uint32_t)((lane & 7) + ((lane >> 4) & 1) * 8) * RS
                            + ((lane >> 3) & 1) * 16;

    const int tig = lane & 3, grp = lane >> 2;
    const int ntiles = (NN + 127) / 128;

    for (int tile = blockIdx.x; tile < ntiles; tile += gridDim.x) {
        const int base = tile * 128;
        __syncthreads();
        for (int idx = tid; idx < 128 * 32; idx += 512) {
            int r = idx >> 5, j4 = (idx & 31) * 4;
            int node = base + r;
            float4 vh = (node < NN) ? *(const float4*)&h[(size_t)node * DH + j4]
                                    : make_float4(0.f, 0.f, 0.f, 0.f);
            float4 vm = (node < NN) ? *(const float4*)&g_msg[(size_t)node * DM + j4]
                                    : make_float4(0.f, 0.f, 0.f, 0.f);
            *(uint2*)(smraw + PO_A + r * RS2 + j4 * 2)         = pack_bf16x4(vh);
            *(uint2*)(smraw + PO_A + r * RS2 + 256 + j4 * 2)   = pack_bf16x4(vm);
        }
        __syncthreads();

        // GEMM1: K=256, this warp covers nt = nh*8 .. nh*8+7 (4 x4-pairs)
        float acc[8][4];
#pragma unroll
        for (int nt = 0; nt < 8; nt++)
#pragma unroll
            for (int r = 0; r < 4; r++) acc[nt][r] = 0.f;
#pragma unroll
        for (int k = 0; k < 16; k++) {
            uint32_t a[4];
            ldmatrix_x4(a[0], a[1], a[2], a[3], a1_base + (uint32_t)k * 32);
#pragma unroll
            for (int p = 0; p < 4; p++) {
                uint32_t b4[4];
                ldmatrix_x4(b4[0], b4[1], b4[2], b4[3],
                            b14_base + (uint32_t)(nh * 4 + p) * (16 * RS2) + (uint32_t)k * 32);
                mma_bf16(acc[2 * p],     a, b4,     acc[2 * p]);
                mma_bf16(acc[2 * p + 1], a, b4 + 2, acc[2 * p + 1]);
            }
        }
        // silu -> U (cols of this warp's half)
#pragma unroll
        for (int ntl = 0; ntl < 8; ntl++) {
            const int c0 = (nh * 8 + ntl) * 8 + tig * 2;
            float2 bb = *(float2*)&b1s[c0];
            float v0 = acc[ntl][0] + bb.x;
            float v1 = acc[ntl][1] + bb.y;
            float v2 = acc[ntl][2] + bb.x;
            float v3 = acc[ntl][3] + bb.y;
            uint32_t q0 = pack_bf16x2(v0 * fsigmoid(v0), v1 * fsigmoid(v1));
            uint32_t q1 = pack_bf16x2(v2 * fsigmoid(v2), v3 * fsigmoid(v3));
            *(uint32_t*)(smraw + PO_U + (m0 + grp) * RS + c0 * 2)     = q0;
            *(uint32_t*)(smraw + PO_U + (m0 + grp + 8) * RS + c0 * 2) = q1;
        }
        __syncthreads();

        // GEMM2: K=128
#pragma unroll
        for (int nt = 0; nt < 8; nt++)
#pragma unroll
            for (int r = 0; r < 4; r++) acc[nt][r] = 0.f;
#pragma unroll
        for (int k = 0; k < 8; k++) {
            uint32_t a[4];
            ldmatrix_x4(a[0], a[1], a[2], a[3], a2_base + (uint32_t)k * 32);
#pragma unroll
            for (int p = 0; p < 4; p++) {
                uint32_t b4[4];
                ldmatrix_x4(b4[0], b4[1], b4[2], b4[3],
                            b24_base + (uint32_t)(nh * 4 + p) * (16 * RS) + (uint32_t)k * 32);
                mma_bf16(acc[2 * p],     a, b4,     acc[2 * p]);
                mma_bf16(acc[2 * p + 1], a, b4 + 2, acc[2 * p + 1]);
            }
        }

        const int node0 = base + m0 + grp;
        const int node1 = node0 + 8;
#pragma unroll
        for (int ntl = 0; ntl < 8; ntl++) {
            const int c0 = (nh * 8 + ntl) * 8 + tig * 2;
            float2 bb = *(float2*)&b2s[c0];
            if (node0 < NN) {
                float2 hv = *(const float2*)&h[(size_t)node0 * DH + c0];
                *(float2*)&out[(size_t)node0 * DH + c0] =
                    make_float2(hv.x + acc[ntl][0] + bb.x, hv.y + acc[ntl][1] + bb.y);
            }
            if (node1 < NN) {
                float2 hv = *(const float2*)&h[(size_t)node1 * DH + c0];
                *(float2*)&out[(size_t)node1 * DH + c0] =
                    make_float2(hv.x + acc[ntl][2] + bb.x, hv.y + acc[ntl][3] + bb.y);
            }
        }
    }
}

// ---------------------------------------------------------------------------
extern "C" void kernel_launch(void* const* d_in, const int* in_sizes, int n_in,
                              void* d_out, int out_size) {
    const float* x   = (const float*)d_in[0];
    const float* h   = (const float*)d_in[1];
    const float* ea  = (const float*)d_in[2];
    const float* We1 = (const float*)d_in[3];
    const float* be1 = (const float*)d_in[4];
    const float* We2 = (const float*)d_in[5];
    const float* be2 = (const float*)d_in[6];
    const float* Wh1 = (const float*)d_in[7];
    const float* bh1 = (const float*)d_in[8];
    const float* Wh2 = (const float*)d_in[9];
    const float* bh2 = (const float*)d_in[10];
    const float* Wa  = (const float*)d_in[11];
    const float* ba  = (const float*)d_in[12];
    const int*   ei  = (const int*)d_in[13];   // int32
    float* out = (float*)d_out;

    cudaFuncSetAttribute(node_pre_kernel,
                         cudaFuncAttributeMaxDynamicSharedMemorySize, NP_TOTAL);
    cudaFuncSetAttribute(edge_kernel,
                         cudaFuncAttributeMaxDynamicSharedMemorySize, EB_TOTAL);
    cudaFuncSetAttribute(node_post_kernel,
                         cudaFuncAttributeMaxDynamicSharedMemorySize, PO_TOTAL);

    node_pre_kernel<<<296, 256, NP_TOTAL>>>(h, We1);   // also zeroes g_msg
    edge_kernel<<<296, 256, EB_TOTAL>>>(x, ea, We1, be1, We2, be2, Wa, ba, ei);
    node_post_kernel<<<148, 512, PO_TOTAL>>>(h, Wh1, bh1, Wh2, bh2, out);
}

// round 15
// speedup vs baseline: 3.4791x; 1.0005x over previous
#include <cuda_runtime.h>
#include <cuda_bf16.h>
#include <math.h>
#include <stdint.h>

// ----------------------------------------------------------------------------
// IGNN / EGNN layer, GB300 (sm_103a built as sm_103 -> mma.sync, no tcgen05).
// Round 15: bf16x2-vectorized silu (tanh.approx.bf16x2, 2 values per MUFU op)
// on the bf16-destined silu sites (edge stage-1 m1, node_post U). Edge
// epilogue silu stays fp32 for message/attention precision. Everything else
// unchanged from R14.
// ----------------------------------------------------------------------------

#define NN 50000
#define NE 800000
#define DH 128
#define DE 16
#define DM 128

__device__ __align__(16) float g_Ha[(size_t)NN * DM];
__device__ __align__(16) float g_Hb[(size_t)NN * DM];
__device__ __align__(16) float g_msg[(size_t)NN * DM];

// fp32 sigmoid via tanh.approx.f32 (1 MUFU)
__device__ __forceinline__ float fsigmoid(float v) {
    float t;
    asm("tanh.approx.f32 %0, %1;" : "=f"(t) : "f"(v * 0.5f));
    return fmaf(0.5f, t, 0.5f);
}

__device__ __forceinline__ uint32_t pack_bf16x2(float a, float b) {
    __nv_bfloat162 p = __floats2bfloat162_rn(a, b);
    return *(uint32_t*)&p;
}

// silu on a packed pair, entirely in bf16x2 (1 MUFU for 2 values).
// Returns bf16x2( v*sigmoid(v) ) for v = (a, b).
__device__ __forceinline__ uint32_t silu_bf16x2(float a, float b) {
    const uint32_t HALF2 = 0x3F003F00u;   // (0.5, 0.5) bf16x2
    uint32_t u = pack_bf16x2(a, b);
    uint32_t hu, t, sg, s;
    asm("mul.rn.bf16x2 %0, %1, %2;" : "=r"(hu) : "r"(u), "r"(HALF2));
    asm("tanh.approx.bf16x2 %0, %1;" : "=r"(t) : "r"(hu));
    asm("fma.rn.bf16x2 %0, %1, %2, %3;" : "=r"(sg) : "r"(t), "r"(HALF2), "r"(HALF2));
    asm("mul.rn.bf16x2 %0, %1, %2;" : "=r"(s) : "r"(u), "r"(sg));
    return s;
}

__device__ __forceinline__ uint32_t smem_to_u32(const void* smem_ptr) {
    uint32_t addr;
    asm("{ .reg .u64 tmp; cvta.to.shared.u64 tmp, %1; cvt.u32.u64 %0, tmp; }"
        : "=r"(addr) : "l"(smem_ptr));
    return addr;
}

__device__ __forceinline__ void ldmatrix_x4(uint32_t& r0, uint32_t& r1,
                                            uint32_t& r2, uint32_t& r3, uint32_t addr) {
    asm volatile("ldmatrix.sync.aligned.m8n8.x4.shared.b16 {%0,%1,%2,%3}, [%4];"
                 : "=r"(r0), "=r"(r1), "=r"(r2), "=r"(r3) : "r"(addr));
}
__device__ __forceinline__ void ldmatrix_x2(uint32_t& r0, uint32_t& r1, uint32_t addr) {
    asm volatile("ldmatrix.sync.aligned.m8n8.x2.shared.b16 {%0,%1}, [%2];"
                 : "=r"(r0), "=r"(r1) : "r"(addr));
}
__device__ __forceinline__ void mma_bf16(float d[4], const uint32_t a[4],
                                         const uint32_t b[2], const float c[4]) {
    asm volatile(
        "mma.sync.aligned.m16n8k16.row.col.f32.bf16.bf16.f32 "
        "{%0,%1,%2,%3}, {%4,%5,%6,%7}, {%8,%9}, {%10,%11,%12,%13};"
        : "=f"(d[0]), "=f"(d[1]), "=f"(d[2]), "=f"(d[3])
        : "r"(a[0]), "r"(a[1]), "r"(a[2]), "r"(a[3]),
          "r"(b[0]), "r"(b[1]),
          "f"(c[0]), "f"(c[1]), "f"(c[2]), "f"(c[3]));
}
__device__ __forceinline__ void red_v4(float* addr, float v0, float v1, float v2, float v3) {
    asm volatile("red.global.add.v4.f32 [%0], {%1, %2, %3, %4};"
                 :: "l"(addr), "f"(v0), "f"(v1), "f"(v2), "f"(v3) : "memory");
}

__device__ __forceinline__ uint2 pack_bf16x4(float4 v) {
    __nv_bfloat162 lo = __floats2bfloat162_rn(v.x, v.y);
    __nv_bfloat162 hi = __floats2bfloat162_rn(v.z, v.w);
    uint2 r;
    r.x = *(uint32_t*)&lo;
    r.y = *(uint32_t*)&hi;
    return r;
}
__device__ __forceinline__ float2 unpack_bf16x2(uint32_t w) {
    __nv_bfloat162 p = *(__nv_bfloat162*)&w;
    return make_float2(__bfloat162float(p.x), __bfloat162float(p.y));
}

// ---------------------------------------------------------------------------
// kernel 1 (HMMA): Ha = h @ W1a^T, Hb = h @ W1b^T + g_msg zeroing.
// (unchanged from R14)
// ---------------------------------------------------------------------------
#define NP_A   0
#define NP_WA  34816
#define NP_WB  69632
#define NP_TOTAL 104448
#define RS 272

__global__ void __launch_bounds__(256, 2)
node_pre_kernel(const float* __restrict__ h, const float* __restrict__ We1) {
    extern __shared__ __align__(16) char smraw[];
    const uint32_t smem_u32 = smem_to_u32(smraw);
    const int tid  = threadIdx.x;
    const int warp = tid >> 5;
    const int lane = tid & 31;

    for (int idx = tid; idx < 128 * 128; idx += 256) {
        int n = idx >> 7, k = idx & 127;
        *(__nv_bfloat16*)(smraw + NP_WA + n * RS + k * 2) =
            __float2bfloat16(We1[n * 273 + k]);
        *(__nv_bfloat16*)(smraw + NP_WB + n * RS + k * 2) =
            __float2bfloat16(We1[n * 273 + 128 + k]);
    }
    __syncthreads();

    const int m0 = warp * 16;
    const int arow = m0 + (lane & 7) + ((lane >> 3) & 1) * 8;
    const uint32_t a_base  = smem_u32 + NP_A + (uint32_t)arow * RS + ((lane >> 4) & 1) * 16;
    const uint32_t ba4_base = smem_u32 + NP_WA
                            + (uint32_t)((lane & 7) + ((lane >> 4) & 1) * 8) * RS
                            + ((lane >> 3) & 1) * 16;
    const uint32_t bb4_base = ba4_base + (NP_WB - NP_WA);

    const int tig = lane & 3, grp = lane >> 2;
    const int ntiles = (NN + 127) / 128;

    for (int tile = blockIdx.x; tile < ntiles; tile += gridDim.x) {
        const int base = tile * 128;
        __syncthreads();
        for (int idx = tid; idx < 128 * 32; idx += 256) {
            int r = idx >> 5, j4 = (idx & 31) * 4;
            int node = base + r;
            float4 v = make_float4(0.f, 0.f, 0.f, 0.f);
            if (node < NN) {
                v = *(const float4*)&h[(size_t)node * DH + j4];
                *(float4*)&g_msg[(size_t)node * DM + j4] = make_float4(0.f, 0.f, 0.f, 0.f);
            }
            *(uint2*)(smraw + NP_A + r * RS + j4 * 2) = pack_bf16x4(v);
        }
        __syncthreads();

        const int node0 = base + m0 + grp;
        const int node1 = node0 + 8;

        uint32_t afr[8][4];
#pragma unroll
        for (int k = 0; k < 8; k++)
            ldmatrix_x4(afr[k][0], afr[k][1], afr[k][2], afr[k][3],
                        a_base + (uint32_t)k * 32);

        float acc[16][4];

#pragma unroll
        for (int nt = 0; nt < 16; nt++)
#pragma unroll
            for (int r = 0; r < 4; r++) acc[nt][r] = 0.f;
#pragma unroll
        for (int k = 0; k < 8; k++) {
#pragma unroll
            for (int ntp = 0; ntp < 8; ntp++) {
                uint32_t b4[4];
                ldmatrix_x4(b4[0], b4[1], b4[2], b4[3],
                            ba4_base + (uint32_t)ntp * (16 * RS) + (uint32_t)k * 32);
                mma_bf16(acc[2 * ntp],     afr[k], b4,     acc[2 * ntp]);
                mma_bf16(acc[2 * ntp + 1], afr[k], b4 + 2, acc[2 * ntp + 1]);
            }
        }
#pragma unroll
        for (int nt = 0; nt < 16; nt++) {
            const int c0 = nt * 8 + tig * 2;
            if (node0 < NN) *(float2*)&g_Ha[(size_t)node0 * DM + c0] =
                make_float2(acc[nt][0], acc[nt][1]);
            if (node1 < NN) *(float2*)&g_Ha[(size_t)node1 * DM + c0] =
                make_float2(acc[nt][2], acc[nt][3]);
        }

#pragma unroll
        for (int nt = 0; nt < 16; nt++)
#pragma unroll
            for (int r = 0; r < 4; r++) acc[nt][r] = 0.f;
#pragma unroll
        for (int k = 0; k < 8; k++) {
#pragma unroll
            for (int ntp = 0; ntp < 8; ntp++) {
                uint32_t b4[4];
                ldmatrix_x4(b4[0], b4[1], b4[2], b4[3],
                            bb4_base + (uint32_t)ntp * (16 * RS) + (uint32_t)k * 32);
                mma_bf16(acc[2 * ntp],     afr[k], b4,     acc[2 * ntp]);
                mma_bf16(acc[2 * ntp + 1], afr[k], b4 + 2, acc[2 * ntp + 1]);
            }
        }
#pragma unroll
        for (int nt = 0; nt < 16; nt++) {
            const int c0 = nt * 8 + tig * 2;
            if (node0 < NN) *(float2*)&g_Hb[(size_t)node0 * DM + c0] =
                make_float2(acc[nt][0], acc[nt][1]);
            if (node1 < NN) *(float2*)&g_Hb[(size_t)node1 * DM + c0] =
                make_float2(acc[nt][2], acc[nt][3]);
        }
    }
}

// ---------------------------------------------------------------------------
// kernel 2: edge kernel — warp-autonomous, coalesced gather, full-HMMA.
// Stage-1 silu now bf16x2 (m1 is bf16-destined anyway).
// ---------------------------------------------------------------------------
#define EB_C     0
#define EB_EA    34816
#define EB_W2    38912
#define EB_W1E   73728
#define EB_WR    77824
#define EB_BE1   78336
#define EB_BE2   78848
#define EB_WAS   79360
#define EB_TOTAL 79872

#define CSTRIDE 272
#define WARP_C_BYTES (16 * CSTRIDE)
#define WARP_EA_BYTES 512

__global__ void __launch_bounds__(256, 2)
edge_kernel(const float* __restrict__ x,
            const float* __restrict__ edge_attr,
            const float* __restrict__ We1,
            const float* __restrict__ be1,
            const float* __restrict__ We2,
            const float* __restrict__ be2,
            const float* __restrict__ Wa,
            const float* __restrict__ ba,
            const int* __restrict__ ei) {
    extern __shared__ __align__(16) char smraw[];
    float* Wr   = (float*)(smraw + EB_WR);
    float* be1s = (float*)(smraw + EB_BE1);
    float* be2s = (float*)(smraw + EB_BE2);
    float* Was  = (float*)(smraw + EB_WAS);

    const uint32_t smem_u32 = smem_to_u32(smraw);
    const int tid  = threadIdx.x;
    const int warp = tid >> 5;
    const int lane = tid & 31;

    for (int idx = tid; idx < 128 * 128; idx += 256) {
        int n = idx >> 7, k = idx & 127;
        *(__nv_bfloat16*)(smraw + EB_W2 + n * CSTRIDE + k * 2) =
            __float2bfloat16(We2[n * 128 + k]);
    }
    for (int idx = tid; idx < 128 * 16; idx += 256) {
        int n = idx >> 4, t = idx & 15;
        *(__nv_bfloat16*)(smraw + EB_W1E + n * 32 + t * 2) =
            __float2bfloat16(We1[n * 273 + 257 + t]);
    }
    for (int k = tid; k < 128; k += 256) {
        Wr[k]   = We1[k * 273 + 256];
        be1s[k] = be1[k];
        be2s[k] = be2[k];
        Was[k]  = Wa[k];
    }
    const float ba0 = ba[0];
    __syncthreads();

    const uint32_t c_region  = smem_u32 + EB_C  + (uint32_t)warp * WARP_C_BYTES;
    const uint32_t ea_region = smem_u32 + EB_EA + (uint32_t)warp * WARP_EA_BYTES;

    const int tig = lane & 3, grp = lane >> 2;
    const uint32_t c_fr0 = c_region + (uint32_t)grp * CSTRIDE + (uint32_t)tig * 4;
    const uint32_t c_fr1 = c_fr0 + 8 * CSTRIDE;
    const uint32_t ea_lm = ea_region + (uint32_t)(lane & 15) * 32 + ((lane >> 4) & 1) * 16;
    const uint32_t w1e4_base = smem_u32 + EB_W1E
                             + (uint32_t)((lane & 7) + ((lane >> 4) & 1) * 8) * 32
                             + ((lane >> 3) & 1) * 16;
    const uint32_t b4_base = smem_u32 + EB_W2
                           + (uint32_t)((lane & 7) + ((lane >> 4) & 1) * 8) * CSTRIDE
                           + ((lane >> 3) & 1) * 16;

    const int jj = tig >> 1;
    const bool isOdd = (tig & 1) != 0;

    const int NWT = NE / 16;
    const int wstride = gridDim.x * 8;

    const float4 wr4  = *(const float4*)(Wr + lane * 4);
    const float4 be14 = *(const float4*)(be1s + lane * 4);

    for (int wt = blockIdx.x * 8 + warp; wt < NWT; wt += wstride) {
        const int base = wt * 16;

        int rld = 0, cld = 0;
        float radld = 0.f;
        if (lane < 16) {
            rld = ei[base + lane];
            cld = ei[NE + base + lane];
            float dx = x[(size_t)rld * 3 + 0] - x[(size_t)cld * 3 + 0];
            float dy = x[(size_t)rld * 3 + 1] - x[(size_t)cld * 3 + 1];
            float dz = x[(size_t)rld * 3 + 2] - x[(size_t)cld * 3 + 2];
            radld = sqrtf(dx * dx + dy * dy + dz * dz);
        }

#pragma unroll
        for (int e = 0; e < 16; e++) {
            const int   row  = __shfl_sync(0xFFFFFFFF, rld, e);
            const int   colN = __shfl_sync(0xFFFFFFFF, cld, e);
            const float rv   = __shfl_sync(0xFFFFFFFF, radld, e);
            float4 ha = *(const float4*)&g_Ha[(size_t)row  * DM + lane * 4];
            float4 hb = *(const float4*)&g_Hb[(size_t)colN * DM + lane * 4];
            float4 c;
            c.x = ha.x + hb.x + be14.x + rv * wr4.x;
            c.y = ha.y + hb.y + be14.y + rv * wr4.y;
            c.z = ha.z + hb.z + be14.z + rv * wr4.z;
            c.w = ha.w + hb.w + be14.w + rv * wr4.w;
            *(uint2*)(smraw + (c_region - smem_u32) + e * CSTRIDE + lane * 8) = pack_bf16x4(c);
        }

        {
            int e = lane >> 1, hf2 = lane & 1;
            const float4* pe = (const float4*)(edge_attr + (size_t)(base + e) * DE + hf2 * 8);
            float4 u0 = pe[0], u1 = pe[1];
            uint2 w0 = pack_bf16x4(u0), w1 = pack_bf16x4(u1);
            *(uint4*)(smraw + (ea_region - smem_u32) + e * 32 + hf2 * 16) =
                make_uint4(w0.x, w0.y, w1.x, w1.y);
        }
        __syncwarp();

        float dacc[16][4];
#pragma unroll
        for (int nt = 0; nt < 16; nt++) {
            uint32_t lo = *(const uint32_t*)(smraw + (c_fr0 - smem_u32) + nt * 16);
            uint32_t hi = *(const uint32_t*)(smraw + (c_fr1 - smem_u32) + nt * 16);
            float2 f0 = unpack_bf16x2(lo);
            float2 f1 = unpack_bf16x2(hi);
            dacc[nt][0] = f0.x; dacc[nt][1] = f0.y;
            dacc[nt][2] = f1.x; dacc[nt][3] = f1.y;
        }
        {
            uint32_t aea[4];
            ldmatrix_x4(aea[0], aea[1], aea[2], aea[3], ea_lm);
#pragma unroll
            for (int ntp = 0; ntp < 8; ntp++) {
                uint32_t b4[4];
                ldmatrix_x4(b4[0], b4[1], b4[2], b4[3],
                            w1e4_base + (uint32_t)ntp * 512);
                mma_bf16(dacc[2 * ntp],     aea, b4,     dacc[2 * ntp]);
                mma_bf16(dacc[2 * ntp + 1], aea, b4 + 2, dacc[2 * ntp + 1]);
            }
        }
        __syncwarp();

        // stage-1 silu entirely in bf16x2 (m1 is bf16-destined)
        uint32_t au[8][4];
#pragma unroll
        for (int kk = 0; kk < 8; kk++) {
            float* d0 = dacc[2 * kk];
            float* d1 = dacc[2 * kk + 1];
            au[kk][0] = silu_bf16x2(d0[0], d0[1]);
            au[kk][1] = silu_bf16x2(d0[2], d0[3]);
            au[kk][2] = silu_bf16x2(d1[0], d1[1]);
            au[kk][3] = silu_bf16x2(d1[2], d1[3]);
        }

        float dd[16][4];
#pragma unroll
        for (int nt = 0; nt < 16; nt++)
#pragma unroll
            for (int r = 0; r < 4; r++) dd[nt][r] = 0.f;

#pragma unroll
        for (int kk = 0; kk < 8; kk++) {
#pragma unroll
            for (int ntp = 0; ntp < 8; ntp++) {
                uint32_t b4[4];
                ldmatrix_x4(b4[0], b4[1], b4[2], b4[3],
                            b4_base + (uint32_t)ntp * (16 * CSTRIDE) + (uint32_t)kk * 32);
                mma_bf16(dd[2 * ntp],     au[kk], b4,     dd[2 * ntp]);
                mma_bf16(dd[2 * ntp + 1], au[kk], b4 + 2, dd[2 * ntp + 1]);
            }
        }

        float pr0 = 0.f, pr1 = 0.f;
#pragma unroll
        for (int nt = 0; nt < 16; nt++) {
            const int c0 = nt * 8 + tig * 2;
            float2 bb = *(float2*)&be2s[c0];
            float2 wa = *(float2*)&Was[c0];
            float v0 = dd[nt][0] + bb.x;
            float v1 = dd[nt][1] + bb.y;
            float v2 = dd[nt][2] + bb.x;
            float v3 = dd[nt][3] + bb.y;
            float s0 = v0 * fsigmoid(v0);
            float s1 = v1 * fsigmoid(v1);
            float s2 = v2 * fsigmoid(v2);
            float s3 = v3 * fsigmoid(v3);
            dd[nt][0] = s0; dd[nt][1] = s1; dd[nt][2] = s2; dd[nt][3] = s3;
            pr0 += s0 * wa.x + s1 * wa.y;
            pr1 += s2 * wa.x + s3 * wa.y;
        }
        pr0 += __shfl_xor_sync(0xFFFFFFFF, pr0, 1);
        pr0 += __shfl_xor_sync(0xFFFFFFFF, pr0, 2);
        pr1 += __shfl_xor_sync(0xFFFFFFFF, pr1, 1);
        pr1 += __shfl_xor_sync(0xFFFFFFFF, pr1, 2);
        const float att0 = fsigmoid(pr0 + ba0);
        const float att1 = fsigmoid(pr1 + ba0);

        const int node0 = __shfl_sync(0xFFFFFFFF, rld, grp);
        const int node1 = __shfl_sync(0xFFFFFFFF, rld, grp + 8);
        const float attm = isOdd ? att1 : att0;
        float* dst = g_msg + (size_t)(isOdd ? node1 : node0) * DM + jj * 4;
#pragma unroll
        for (int nt = 0; nt < 16; nt++) {
            float s0 = dd[nt][0], s1 = dd[nt][1];
            float s2 = dd[nt][2], s3 = dd[nt][3];
            float q0 = __shfl_xor_sync(0xFFFFFFFF, s0, 1);
            float q1 = __shfl_xor_sync(0xFFFFFFFF, s1, 1);
            float q2 = __shfl_xor_sync(0xFFFFFFFF, s2, 1);
            float q3 = __shfl_xor_sync(0xFFFFFFFF, s3, 1);
            float v0 = isOdd ? q2 : s0;
            float v1 = isOdd ? q3 : s1;
            float v2 = isOdd ? s2 : q0;
            float v3 = isOdd ? s3 : q1;
            red_v4(dst + nt * 8, v0 * attm, v1 * attm, v2 * attm, v3 * attm);
        }
    }
}

// ---------------------------------------------------------------------------
// kernel 3 (HMMA): node post — 512 threads, warp-pair nt split (R14),
// U-silu now bf16x2.
// ---------------------------------------------------------------------------
#define PO_A   0
#define PO_W1  67584
#define PO_W2  135168
#define PO_U   169984
#define PO_B1  204800
#define PO_B2  205312
#define PO_TOTAL 205824
#define RS2 528

__global__ void __launch_bounds__(512, 1)
node_post_kernel(const float* __restrict__ h,
                 const float* __restrict__ Wh1,
                 const float* __restrict__ bh1,
                 const float* __restrict__ Wh2,
                 const float* __restrict__ bh2,
                 float* __restrict__ out) {
    extern __shared__ __align__(16) char smraw[];
    float* b1s = (float*)(smraw + PO_B1);
    float* b2s = (float*)(smraw + PO_B2);

    const uint32_t smem_u32 = smem_to_u32(smraw);
    const int tid  = threadIdx.x;
    const int warp = tid >> 5;
    const int lane = tid & 31;
    const int rg   = warp & 7;
    const int nh   = warp >> 3;

    for (int idx = tid; idx < 128 * 64; idx += 512) {
        int n = idx >> 6, k4 = (idx & 63) * 4;
        float4 v = *(const float4*)&Wh1[(size_t)n * 256 + k4];
        *(uint2*)(smraw + PO_W1 + n * RS2 + k4 * 2) = pack_bf16x4(v);
    }
    for (int idx = tid; idx < 128 * 32; idx += 512) {
        int n = idx >> 5, k4 = (idx & 31) * 4;
        float4 v = *(const float4*)&Wh2[(size_t)n * 128 + k4];
        *(uint2*)(smraw + PO_W2 + n * RS + k4 * 2) = pack_bf16x4(v);
    }
    for (int k = tid; k < 128; k += 512) {
        b1s[k] = bh1[k];
        b2s[k] = bh2[k];
    }
    __syncthreads();

    const int m0 = rg * 16;
    const int arow = m0 + (lane & 7) + ((lane >> 3) & 1) * 8;
    const uint32_t a1_base = smem_u32 + PO_A + (uint32_t)arow * RS2 + ((lane >> 4) & 1) * 16;
    const uint32_t a2_base = smem_u32 + PO_U + (uint32_t)arow * RS  + ((lane >> 4) & 1) * 16;
    const uint32_t b14_base = smem_u32 + PO_W1
                            + (uint32_t)((lane & 7) + ((lane >> 4) & 1) * 8) * RS2
                            + ((lane >> 3) & 1) * 16;
    const uint32_t b24_base = smem_u32 + PO_W2
                            + (uint32_t)((lane & 7) + ((lane >> 4) & 1) * 8) * RS
                            + ((lane >> 3) & 1) * 16;

    const int tig = lane & 3, grp = lane >> 2;
    const int ntiles = (NN + 127) / 128;

    for (int tile = blockIdx.x; tile < ntiles; tile += gridDim.x) {
        const int base = tile * 128;
        __syncthreads();
        for (int idx = tid; idx < 128 * 32; idx += 512) {
            int r = idx >> 5, j4 = (idx & 31) * 4;
            int node = base + r;
            float4 vh = (node < NN) ? *(const float4*)&h[(size_t)node * DH + j4]
                                    : make_float4(0.f, 0.f, 0.f, 0.f);
            float4 vm = (node < NN) ? *(const float4*)&g_msg[(size_t)node * DM + j4]
                                    : make_float4(0.f, 0.f, 0.f, 0.f);
            *(uint2*)(smraw + PO_A + r * RS2 + j4 * 2)         = pack_bf16x4(vh);
            *(uint2*)(smraw + PO_A + r * RS2 + 256 + j4 * 2)   = pack_bf16x4(vm);
        }
        __syncthreads();

        float acc[8][4];
#pragma unroll
        for (int nt = 0; nt < 8; nt++)
#pragma unroll
            for (int r = 0; r < 4; r++) acc[nt][r] = 0.f;
#pragma unroll
        for (int k = 0; k < 16; k++) {
            uint32_t a[4];
            ldmatrix_x4(a[0], a[1], a[2], a[3], a1_base + (uint32_t)k * 32);
#pragma unroll
            for (int p = 0; p < 4; p++) {
                uint32_t b4[4];
                ldmatrix_x4(b4[0], b4[1], b4[2], b4[3],
                            b14_base + (uint32_t)(nh * 4 + p) * (16 * RS2) + (uint32_t)k * 32);
                mma_bf16(acc[2 * p],     a, b4,     acc[2 * p]);
                mma_bf16(acc[2 * p + 1], a, b4 + 2, acc[2 * p + 1]);
            }
        }
        // U-silu in bf16x2
#pragma unroll
        for (int ntl = 0; ntl < 8; ntl++) {
            const int c0 = (nh * 8 + ntl) * 8 + tig * 2;
            float2 bb = *(float2*)&b1s[c0];
            uint32_t q0 = silu_bf16x2(acc[ntl][0] + bb.x, acc[ntl][1] + bb.y);
            uint32_t q1 = silu_bf16x2(acc[ntl][2] + bb.x, acc[ntl][3] + bb.y);
            *(uint32_t*)(smraw + PO_U + (m0 + grp) * RS + c0 * 2)     = q0;
            *(uint32_t*)(smraw + PO_U + (m0 + grp + 8) * RS + c0 * 2) = q1;
        }
        __syncthreads();

#pragma unroll
        for (int nt = 0; nt < 8; nt++)
#pragma unroll
            for (int r = 0; r < 4; r++) acc[nt][r] = 0.f;
#pragma unroll
        for (int k = 0; k < 8; k++) {
            uint32_t a[4];
            ldmatrix_x4(a[0], a[1], a[2], a[3], a2_base + (uint32_t)k * 32);
#pragma unroll
            for (int p = 0; p < 4; p++) {
                uint32_t b4[4];
                ldmatrix_x4(b4[0], b4[1], b4[2], b4[3],
                            b24_base + (uint32_t)(nh * 4 + p) * (16 * RS) + (uint32_t)k * 32);
                mma_bf16(acc[2 * p],     a, b4,     acc[2 * p]);
                mma_bf16(acc[2 * p + 1], a, b4 + 2, acc[2 * p + 1]);
            }
        }

        const int node0 = base + m0 + grp;
        const int node1 = node0 + 8;
#pragma unroll
        for (int ntl = 0; ntl < 8; ntl++) {
            const int c0 = (nh * 8 + ntl) * 8 + tig * 2;
            float2 bb = *(float2*)&b2s[c0];
            if (node0 < NN) {
                float2 hv = *(const float2*)&h[(size_t)node0 * DH + c0];
                *(float2*)&out[(size_t)node0 * DH + c0] =
                    make_float2(hv.x + acc[ntl][0] + bb.x, hv.y + acc[ntl][1] + bb.y);
            }
            if (node1 < NN) {
                float2 hv = *(const float2*)&h[(size_t)node1 * DH + c0];
                *(float2*)&out[(size_t)node1 * DH + c0] =
                    make_float2(hv.x + acc[ntl][2] + bb.x, hv.y + acc[ntl][3] + bb.y);
            }
        }
    }
}

// ---------------------------------------------------------------------------
extern "C" void kernel_launch(void* const* d_in, const int* in_sizes, int n_in,
                              void* d_out, int out_size) {
    const float* x   = (const float*)d_in[0];
    const float* h   = (const float*)d_in[1];
    const float* ea  = (const float*)d_in[2];
    const float* We1 = (const float*)d_in[3];
    const float* be1 = (const float*)d_in[4];
    const float* We2 = (const float*)d_in[5];
    const float* be2 = (const float*)d_in[6];
    const float* Wh1 = (const float*)d_in[7];
    const float* bh1 = (const float*)d_in[8];
    const float* Wh2 = (const float*)d_in[9];
    const float* bh2 = (const float*)d_in[10];
    const float* Wa  = (const float*)d_in[11];
    const float* ba  = (const float*)d_in[12];
    const int*   ei  = (const int*)d_in[13];   // int32
    float* out = (float*)d_out;

    cudaFuncSetAttribute(node_pre_kernel,
                         cudaFuncAttributeMaxDynamicSharedMemorySize, NP_TOTAL);
    cudaFuncSetAttribute(edge_kernel,
                         cudaFuncAttributeMaxDynamicSharedMemorySize, EB_TOTAL);
    cudaFuncSetAttribute(node_post_kernel,
                         cudaFuncAttributeMaxDynamicSharedMemorySize, PO_TOTAL);

    node_pre_kernel<<<296, 256, NP_TOTAL>>>(h, We1);   // also zeroes g_msg
    edge_kernel<<<296, 256, EB_TOTAL>>>(x, ea, We1, be1, We2, be2, Wa, ba, ei);
    node_post_kernel<<<148, 512, PO_TOTAL>>>(h, Wh1, bh1, Wh2, bh2, out);
}